// round 1
// baseline (speedup 1.0000x reference)
#include <cuda_runtime.h>
#include <math.h>

#define NT 4096      // total tokens (B*L)
#define DM 1024      // d_model
#define DH 4096      // d_hidden
#define NH 16
#define HD 64
#define LSEQ 2048
#define NBATCH 2

// ---------------- scratch (static device globals; no runtime alloc) ----------------
__device__ float g_xn [NT * DM];
__device__ float g_q  [NT * DM];
__device__ float g_k  [NT * DM];
__device__ float g_v  [NT * DM];
__device__ float g_att[NT * DM];
__device__ float g_x1 [NT * DM];
__device__ float g_xn2[NT * DM];
__device__ float g_gate[(size_t)NT * DH];
__device__ float g_hid [(size_t)NT * DH];

// ---------------- RMSNorm: one block per row ----------------
__global__ __launch_bounds__(256) void rmsnorm_kernel(
    const float* __restrict__ x, const float* __restrict__ w, float* __restrict__ out)
{
    int row = blockIdx.x;
    const float* xr = x + (size_t)row * DM;
    float s = 0.f;
    for (int i = threadIdx.x; i < DM; i += 256) { float v = xr[i]; s += v * v; }
    __shared__ float red[8];
    #pragma unroll
    for (int o = 16; o > 0; o >>= 1) s += __shfl_xor_sync(0xffffffffu, s, o);
    if ((threadIdx.x & 31) == 0) red[threadIdx.x >> 5] = s;
    __syncthreads();
    if (threadIdx.x < 8) {
        float v = red[threadIdx.x];
        #pragma unroll
        for (int o = 4; o > 0; o >>= 1) v += __shfl_xor_sync(0xffu, v, o);
        if (threadIdx.x == 0) red[0] = v;
    }
    __syncthreads();
    float inv = rsqrtf(red[0] * (1.0f / DM) + 1e-6f);
    float* orow = out + (size_t)row * DM;
    for (int i = threadIdx.x; i < DM; i += 256) orow[i] = w[i] * xr[i] * inv;
}

// ---------------- SGEMM: C[M,N] = A[M,K] @ B[K,N] (+bias)(+res) ----------------
// BM=BN=64, BK=16, 256 threads, 4x4 per thread. M,N div 64; K div 16 (holds here).
template <int HAS_BIAS, int HAS_RES>
__global__ __launch_bounds__(256) void sgemm64(
    const float* __restrict__ A, const float* __restrict__ B, float* __restrict__ C,
    int M, int N, int K, const float* __restrict__ bias, const float* __restrict__ res)
{
    const int BM = 64, BN = 64, BK = 16;
    __shared__ float As[BK][BM + 4];
    __shared__ float Bs[BK][BN + 4];
    int tid = threadIdx.x;
    int bm = blockIdx.y * BM, bn = blockIdx.x * BN;
    int tr = (tid >> 4) << 2;   // output row tile base (0..60)
    int tc = (tid & 15) << 2;   // output col tile base

    int arow = tid >> 2;            // 0..63
    int acol = (tid & 3) << 2;      // 0,4,8,12
    int brow = tid >> 4;            // 0..15
    int bcol = (tid & 15) << 2;

    const float* Ap = A + (size_t)(bm + arow) * K + acol;
    const float* Bp = B + (size_t)brow * N + bn + bcol;

    float acc[4][4] = {};

    for (int kk = 0; kk < K; kk += BK) {
        float4 a4 = *(const float4*)Ap;  Ap += BK;
        float4 b4 = *(const float4*)Bp;  Bp += (size_t)BK * N;
        As[acol + 0][arow] = a4.x;
        As[acol + 1][arow] = a4.y;
        As[acol + 2][arow] = a4.z;
        As[acol + 3][arow] = a4.w;
        *(float4*)&Bs[brow][bcol] = b4;
        __syncthreads();
        #pragma unroll
        for (int k = 0; k < BK; k++) {
            float a0 = As[k][tr + 0], a1 = As[k][tr + 1], a2 = As[k][tr + 2], a3 = As[k][tr + 3];
            float4 b = *(const float4*)&Bs[k][tc];
            acc[0][0] += a0 * b.x; acc[0][1] += a0 * b.y; acc[0][2] += a0 * b.z; acc[0][3] += a0 * b.w;
            acc[1][0] += a1 * b.x; acc[1][1] += a1 * b.y; acc[1][2] += a1 * b.z; acc[1][3] += a1 * b.w;
            acc[2][0] += a2 * b.x; acc[2][1] += a2 * b.y; acc[2][2] += a2 * b.z; acc[2][3] += a2 * b.w;
            acc[3][0] += a3 * b.x; acc[3][1] += a3 * b.y; acc[3][2] += a3 * b.z; acc[3][3] += a3 * b.w;
        }
        __syncthreads();
    }

    #pragma unroll
    for (int i = 0; i < 4; i++) {
        int row = bm + tr + i;
        size_t off = (size_t)row * N + bn + tc;
        float4 r;
        r.x = acc[i][0]; r.y = acc[i][1]; r.z = acc[i][2]; r.w = acc[i][3];
        if (HAS_BIAS) {
            r.x += bias[bn + tc + 0]; r.y += bias[bn + tc + 1];
            r.z += bias[bn + tc + 2]; r.w += bias[bn + tc + 3];
        }
        if (HAS_RES) {
            float4 rr = *(const float4*)(res + off);
            r.x += rr.x; r.y += rr.y; r.z += rr.z; r.w += rr.w;
        }
        *(float4*)(C + off) = r;
    }
}

// ---------------- Flash attention (fp32, BQ=64, BKV=32, HD=64) ----------------
// Q/K/V layout: [token, head*64 + d]. One block = (q-tile, batch*head).
__global__ __launch_bounds__(256) void flash_attn_kernel(
    const float* __restrict__ Q, const float* __restrict__ Kb,
    const float* __restrict__ Vb, float* __restrict__ O)
{
    const int BQ = 64, BKV = 32;
    __shared__ float sQ[BQ][HD + 4];
    __shared__ float sK[BKV][HD + 4];
    __shared__ float sV[BKV][HD + 4];
    __shared__ float sP[BQ][BKV + 4];

    int tid = threadIdx.x;          // 256
    int bh = blockIdx.y;
    int b = bh >> 4, h = bh & 15;
    int q0 = blockIdx.x * BQ;
    size_t base = ((size_t)b * LSEQ) * DM + (size_t)h * HD;

    // load Q tile: 64 rows x 16 float4
    #pragma unroll
    for (int i = 0; i < 4; i++) {
        int flat = tid + 256 * i;
        int r = flat >> 4, c4 = flat & 15;
        *(float4*)&sQ[r][c4 * 4] =
            *(const float4*)(Q + base + (size_t)(q0 + r) * DM + c4 * 4);
    }

    int r  = tid >> 2;      // query row this thread serves (0..63)
    int qd = tid & 3;       // quad id within row
    int d0 = qd * 16;       // output-dim slice

    float m_r = -1e30f, l_r = 0.f;
    float o[16];
    #pragma unroll
    for (int c = 0; c < 16; c++) o[c] = 0.f;

    for (int kv = 0; kv < LSEQ; kv += BKV) {
        __syncthreads();   // previous-iteration smem reads done
        #pragma unroll
        for (int i = 0; i < 2; i++) {
            int flat = tid + 256 * i;
            int rr = flat >> 4, c4 = flat & 15;
            *(float4*)&sK[rr][c4 * 4] =
                *(const float4*)(Kb + base + (size_t)(kv + rr) * DM + c4 * 4);
            *(float4*)&sV[rr][c4 * 4] =
                *(const float4*)(Vb + base + (size_t)(kv + rr) * DM + c4 * 4);
        }
        __syncthreads();

        // S tile: thread covers j = qd + 4*jj, jj=0..7
        float s[8];
        #pragma unroll
        for (int jj = 0; jj < 8; jj++) s[jj] = 0.f;
        #pragma unroll
        for (int d = 0; d < HD; d += 4) {
            float4 qv = *(const float4*)&sQ[r][d];
            #pragma unroll
            for (int jj = 0; jj < 8; jj++) {
                float4 k4 = *(const float4*)&sK[qd + jj * 4][d];
                s[jj] += qv.x * k4.x + qv.y * k4.y + qv.z * k4.z + qv.w * k4.w;
            }
        }
        #pragma unroll
        for (int jj = 0; jj < 8; jj++) s[jj] *= 0.125f;  // 1/sqrt(64)

        float tmax = s[0];
        #pragma unroll
        for (int jj = 1; jj < 8; jj++) tmax = fmaxf(tmax, s[jj]);
        tmax = fmaxf(tmax, __shfl_xor_sync(0xffffffffu, tmax, 1));
        tmax = fmaxf(tmax, __shfl_xor_sync(0xffffffffu, tmax, 2));
        float m_new = fmaxf(m_r, tmax);

        float psum = 0.f;
        #pragma unroll
        for (int jj = 0; jj < 8; jj++) {
            float p = __expf(s[jj] - m_new);
            sP[r][qd + jj * 4] = p;
            psum += p;
        }
        psum += __shfl_xor_sync(0xffffffffu, psum, 1);
        psum += __shfl_xor_sync(0xffffffffu, psum, 2);

        float fac = __expf(m_r - m_new);
        l_r = l_r * fac + psum;
        m_r = m_new;
        #pragma unroll
        for (int c = 0; c < 16; c++) o[c] *= fac;
        __syncthreads();   // P visible

        #pragma unroll 4
        for (int j = 0; j < BKV; j++) {
            float p = sP[r][j];
            #pragma unroll
            for (int c = 0; c < 16; c += 4) {
                float4 vv = *(const float4*)&sV[j][d0 + c];
                o[c + 0] += p * vv.x; o[c + 1] += p * vv.y;
                o[c + 2] += p * vv.z; o[c + 3] += p * vv.w;
            }
        }
    }

    float inv = 1.f / l_r;
    #pragma unroll
    for (int c = 0; c < 16; c += 4) {
        float4 w4;
        w4.x = o[c + 0] * inv; w4.y = o[c + 1] * inv;
        w4.z = o[c + 2] * inv; w4.w = o[c + 3] * inv;
        *(float4*)(O + base + (size_t)(q0 + r) * DM + d0 + c) = w4;
    }
}

// ---------------- SwiGLU elementwise: g = silu(g) * u ----------------
__global__ __launch_bounds__(256) void swiglu_kernel(
    float* __restrict__ g, const float* __restrict__ u, size_t n)
{
    size_t i = (size_t)blockIdx.x * 256 + threadIdx.x;
    if (i < n) {
        float x = g[i];
        float sig = 1.f / (1.f + __expf(-x));
        g[i] = x * sig * u[i];
    }
}

// ---------------- launch ----------------
extern "C" void kernel_launch(void* const* d_in, const int* in_sizes, int n_in,
                              void* d_out, int out_size)
{
    const float* x           = (const float*)d_in[0];
    const float* W_q         = (const float*)d_in[1];
    const float* W_k         = (const float*)d_in[2];
    const float* W_v         = (const float*)d_in[3];
    const float* W_o         = (const float*)d_in[4];
    const float* b_o         = (const float*)d_in[5];
    const float* attn_norm_w = (const float*)d_in[6];
    const float* ffn_norm_w  = (const float*)d_in[7];
    const float* W_gate      = (const float*)d_in[8];
    const float* W_hidden    = (const float*)d_in[9];
    const float* W_out       = (const float*)d_in[10];
    const float* b_out       = (const float*)d_in[11];
    float* out = (float*)d_out;

    float *xn, *q, *k, *v, *att, *x1, *xn2, *gate, *hid;
    cudaGetSymbolAddress((void**)&xn,   g_xn);
    cudaGetSymbolAddress((void**)&q,    g_q);
    cudaGetSymbolAddress((void**)&k,    g_k);
    cudaGetSymbolAddress((void**)&v,    g_v);
    cudaGetSymbolAddress((void**)&att,  g_att);
    cudaGetSymbolAddress((void**)&x1,   g_x1);
    cudaGetSymbolAddress((void**)&xn2,  g_xn2);
    cudaGetSymbolAddress((void**)&gate, g_gate);
    cudaGetSymbolAddress((void**)&hid,  g_hid);

    dim3 gProj(DM / 64, NT / 64);   // N=1024 GEMMs
    dim3 gFfn (DH / 64, NT / 64);   // N=4096 GEMMs

    // 1. attn pre-norm
    rmsnorm_kernel<<<NT, 256>>>(x, attn_norm_w, xn);
    // 2. Q, K, V projections
    sgemm64<0, 0><<<gProj, 256>>>(xn, W_q, q, NT, DM, DM, nullptr, nullptr);
    sgemm64<0, 0><<<gProj, 256>>>(xn, W_k, k, NT, DM, DM, nullptr, nullptr);
    sgemm64<0, 0><<<gProj, 256>>>(xn, W_v, v, NT, DM, DM, nullptr, nullptr);
    // 3. attention
    flash_attn_kernel<<<dim3(LSEQ / 64, NBATCH * NH), 256>>>(q, k, v, att);
    // 4. output projection + bias + residual
    sgemm64<1, 1><<<gProj, 256>>>(att, W_o, x1, NT, DM, DM, b_o, x);
    // 5. ffn pre-norm
    rmsnorm_kernel<<<NT, 256>>>(x1, ffn_norm_w, xn2);
    // 6. gate & hidden
    sgemm64<0, 0><<<gFfn, 256>>>(xn2, W_gate,   gate, NT, DH, DM, nullptr, nullptr);
    sgemm64<0, 0><<<gFfn, 256>>>(xn2, W_hidden, hid,  NT, DH, DM, nullptr, nullptr);
    // 7. silu(gate) * hidden  (in place into gate)
    swiglu_kernel<<<(unsigned)(((size_t)NT * DH) / 256), 256>>>(gate, hid, (size_t)NT * DH);
    // 8. out projection + bias + residual
    sgemm64<1, 1><<<gProj, 256>>>(gate, W_out, out, NT, DM, DH, b_out, x1);
}

// round 2
// speedup vs baseline: 1.6931x; 1.6931x over previous
#include <cuda_runtime.h>
#include <math.h>

#define NT 4096      // total tokens (B*L)
#define DM 1024      // d_model
#define DH 4096      // d_hidden
#define NH 16
#define HD 64
#define LSEQ 2048
#define NBATCH 2

// ---------------- scratch (static device globals; no runtime alloc) ----------------
__device__ float g_xn [NT * DM];
__device__ float g_q  [NT * DM];
__device__ float g_k  [NT * DM];
__device__ float g_v  [NT * DM];
__device__ float g_att[NT * DM];
__device__ float g_x1 [NT * DM];
__device__ float g_xn2[NT * DM];
__device__ float g_gate[(size_t)NT * DH];
__device__ float g_hid [(size_t)NT * DH];

// ---------------- RMSNorm: one block per row ----------------
__global__ __launch_bounds__(256) void rmsnorm_kernel(
    const float* __restrict__ x, const float* __restrict__ w, float* __restrict__ out)
{
    int row = blockIdx.x;
    const float* xr = x + (size_t)row * DM;
    float s = 0.f;
    for (int i = threadIdx.x; i < DM; i += 256) { float v = xr[i]; s += v * v; }
    __shared__ float red[8];
    #pragma unroll
    for (int o = 16; o > 0; o >>= 1) s += __shfl_xor_sync(0xffffffffu, s, o);
    if ((threadIdx.x & 31) == 0) red[threadIdx.x >> 5] = s;
    __syncthreads();
    if (threadIdx.x < 8) {
        float v = red[threadIdx.x];
        #pragma unroll
        for (int o = 4; o > 0; o >>= 1) v += __shfl_xor_sync(0xffu, v, o);
        if (threadIdx.x == 0) red[0] = v;
    }
    __syncthreads();
    float inv = rsqrtf(red[0] * (1.0f / DM) + 1e-6f);
    float* orow = out + (size_t)row * DM;
    for (int i = threadIdx.x; i < DM; i += 256) orow[i] = w[i] * xr[i] * inv;
}

// ================= tf32 tensor-core GEMM =================
// C[M,N] = A[M,K] @ B[K,N] (+bias)(+res). M%128==0, N%128==0, K%32==0.
// BM=128, BN=128, BK=32, 256 threads (8 warps as 4x2), warp tile 32x64.
// As[m][k] stride 36 (==4 mod 32 -> frag LDS conflict-free)
// Bs[k][n] stride 136 (==8 mod 32 -> frag LDS conflict-free)
#define GBM 128
#define GBN 128
#define GBK 32
#define ASTRIDE 36
#define BSTRIDE 136
#define STAGE_FLOATS (GBM * ASTRIDE + GBK * BSTRIDE)   // 4608 + 4352 = 8960
#define GEMM_SMEM_BYTES (2 * STAGE_FLOATS * 4)         // 71680

__device__ __forceinline__ void cpasync16(float* dst, const float* src) {
    unsigned saddr = (unsigned)__cvta_generic_to_shared(dst);
    asm volatile("cp.async.cg.shared.global [%0], [%1], 16;\n" :: "r"(saddr), "l"(src));
}
__device__ __forceinline__ unsigned cvt_tf32(float x) {
    unsigned r; asm("cvt.rna.tf32.f32 %0, %1;" : "=r"(r) : "f"(x)); return r;
}
__device__ __forceinline__ void mma_tf32(float* c, const unsigned* a, const unsigned* b) {
    asm volatile("mma.sync.aligned.m16n8k8.row.col.f32.tf32.tf32.f32 "
        "{%0,%1,%2,%3}, {%4,%5,%6,%7}, {%8,%9}, {%0,%1,%2,%3};\n"
        : "+f"(c[0]), "+f"(c[1]), "+f"(c[2]), "+f"(c[3])
        : "r"(a[0]), "r"(a[1]), "r"(a[2]), "r"(a[3]), "r"(b[0]), "r"(b[1]));
}

template <int HAS_BIAS, int HAS_RES>
__global__ __launch_bounds__(256, 2) void gemm_tf32(
    const float* __restrict__ A, const float* __restrict__ B, float* __restrict__ C,
    int M, int N, int K, const float* __restrict__ bias, const float* __restrict__ res)
{
    extern __shared__ float smem[];
    int tid = threadIdx.x;
    int bn = blockIdx.x * GBN, bm = blockIdx.y * GBM;
    int lane = tid & 31, g = lane >> 2, tg = lane & 3;
    int wid = tid >> 5;
    int m_base = (wid >> 1) * 32;
    int n_base = (wid & 1) * 64;

    float c[2][8][4];
    #pragma unroll
    for (int mt = 0; mt < 2; mt++)
        #pragma unroll
        for (int nt = 0; nt < 8; nt++)
            #pragma unroll
            for (int i = 0; i < 4; i++) c[mt][nt][i] = 0.f;

    // gmem->smem assignment
    int a_m  = tid >> 3;            // 0..31, +32*i
    int a_c4 = (tid & 7) * 4;       // float col 0..28
    int b_k  = tid >> 5;            // 0..7, +8*i
    int b_c4 = (tid & 31) * 4;      // float col 0..124

    const int iters = K / GBK;

    // stage issue
    {
        float* As = smem;
        float* Bs = As + GBM * ASTRIDE;
        #pragma unroll
        for (int i = 0; i < 4; i++) {
            int m = a_m + 32 * i;
            cpasync16(As + m * ASTRIDE + a_c4, A + (size_t)(bm + m) * K + a_c4);
        }
        #pragma unroll
        for (int i = 0; i < 4; i++) {
            int k = b_k + 8 * i;
            cpasync16(Bs + k * BSTRIDE + b_c4, B + (size_t)k * N + bn + b_c4);
        }
        asm volatile("cp.async.commit_group;\n" ::: "memory");
    }

    for (int it = 0; it < iters; ++it) {
        if (it + 1 < iters) {
            int kk = (it + 1) * GBK;
            float* As = smem + ((it + 1) & 1) * STAGE_FLOATS;
            float* Bs = As + GBM * ASTRIDE;
            #pragma unroll
            for (int i = 0; i < 4; i++) {
                int m = a_m + 32 * i;
                cpasync16(As + m * ASTRIDE + a_c4, A + (size_t)(bm + m) * K + kk + a_c4);
            }
            #pragma unroll
            for (int i = 0; i < 4; i++) {
                int k = b_k + 8 * i;
                cpasync16(Bs + k * BSTRIDE + b_c4, B + (size_t)(kk + k) * N + bn + b_c4);
            }
            asm volatile("cp.async.commit_group;\n" ::: "memory");
            asm volatile("cp.async.wait_group 1;\n" ::: "memory");
        } else {
            asm volatile("cp.async.wait_group 0;\n" ::: "memory");
        }
        __syncthreads();

        const float* As = smem + (it & 1) * STAGE_FLOATS;
        const float* Bs = As + GBM * ASTRIDE;

        #pragma unroll
        for (int ks = 0; ks < 4; ++ks) {
            unsigned af[2][4], bf[8][2];
            int kc = ks * 8 + tg;
            #pragma unroll
            for (int mt = 0; mt < 2; ++mt) {
                int row = m_base + mt * 16 + g;
                af[mt][0] = cvt_tf32(As[row * ASTRIDE + kc]);
                af[mt][1] = cvt_tf32(As[(row + 8) * ASTRIDE + kc]);
                af[mt][2] = cvt_tf32(As[row * ASTRIDE + kc + 4]);
                af[mt][3] = cvt_tf32(As[(row + 8) * ASTRIDE + kc + 4]);
            }
            #pragma unroll
            for (int nt = 0; nt < 8; ++nt) {
                int coln = n_base + nt * 8 + g;
                bf[nt][0] = cvt_tf32(Bs[kc * BSTRIDE + coln]);
                bf[nt][1] = cvt_tf32(Bs[(kc + 4) * BSTRIDE + coln]);
            }
            #pragma unroll
            for (int mt = 0; mt < 2; ++mt)
                #pragma unroll
                for (int nt = 0; nt < 8; ++nt)
                    mma_tf32(c[mt][nt], af[mt], bf[nt]);
        }
        __syncthreads();
    }

    // epilogue
    #pragma unroll
    for (int mt = 0; mt < 2; ++mt) {
        #pragma unroll
        for (int nt = 0; nt < 8; ++nt) {
            int row = bm + m_base + mt * 16 + g;
            int col = bn + n_base + nt * 8 + 2 * tg;
            size_t o0 = (size_t)row * N + col;
            size_t o1 = (size_t)(row + 8) * N + col;
            float2 v0 = make_float2(c[mt][nt][0], c[mt][nt][1]);
            float2 v1 = make_float2(c[mt][nt][2], c[mt][nt][3]);
            if (HAS_BIAS) {
                float b0v = bias[col], b1v = bias[col + 1];
                v0.x += b0v; v0.y += b1v;
                v1.x += b0v; v1.y += b1v;
            }
            if (HAS_RES) {
                float2 r0 = *(const float2*)(res + o0);
                float2 r1 = *(const float2*)(res + o1);
                v0.x += r0.x; v0.y += r0.y;
                v1.x += r1.x; v1.y += r1.y;
            }
            *(float2*)(C + o0) = v0;
            *(float2*)(C + o1) = v1;
        }
    }
}

// ---------------- Flash attention (fp32, BQ=64, BKV=32, HD=64) ----------------
__global__ __launch_bounds__(256) void flash_attn_kernel(
    const float* __restrict__ Q, const float* __restrict__ Kb,
    const float* __restrict__ Vb, float* __restrict__ O)
{
    const int BQ = 64, BKV = 32;
    __shared__ float sQ[BQ][HD + 4];
    __shared__ float sK[BKV][HD + 4];
    __shared__ float sV[BKV][HD + 4];
    __shared__ float sP[BQ][BKV + 4];

    int tid = threadIdx.x;          // 256
    int bh = blockIdx.y;
    int b = bh >> 4, h = bh & 15;
    int q0 = blockIdx.x * BQ;
    size_t base = ((size_t)b * LSEQ) * DM + (size_t)h * HD;

    #pragma unroll
    for (int i = 0; i < 4; i++) {
        int flat = tid + 256 * i;
        int r = flat >> 4, c4 = flat & 15;
        *(float4*)&sQ[r][c4 * 4] =
            *(const float4*)(Q + base + (size_t)(q0 + r) * DM + c4 * 4);
    }

    int r  = tid >> 2;
    int qd = tid & 3;
    int d0 = qd * 16;

    float m_r = -1e30f, l_r = 0.f;
    float o[16];
    #pragma unroll
    for (int c = 0; c < 16; c++) o[c] = 0.f;

    for (int kv = 0; kv < LSEQ; kv += BKV) {
        __syncthreads();
        #pragma unroll
        for (int i = 0; i < 2; i++) {
            int flat = tid + 256 * i;
            int rr = flat >> 4, c4 = flat & 15;
            *(float4*)&sK[rr][c4 * 4] =
                *(const float4*)(Kb + base + (size_t)(kv + rr) * DM + c4 * 4);
            *(float4*)&sV[rr][c4 * 4] =
                *(const float4*)(Vb + base + (size_t)(kv + rr) * DM + c4 * 4);
        }
        __syncthreads();

        float s[8];
        #pragma unroll
        for (int jj = 0; jj < 8; jj++) s[jj] = 0.f;
        #pragma unroll
        for (int d = 0; d < HD; d += 4) {
            float4 qv = *(const float4*)&sQ[r][d];
            #pragma unroll
            for (int jj = 0; jj < 8; jj++) {
                float4 k4 = *(const float4*)&sK[qd + jj * 4][d];
                s[jj] += qv.x * k4.x + qv.y * k4.y + qv.z * k4.z + qv.w * k4.w;
            }
        }
        #pragma unroll
        for (int jj = 0; jj < 8; jj++) s[jj] *= 0.125f;

        float tmax = s[0];
        #pragma unroll
        for (int jj = 1; jj < 8; jj++) tmax = fmaxf(tmax, s[jj]);
        tmax = fmaxf(tmax, __shfl_xor_sync(0xffffffffu, tmax, 1));
        tmax = fmaxf(tmax, __shfl_xor_sync(0xffffffffu, tmax, 2));
        float m_new = fmaxf(m_r, tmax);

        float psum = 0.f;
        #pragma unroll
        for (int jj = 0; jj < 8; jj++) {
            float p = __expf(s[jj] - m_new);
            sP[r][qd + jj * 4] = p;
            psum += p;
        }
        psum += __shfl_xor_sync(0xffffffffu, psum, 1);
        psum += __shfl_xor_sync(0xffffffffu, psum, 2);

        float fac = __expf(m_r - m_new);
        l_r = l_r * fac + psum;
        m_r = m_new;
        #pragma unroll
        for (int c = 0; c < 16; c++) o[c] *= fac;
        __syncthreads();

        #pragma unroll 4
        for (int j = 0; j < BKV; j++) {
            float p = sP[r][j];
            #pragma unroll
            for (int c = 0; c < 16; c += 4) {
                float4 vv = *(const float4*)&sV[j][d0 + c];
                o[c + 0] += p * vv.x; o[c + 1] += p * vv.y;
                o[c + 2] += p * vv.z; o[c + 3] += p * vv.w;
            }
        }
    }

    float inv = 1.f / l_r;
    #pragma unroll
    for (int c = 0; c < 16; c += 4) {
        float4 w4;
        w4.x = o[c + 0] * inv; w4.y = o[c + 1] * inv;
        w4.z = o[c + 2] * inv; w4.w = o[c + 3] * inv;
        *(float4*)(O + base + (size_t)(q0 + r) * DM + d0 + c) = w4;
    }
}

// ---------------- SwiGLU elementwise ----------------
__global__ __launch_bounds__(256) void swiglu_kernel(
    float* __restrict__ g, const float* __restrict__ u, size_t n)
{
    size_t i = (size_t)blockIdx.x * 256 + threadIdx.x;
    if (i < n) {
        float x = g[i];
        float sig = 1.f / (1.f + __expf(-x));
        g[i] = x * sig * u[i];
    }
}

// ---------------- launch ----------------
extern "C" void kernel_launch(void* const* d_in, const int* in_sizes, int n_in,
                              void* d_out, int out_size)
{
    const float* x           = (const float*)d_in[0];
    const float* W_q         = (const float*)d_in[1];
    const float* W_k         = (const float*)d_in[2];
    const float* W_v         = (const float*)d_in[3];
    const float* W_o         = (const float*)d_in[4];
    const float* b_o         = (const float*)d_in[5];
    const float* attn_norm_w = (const float*)d_in[6];
    const float* ffn_norm_w  = (const float*)d_in[7];
    const float* W_gate      = (const float*)d_in[8];
    const float* W_hidden    = (const float*)d_in[9];
    const float* W_out       = (const float*)d_in[10];
    const float* b_out       = (const float*)d_in[11];
    float* out = (float*)d_out;

    float *xn, *q, *k, *v, *att, *x1, *xn2, *gate, *hid;
    cudaGetSymbolAddress((void**)&xn,   g_xn);
    cudaGetSymbolAddress((void**)&q,    g_q);
    cudaGetSymbolAddress((void**)&k,    g_k);
    cudaGetSymbolAddress((void**)&v,    g_v);
    cudaGetSymbolAddress((void**)&att,  g_att);
    cudaGetSymbolAddress((void**)&x1,   g_x1);
    cudaGetSymbolAddress((void**)&xn2,  g_xn2);
    cudaGetSymbolAddress((void**)&gate, g_gate);
    cudaGetSymbolAddress((void**)&hid,  g_hid);

    static int smem_set = 0;
    if (!smem_set) {
        cudaFuncSetAttribute(gemm_tf32<0, 0>,
            cudaFuncAttributeMaxDynamicSharedMemorySize, GEMM_SMEM_BYTES);
        cudaFuncSetAttribute(gemm_tf32<1, 1>,
            cudaFuncAttributeMaxDynamicSharedMemorySize, GEMM_SMEM_BYTES);
        smem_set = 1;
    }

    dim3 gProj(DM / GBN, NT / GBM);   // (8, 32)
    dim3 gFfn (DH / GBN, NT / GBM);   // (32, 32)

    rmsnorm_kernel<<<NT, 256>>>(x, attn_norm_w, xn);
    gemm_tf32<0, 0><<<gProj, 256, GEMM_SMEM_BYTES>>>(xn, W_q, q, NT, DM, DM, nullptr, nullptr);
    gemm_tf32<0, 0><<<gProj, 256, GEMM_SMEM_BYTES>>>(xn, W_k, k, NT, DM, DM, nullptr, nullptr);
    gemm_tf32<0, 0><<<gProj, 256, GEMM_SMEM_BYTES>>>(xn, W_v, v, NT, DM, DM, nullptr, nullptr);
    flash_attn_kernel<<<dim3(LSEQ / 64, NBATCH * NH), 256>>>(q, k, v, att);
    gemm_tf32<1, 1><<<gProj, 256, GEMM_SMEM_BYTES>>>(att, W_o, x1, NT, DM, DM, b_o, x);
    rmsnorm_kernel<<<NT, 256>>>(x1, ffn_norm_w, xn2);
    gemm_tf32<0, 0><<<gFfn, 256, GEMM_SMEM_BYTES>>>(xn2, W_gate,   gate, NT, DH, DM, nullptr, nullptr);
    gemm_tf32<0, 0><<<gFfn, 256, GEMM_SMEM_BYTES>>>(xn2, W_hidden, hid,  NT, DH, DM, nullptr, nullptr);
    swiglu_kernel<<<(unsigned)(((size_t)NT * DH) / 256), 256>>>(gate, hid, (size_t)NT * DH);
    gemm_tf32<1, 1><<<gProj, 256, GEMM_SMEM_BYTES>>>(gate, W_out, out, NT, DM, DH, b_out, x1);
}

// round 3
// speedup vs baseline: 4.6491x; 2.7459x over previous
#include <cuda_runtime.h>
#include <math.h>

#define NT 4096      // total tokens (B*L)
#define DM 1024      // d_model
#define DH 4096      // d_hidden
#define NH 16
#define HD 64
#define LSEQ 2048
#define NBATCH 2

// ---------------- scratch (static device globals; no runtime alloc) ----------------
__device__ float g_xn [NT * DM];
__device__ float g_q  [NT * DM];
__device__ float g_k  [NT * DM];
__device__ float g_v  [NT * DM];
__device__ float g_att[NT * DM];
__device__ float g_x1 [NT * DM];
__device__ float g_xn2[NT * DM];
__device__ float g_gate[(size_t)NT * DH];
__device__ float g_hid [(size_t)NT * DH];

// ---------------- common PTX helpers ----------------
__device__ __forceinline__ void cpasync16(float* dst, const float* src) {
    unsigned saddr = (unsigned)__cvta_generic_to_shared(dst);
    asm volatile("cp.async.cg.shared.global [%0], [%1], 16;\n" :: "r"(saddr), "l"(src));
}
__device__ __forceinline__ unsigned cvt_tf32(float x) {
    unsigned r; asm("cvt.rna.tf32.f32 %0, %1;" : "=r"(r) : "f"(x)); return r;
}
__device__ __forceinline__ void mma_tf32(float* c, const unsigned* a, const unsigned* b) {
    asm volatile("mma.sync.aligned.m16n8k8.row.col.f32.tf32.tf32.f32 "
        "{%0,%1,%2,%3}, {%4,%5,%6,%7}, {%8,%9}, {%0,%1,%2,%3};\n"
        : "+f"(c[0]), "+f"(c[1]), "+f"(c[2]), "+f"(c[3])
        : "r"(a[0]), "r"(a[1]), "r"(a[2]), "r"(a[3]), "r"(b[0]), "r"(b[1]));
}

// ---------------- RMSNorm: one block per row ----------------
__global__ __launch_bounds__(256) void rmsnorm_kernel(
    const float* __restrict__ x, const float* __restrict__ w, float* __restrict__ out)
{
    int row = blockIdx.x;
    const float* xr = x + (size_t)row * DM;
    float s = 0.f;
    for (int i = threadIdx.x; i < DM; i += 256) { float v = xr[i]; s += v * v; }
    __shared__ float red[8];
    #pragma unroll
    for (int o = 16; o > 0; o >>= 1) s += __shfl_xor_sync(0xffffffffu, s, o);
    if ((threadIdx.x & 31) == 0) red[threadIdx.x >> 5] = s;
    __syncthreads();
    if (threadIdx.x < 8) {
        float v = red[threadIdx.x];
        #pragma unroll
        for (int o = 4; o > 0; o >>= 1) v += __shfl_xor_sync(0xffu, v, o);
        if (threadIdx.x == 0) red[0] = v;
    }
    __syncthreads();
    float inv = rsqrtf(red[0] * (1.0f / DM) + 1e-6f);
    float* orow = out + (size_t)row * DM;
    for (int i = threadIdx.x; i < DM; i += 256) orow[i] = w[i] * xr[i] * inv;
}

// ================= tf32 tensor-core GEMM =================
#define GBM 128
#define GBN 128
#define GBK 32
#define ASTRIDE 36
#define BSTRIDE 136
#define STAGE_FLOATS (GBM * ASTRIDE + GBK * BSTRIDE)
#define GEMM_SMEM_BYTES (2 * STAGE_FLOATS * 4)

template <int HAS_BIAS, int HAS_RES>
__global__ __launch_bounds__(256, 2) void gemm_tf32(
    const float* __restrict__ A, const float* __restrict__ B, float* __restrict__ C,
    int M, int N, int K, const float* __restrict__ bias, const float* __restrict__ res)
{
    extern __shared__ float smem[];
    int tid = threadIdx.x;
    int bn = blockIdx.x * GBN, bm = blockIdx.y * GBM;
    int lane = tid & 31, g = lane >> 2, tg = lane & 3;
    int wid = tid >> 5;
    int m_base = (wid >> 1) * 32;
    int n_base = (wid & 1) * 64;

    float c[2][8][4];
    #pragma unroll
    for (int mt = 0; mt < 2; mt++)
        #pragma unroll
        for (int nt = 0; nt < 8; nt++)
            #pragma unroll
            for (int i = 0; i < 4; i++) c[mt][nt][i] = 0.f;

    int a_m  = tid >> 3;
    int a_c4 = (tid & 7) * 4;
    int b_k  = tid >> 5;
    int b_c4 = (tid & 31) * 4;

    const int iters = K / GBK;

    {
        float* As = smem;
        float* Bs = As + GBM * ASTRIDE;
        #pragma unroll
        for (int i = 0; i < 4; i++) {
            int m = a_m + 32 * i;
            cpasync16(As + m * ASTRIDE + a_c4, A + (size_t)(bm + m) * K + a_c4);
        }
        #pragma unroll
        for (int i = 0; i < 4; i++) {
            int k = b_k + 8 * i;
            cpasync16(Bs + k * BSTRIDE + b_c4, B + (size_t)k * N + bn + b_c4);
        }
        asm volatile("cp.async.commit_group;\n" ::: "memory");
    }

    for (int it = 0; it < iters; ++it) {
        if (it + 1 < iters) {
            int kk = (it + 1) * GBK;
            float* As = smem + ((it + 1) & 1) * STAGE_FLOATS;
            float* Bs = As + GBM * ASTRIDE;
            #pragma unroll
            for (int i = 0; i < 4; i++) {
                int m = a_m + 32 * i;
                cpasync16(As + m * ASTRIDE + a_c4, A + (size_t)(bm + m) * K + kk + a_c4);
            }
            #pragma unroll
            for (int i = 0; i < 4; i++) {
                int k = b_k + 8 * i;
                cpasync16(Bs + k * BSTRIDE + b_c4, B + (size_t)(kk + k) * N + bn + b_c4);
            }
            asm volatile("cp.async.commit_group;\n" ::: "memory");
            asm volatile("cp.async.wait_group 1;\n" ::: "memory");
        } else {
            asm volatile("cp.async.wait_group 0;\n" ::: "memory");
        }
        __syncthreads();

        const float* As = smem + (it & 1) * STAGE_FLOATS;
        const float* Bs = As + GBM * ASTRIDE;

        #pragma unroll
        for (int ks = 0; ks < 4; ++ks) {
            unsigned af[2][4], bf[8][2];
            int kc = ks * 8 + tg;
            #pragma unroll
            for (int mt = 0; mt < 2; ++mt) {
                int row = m_base + mt * 16 + g;
                af[mt][0] = cvt_tf32(As[row * ASTRIDE + kc]);
                af[mt][1] = cvt_tf32(As[(row + 8) * ASTRIDE + kc]);
                af[mt][2] = cvt_tf32(As[row * ASTRIDE + kc + 4]);
                af[mt][3] = cvt_tf32(As[(row + 8) * ASTRIDE + kc + 4]);
            }
            #pragma unroll
            for (int nt = 0; nt < 8; ++nt) {
                int coln = n_base + nt * 8 + g;
                bf[nt][0] = cvt_tf32(Bs[kc * BSTRIDE + coln]);
                bf[nt][1] = cvt_tf32(Bs[(kc + 4) * BSTRIDE + coln]);
            }
            #pragma unroll
            for (int mt = 0; mt < 2; ++mt)
                #pragma unroll
                for (int nt = 0; nt < 8; ++nt)
                    mma_tf32(c[mt][nt], af[mt], bf[nt]);
        }
        __syncthreads();
    }

    #pragma unroll
    for (int mt = 0; mt < 2; ++mt) {
        #pragma unroll
        for (int nt = 0; nt < 8; ++nt) {
            int row = bm + m_base + mt * 16 + g;
            int col = bn + n_base + nt * 8 + 2 * tg;
            size_t o0 = (size_t)row * N + col;
            size_t o1 = (size_t)(row + 8) * N + col;
            float2 v0 = make_float2(c[mt][nt][0], c[mt][nt][1]);
            float2 v1 = make_float2(c[mt][nt][2], c[mt][nt][3]);
            if (HAS_BIAS) {
                float b0v = bias[col], b1v = bias[col + 1];
                v0.x += b0v; v0.y += b1v;
                v1.x += b0v; v1.y += b1v;
            }
            if (HAS_RES) {
                float2 r0 = *(const float2*)(res + o0);
                float2 r1 = *(const float2*)(res + o1);
                v0.x += r0.x; v0.y += r0.y;
                v1.x += r1.x; v1.y += r1.y;
            }
            *(float2*)(C + o0) = v0;
            *(float2*)(C + o1) = v1;
        }
    }
}

// ================= tensor-core flash attention =================
// BQ=128, BKV=64, HD=64. 256 threads (8 warps), warp owns 16 q-rows.
// S = Q K^T and O += P V via mma.m16n8k8 tf32. Online softmax in registers.
// Strides: row-index-varies-with-g loads need stride%32==4 (sK=68, sP=68);
//          row-index-varies-with-tg loads need stride%32==8 (sV=72).
#define FBQ 128
#define FBKV 64
#define KSTR 68
#define VSTR 72
#define PSTR 68
#define FA_SMEM_FLOATS (2 * FBKV * KSTR + 2 * FBKV * VSTR + FBQ * PSTR)
#define FA_SMEM_BYTES (FA_SMEM_FLOATS * 4)   // 106496

__global__ __launch_bounds__(256, 1) void flash_tc_kernel(
    const float* __restrict__ Q, const float* __restrict__ Kb,
    const float* __restrict__ Vb, float* __restrict__ O)
{
    extern __shared__ float fsm[];
    float* sK = fsm;
    float* sV = fsm + 2 * FBKV * KSTR;
    float* sP = fsm + 2 * FBKV * KSTR + 2 * FBKV * VSTR;

    int tid = threadIdx.x;
    int lane = tid & 31, g = lane >> 2, tg = lane & 3;
    int wid = tid >> 5;
    int mrow = wid * 16;

    int bh = blockIdx.y;
    int b = bh >> 4, h = bh & 15;
    int q0 = blockIdx.x * FBQ;
    size_t base = ((size_t)b * LSEQ) * DM + (size_t)h * HD;

    // ---- stage Q through sP, build per-warp Q fragments ----
    #pragma unroll
    for (int i = 0; i < 8; i++) {
        int flat = tid + 256 * i;
        int r = flat >> 4, c4 = (flat & 15) * 4;
        *(float4*)&sP[r * PSTR + c4] =
            *(const float4*)(Q + base + (size_t)(q0 + r) * DM + c4);
    }
    __syncthreads();
    unsigned aq[8][4];
    #pragma unroll
    for (int ks = 0; ks < 8; ks++) {
        int kc = ks * 8 + tg;
        aq[ks][0] = cvt_tf32(sP[(mrow + g) * PSTR + kc]);
        aq[ks][1] = cvt_tf32(sP[(mrow + g + 8) * PSTR + kc]);
        aq[ks][2] = cvt_tf32(sP[(mrow + g) * PSTR + kc + 4]);
        aq[ks][3] = cvt_tf32(sP[(mrow + g + 8) * PSTR + kc + 4]);
    }
    __syncthreads();   // sP free for P tiles now

    // K/V gmem->smem cooperative load indices
    int kv_r  = tid >> 4;           // 0..15, +16*i
    int kv_c4 = (tid & 15) * 4;

    // prologue: stage 0
    #pragma unroll
    for (int i = 0; i < 4; i++) {
        int rr = kv_r + 16 * i;
        cpasync16(sK + rr * KSTR + kv_c4, Kb + base + (size_t)rr * DM + kv_c4);
        cpasync16(sV + rr * VSTR + kv_c4, Vb + base + (size_t)rr * DM + kv_c4);
    }
    asm volatile("cp.async.commit_group;\n" ::: "memory");

    float m0 = -1e30f, m1 = -1e30f, l0 = 0.f, l1 = 0.f;
    float co[8][4];
    #pragma unroll
    for (int nt = 0; nt < 8; nt++)
        #pragma unroll
        for (int i = 0; i < 4; i++) co[nt][i] = 0.f;

    const int ITERS = LSEQ / FBKV;   // 32
    for (int it = 0; it < ITERS; ++it) {
        if (it + 1 < ITERS) {
            int st = (it + 1) & 1;
            size_t kvoff = (size_t)(it + 1) * FBKV * DM;
            #pragma unroll
            for (int i = 0; i < 4; i++) {
                int rr = kv_r + 16 * i;
                cpasync16(sK + st * FBKV * KSTR + rr * KSTR + kv_c4,
                          Kb + base + kvoff + (size_t)rr * DM + kv_c4);
                cpasync16(sV + st * FBKV * VSTR + rr * VSTR + kv_c4,
                          Vb + base + kvoff + (size_t)rr * DM + kv_c4);
            }
            asm volatile("cp.async.commit_group;\n" ::: "memory");
            asm volatile("cp.async.wait_group 1;\n" ::: "memory");
        } else {
            asm volatile("cp.async.wait_group 0;\n" ::: "memory");
        }
        __syncthreads();

        const float* K_ = sK + (it & 1) * FBKV * KSTR;
        const float* V_ = sV + (it & 1) * FBKV * VSTR;

        // ---- S = Q K^T : warp computes 16 x 64 ----
        float cs[8][4];
        #pragma unroll
        for (int nt = 0; nt < 8; nt++)
            #pragma unroll
            for (int i = 0; i < 4; i++) cs[nt][i] = 0.f;

        #pragma unroll
        for (int ks = 0; ks < 8; ks++) {
            int kc = ks * 8 + tg;
            unsigned bf[8][2];
            #pragma unroll
            for (int nt = 0; nt < 8; nt++) {
                bf[nt][0] = cvt_tf32(K_[(nt * 8 + g) * KSTR + kc]);
                bf[nt][1] = cvt_tf32(K_[(nt * 8 + g) * KSTR + kc + 4]);
            }
            #pragma unroll
            for (int nt = 0; nt < 8; nt++)
                mma_tf32(cs[nt], aq[ks], bf[nt]);
        }

        // ---- online softmax (rows g and g+8 of warp slab) ----
        float rm0 = -1e30f, rm1 = -1e30f;
        #pragma unroll
        for (int nt = 0; nt < 8; nt++) {
            #pragma unroll
            for (int i = 0; i < 4; i++) cs[nt][i] *= 0.125f;
            rm0 = fmaxf(rm0, fmaxf(cs[nt][0], cs[nt][1]));
            rm1 = fmaxf(rm1, fmaxf(cs[nt][2], cs[nt][3]));
        }
        rm0 = fmaxf(rm0, __shfl_xor_sync(0xffffffffu, rm0, 1));
        rm0 = fmaxf(rm0, __shfl_xor_sync(0xffffffffu, rm0, 2));
        rm1 = fmaxf(rm1, __shfl_xor_sync(0xffffffffu, rm1, 1));
        rm1 = fmaxf(rm1, __shfl_xor_sync(0xffffffffu, rm1, 2));
        float mn0 = fmaxf(m0, rm0);
        float mn1 = fmaxf(m1, rm1);

        float ps0 = 0.f, ps1 = 0.f;
        #pragma unroll
        for (int nt = 0; nt < 8; nt++) {
            float p00 = __expf(cs[nt][0] - mn0);
            float p01 = __expf(cs[nt][1] - mn0);
            float p10 = __expf(cs[nt][2] - mn1);
            float p11 = __expf(cs[nt][3] - mn1);
            ps0 += p00 + p01;
            ps1 += p10 + p11;
            int col = nt * 8 + 2 * tg;
            sP[(mrow + g) * PSTR + col]     = p00;
            sP[(mrow + g) * PSTR + col + 1] = p01;
            sP[(mrow + g + 8) * PSTR + col]     = p10;
            sP[(mrow + g + 8) * PSTR + col + 1] = p11;
        }
        ps0 += __shfl_xor_sync(0xffffffffu, ps0, 1);
        ps0 += __shfl_xor_sync(0xffffffffu, ps0, 2);
        ps1 += __shfl_xor_sync(0xffffffffu, ps1, 1);
        ps1 += __shfl_xor_sync(0xffffffffu, ps1, 2);

        float f0 = __expf(m0 - mn0);
        float f1 = __expf(m1 - mn1);
        l0 = l0 * f0 + ps0;
        l1 = l1 * f1 + ps1;
        m0 = mn0; m1 = mn1;
        #pragma unroll
        for (int nt = 0; nt < 8; nt++) {
            co[nt][0] *= f0; co[nt][1] *= f0;
            co[nt][2] *= f1; co[nt][3] *= f1;
        }
        __syncwarp();   // P slab is warp-private

        // ---- O += P V : warp computes 16 x 64 ----
        #pragma unroll
        for (int ks = 0; ks < 8; ks++) {
            int kc = ks * 8 + tg;
            unsigned ap[4];
            ap[0] = cvt_tf32(sP[(mrow + g) * PSTR + kc]);
            ap[1] = cvt_tf32(sP[(mrow + g + 8) * PSTR + kc]);
            ap[2] = cvt_tf32(sP[(mrow + g) * PSTR + kc + 4]);
            ap[3] = cvt_tf32(sP[(mrow + g + 8) * PSTR + kc + 4]);
            unsigned bv[8][2];
            #pragma unroll
            for (int nt = 0; nt < 8; nt++) {
                bv[nt][0] = cvt_tf32(V_[kc * VSTR + nt * 8 + g]);
                bv[nt][1] = cvt_tf32(V_[(kc + 4) * VSTR + nt * 8 + g]);
            }
            #pragma unroll
            for (int nt = 0; nt < 8; nt++)
                mma_tf32(co[nt], ap, bv[nt]);
        }
        __syncwarp();
        __syncthreads();   // all warps done with this K/V stage
    }

    // ---- normalize + write out ----
    float i0 = 1.f / l0, i1 = 1.f / l1;
    #pragma unroll
    for (int nt = 0; nt < 8; nt++) {
        int col = nt * 8 + 2 * tg;
        size_t o0 = base + (size_t)(q0 + mrow + g) * DM + col;
        size_t o1 = base + (size_t)(q0 + mrow + g + 8) * DM + col;
        *(float2*)(O + o0) = make_float2(co[nt][0] * i0, co[nt][1] * i0);
        *(float2*)(O + o1) = make_float2(co[nt][2] * i1, co[nt][3] * i1);
    }
}

// ---------------- SwiGLU elementwise ----------------
__global__ __launch_bounds__(256) void swiglu_kernel(
    float* __restrict__ g, const float* __restrict__ u, size_t n)
{
    size_t i = (size_t)blockIdx.x * 256 + threadIdx.x;
    if (i < n) {
        float x = g[i];
        float sig = 1.f / (1.f + __expf(-x));
        g[i] = x * sig * u[i];
    }
}

// ---------------- launch ----------------
extern "C" void kernel_launch(void* const* d_in, const int* in_sizes, int n_in,
                              void* d_out, int out_size)
{
    const float* x           = (const float*)d_in[0];
    const float* W_q         = (const float*)d_in[1];
    const float* W_k         = (const float*)d_in[2];
    const float* W_v         = (const float*)d_in[3];
    const float* W_o         = (const float*)d_in[4];
    const float* b_o         = (const float*)d_in[5];
    const float* attn_norm_w = (const float*)d_in[6];
    const float* ffn_norm_w  = (const float*)d_in[7];
    const float* W_gate      = (const float*)d_in[8];
    const float* W_hidden    = (const float*)d_in[9];
    const float* W_out       = (const float*)d_in[10];
    const float* b_out       = (const float*)d_in[11];
    float* out = (float*)d_out;

    float *xn, *q, *k, *v, *att, *x1, *xn2, *gate, *hid;
    cudaGetSymbolAddress((void**)&xn,   g_xn);
    cudaGetSymbolAddress((void**)&q,    g_q);
    cudaGetSymbolAddress((void**)&k,    g_k);
    cudaGetSymbolAddress((void**)&v,    g_v);
    cudaGetSymbolAddress((void**)&att,  g_att);
    cudaGetSymbolAddress((void**)&x1,   g_x1);
    cudaGetSymbolAddress((void**)&xn2,  g_xn2);
    cudaGetSymbolAddress((void**)&gate, g_gate);
    cudaGetSymbolAddress((void**)&hid,  g_hid);

    static int smem_set = 0;
    if (!smem_set) {
        cudaFuncSetAttribute(gemm_tf32<0, 0>,
            cudaFuncAttributeMaxDynamicSharedMemorySize, GEMM_SMEM_BYTES);
        cudaFuncSetAttribute(gemm_tf32<1, 1>,
            cudaFuncAttributeMaxDynamicSharedMemorySize, GEMM_SMEM_BYTES);
        cudaFuncSetAttribute(flash_tc_kernel,
            cudaFuncAttributeMaxDynamicSharedMemorySize, FA_SMEM_BYTES);
        smem_set = 1;
    }

    dim3 gProj(DM / GBN, NT / GBM);
    dim3 gFfn (DH / GBN, NT / GBM);

    rmsnorm_kernel<<<NT, 256>>>(x, attn_norm_w, xn);
    gemm_tf32<0, 0><<<gProj, 256, GEMM_SMEM_BYTES>>>(xn, W_q, q, NT, DM, DM, nullptr, nullptr);
    gemm_tf32<0, 0><<<gProj, 256, GEMM_SMEM_BYTES>>>(xn, W_k, k, NT, DM, DM, nullptr, nullptr);
    gemm_tf32<0, 0><<<gProj, 256, GEMM_SMEM_BYTES>>>(xn, W_v, v, NT, DM, DM, nullptr, nullptr);
    flash_tc_kernel<<<dim3(LSEQ / FBQ, NBATCH * NH), 256, FA_SMEM_BYTES>>>(q, k, v, att);
    gemm_tf32<1, 1><<<gProj, 256, GEMM_SMEM_BYTES>>>(att, W_o, x1, NT, DM, DM, b_o, x);
    rmsnorm_kernel<<<NT, 256>>>(x1, ffn_norm_w, xn2);
    gemm_tf32<0, 0><<<gFfn, 256, GEMM_SMEM_BYTES>>>(xn2, W_gate,   gate, NT, DH, DM, nullptr, nullptr);
    gemm_tf32<0, 0><<<gFfn, 256, GEMM_SMEM_BYTES>>>(xn2, W_hidden, hid,  NT, DH, DM, nullptr, nullptr);
    swiglu_kernel<<<(unsigned)(((size_t)NT * DH) / 256), 256>>>(gate, hid, (size_t)NT * DH);
    gemm_tf32<1, 1><<<gProj, 256, GEMM_SMEM_BYTES>>>(gate, W_out, out, NT, DM, DH, b_out, x1);
}

// round 4
// speedup vs baseline: 5.4013x; 1.1618x over previous
#include <cuda_runtime.h>
#include <math.h>

#define NT 4096      // total tokens (B*L)
#define DM 1024      // d_model
#define DH 4096      // d_hidden
#define NH 16
#define HD 64
#define LSEQ 2048
#define NBATCH 2

// ---------------- scratch (static device globals; no runtime alloc) ----------------
__device__ float g_xn [NT * DM];
__device__ float g_q  [NT * DM];
__device__ float g_k  [NT * DM];
__device__ float g_v  [NT * DM];
__device__ float g_att[NT * DM];
__device__ float g_x1 [NT * DM];
__device__ float g_xn2[NT * DM];
__device__ float g_gate[(size_t)NT * DH];
__device__ float g_hid [(size_t)NT * DH];

// ---------------- common PTX helpers ----------------
__device__ __forceinline__ void cpasync16(float* dst, const float* src) {
    unsigned saddr = (unsigned)__cvta_generic_to_shared(dst);
    asm volatile("cp.async.cg.shared.global [%0], [%1], 16;\n" :: "r"(saddr), "l"(src));
}
// NOTE: tf32 mma reads the top 19 bits of the fp32 bit pattern; feeding raw
// fp32 == truncation rounding. We exploit this to skip cvt entirely.
__device__ __forceinline__ void mma_tf32(float* c, const unsigned* a, const unsigned* b) {
    asm volatile("mma.sync.aligned.m16n8k8.row.col.f32.tf32.tf32.f32 "
        "{%0,%1,%2,%3}, {%4,%5,%6,%7}, {%8,%9}, {%0,%1,%2,%3};\n"
        : "+f"(c[0]), "+f"(c[1]), "+f"(c[2]), "+f"(c[3])
        : "r"(a[0]), "r"(a[1]), "r"(a[2]), "r"(a[3]), "r"(b[0]), "r"(b[1]));
}

// ---------------- RMSNorm: one block per row, float4 ----------------
__global__ __launch_bounds__(256) void rmsnorm_kernel(
    const float* __restrict__ x, const float* __restrict__ w, float* __restrict__ out)
{
    int row = blockIdx.x;
    const float4* xr = (const float4*)(x + (size_t)row * DM);
    float4 v = xr[threadIdx.x];               // DM/4 == 256 == blockDim
    float s = v.x * v.x + v.y * v.y + v.z * v.z + v.w * v.w;
    __shared__ float red[8];
    #pragma unroll
    for (int o = 16; o > 0; o >>= 1) s += __shfl_xor_sync(0xffffffffu, s, o);
    if ((threadIdx.x & 31) == 0) red[threadIdx.x >> 5] = s;
    __syncthreads();
    if (threadIdx.x < 8) {
        float t = red[threadIdx.x];
        #pragma unroll
        for (int o = 4; o > 0; o >>= 1) t += __shfl_xor_sync(0xffu, t, o);
        if (threadIdx.x == 0) red[0] = t;
    }
    __syncthreads();
    float inv = rsqrtf(red[0] * (1.0f / DM) + 1e-6f);
    float4 wv = ((const float4*)w)[threadIdx.x];
    float4 o4;
    o4.x = wv.x * v.x * inv; o4.y = wv.y * v.y * inv;
    o4.z = wv.z * v.z * inv; o4.w = wv.w * v.w * inv;
    ((float4*)(out + (size_t)row * DM))[threadIdx.x] = o4;
}

// ================= tf32 tensor-core GEMM =================
#define GBM 128
#define GBN 128
#define GBK 32
#define ASTRIDE 36
#define BSTRIDE 136
#define STAGE_FLOATS (GBM * ASTRIDE + GBK * BSTRIDE)
#define GEMM_SMEM_BYTES (2 * STAGE_FLOATS * 4)

template <int HAS_BIAS, int HAS_RES>
__global__ __launch_bounds__(256, 2) void gemm_tf32(
    const float* __restrict__ A, const float* __restrict__ B, float* __restrict__ C,
    int M, int N, int K, const float* __restrict__ bias, const float* __restrict__ res)
{
    extern __shared__ float smem[];
    int tid = threadIdx.x;
    int bn = blockIdx.x * GBN, bm = blockIdx.y * GBM;
    int lane = tid & 31, g = lane >> 2, tg = lane & 3;
    int wid = tid >> 5;
    int m_base = (wid >> 1) * 32;
    int n_base = (wid & 1) * 64;

    float c[2][8][4];
    #pragma unroll
    for (int mt = 0; mt < 2; mt++)
        #pragma unroll
        for (int nt = 0; nt < 8; nt++)
            #pragma unroll
            for (int i = 0; i < 4; i++) c[mt][nt][i] = 0.f;

    int a_m  = tid >> 3;
    int a_c4 = (tid & 7) * 4;
    int b_k  = tid >> 5;
    int b_c4 = (tid & 31) * 4;

    const int iters = K / GBK;

    {
        float* As = smem;
        float* Bs = As + GBM * ASTRIDE;
        #pragma unroll
        for (int i = 0; i < 4; i++) {
            int m = a_m + 32 * i;
            cpasync16(As + m * ASTRIDE + a_c4, A + (size_t)(bm + m) * K + a_c4);
        }
        #pragma unroll
        for (int i = 0; i < 4; i++) {
            int k = b_k + 8 * i;
            cpasync16(Bs + k * BSTRIDE + b_c4, B + (size_t)k * N + bn + b_c4);
        }
        asm volatile("cp.async.commit_group;\n" ::: "memory");
    }

    for (int it = 0; it < iters; ++it) {
        if (it + 1 < iters) {
            int kk = (it + 1) * GBK;
            float* As = smem + ((it + 1) & 1) * STAGE_FLOATS;
            float* Bs = As + GBM * ASTRIDE;
            #pragma unroll
            for (int i = 0; i < 4; i++) {
                int m = a_m + 32 * i;
                cpasync16(As + m * ASTRIDE + a_c4, A + (size_t)(bm + m) * K + kk + a_c4);
            }
            #pragma unroll
            for (int i = 0; i < 4; i++) {
                int k = b_k + 8 * i;
                cpasync16(Bs + k * BSTRIDE + b_c4, B + (size_t)(kk + k) * N + bn + b_c4);
            }
            asm volatile("cp.async.commit_group;\n" ::: "memory");
            asm volatile("cp.async.wait_group 1;\n" ::: "memory");
        } else {
            asm volatile("cp.async.wait_group 0;\n" ::: "memory");
        }
        __syncthreads();

        const unsigned* As = (const unsigned*)(smem + (it & 1) * STAGE_FLOATS);
        const unsigned* Bs = As + GBM * ASTRIDE;

        #pragma unroll
        for (int ks = 0; ks < 4; ++ks) {
            unsigned af[2][4], bf[8][2];
            int kc = ks * 8 + tg;
            #pragma unroll
            for (int mt = 0; mt < 2; ++mt) {
                int row = m_base + mt * 16 + g;
                af[mt][0] = As[row * ASTRIDE + kc];
                af[mt][1] = As[(row + 8) * ASTRIDE + kc];
                af[mt][2] = As[row * ASTRIDE + kc + 4];
                af[mt][3] = As[(row + 8) * ASTRIDE + kc + 4];
            }
            #pragma unroll
            for (int nt = 0; nt < 8; ++nt) {
                int coln = n_base + nt * 8 + g;
                bf[nt][0] = Bs[kc * BSTRIDE + coln];
                bf[nt][1] = Bs[(kc + 4) * BSTRIDE + coln];
            }
            #pragma unroll
            for (int mt = 0; mt < 2; ++mt)
                #pragma unroll
                for (int nt = 0; nt < 8; ++nt)
                    mma_tf32(c[mt][nt], af[mt], bf[nt]);
        }
        __syncthreads();
    }

    #pragma unroll
    for (int mt = 0; mt < 2; ++mt) {
        #pragma unroll
        for (int nt = 0; nt < 8; ++nt) {
            int row = bm + m_base + mt * 16 + g;
            int col = bn + n_base + nt * 8 + 2 * tg;
            size_t o0 = (size_t)row * N + col;
            size_t o1 = (size_t)(row + 8) * N + col;
            float2 v0 = make_float2(c[mt][nt][0], c[mt][nt][1]);
            float2 v1 = make_float2(c[mt][nt][2], c[mt][nt][3]);
            if (HAS_BIAS) {
                float b0v = bias[col], b1v = bias[col + 1];
                v0.x += b0v; v0.y += b1v;
                v1.x += b0v; v1.y += b1v;
            }
            if (HAS_RES) {
                float2 r0 = *(const float2*)(res + o0);
                float2 r1 = *(const float2*)(res + o1);
                v0.x += r0.x; v0.y += r0.y;
                v1.x += r1.x; v1.y += r1.y;
            }
            *(float2*)(C + o0) = v0;
            *(float2*)(C + o1) = v1;
        }
    }
}

// ================= tensor-core flash attention =================
#define FBQ 128
#define FBKV 64
#define KSTR 68
#define VSTR 72
#define PSTR 68
#define FA_SMEM_FLOATS (2 * FBKV * KSTR + 2 * FBKV * VSTR + FBQ * PSTR)
#define FA_SMEM_BYTES (FA_SMEM_FLOATS * 4)

__global__ __launch_bounds__(256, 1) void flash_tc_kernel(
    const float* __restrict__ Q, const float* __restrict__ Kb,
    const float* __restrict__ Vb, float* __restrict__ O)
{
    extern __shared__ float fsm[];
    float* sK = fsm;
    float* sV = fsm + 2 * FBKV * KSTR;
    float* sP = fsm + 2 * FBKV * KSTR + 2 * FBKV * VSTR;

    int tid = threadIdx.x;
    int lane = tid & 31, g = lane >> 2, tg = lane & 3;
    int wid = tid >> 5;
    int mrow = wid * 16;

    int bh = blockIdx.y;
    int b = bh >> 4, h = bh & 15;
    int q0 = blockIdx.x * FBQ;
    size_t base = ((size_t)b * LSEQ) * DM + (size_t)h * HD;

    // ---- stage Q through sP, build per-warp Q fragments ----
    #pragma unroll
    for (int i = 0; i < 8; i++) {
        int flat = tid + 256 * i;
        int r = flat >> 4, c4 = (flat & 15) * 4;
        *(float4*)&sP[r * PSTR + c4] =
            *(const float4*)(Q + base + (size_t)(q0 + r) * DM + c4);
    }
    __syncthreads();
    const unsigned* sPu = (const unsigned*)sP;
    unsigned aq[8][4];
    #pragma unroll
    for (int ks = 0; ks < 8; ks++) {
        int kc = ks * 8 + tg;
        aq[ks][0] = sPu[(mrow + g) * PSTR + kc];
        aq[ks][1] = sPu[(mrow + g + 8) * PSTR + kc];
        aq[ks][2] = sPu[(mrow + g) * PSTR + kc + 4];
        aq[ks][3] = sPu[(mrow + g + 8) * PSTR + kc + 4];
    }
    __syncthreads();

    int kv_r  = tid >> 4;
    int kv_c4 = (tid & 15) * 4;

    #pragma unroll
    for (int i = 0; i < 4; i++) {
        int rr = kv_r + 16 * i;
        cpasync16(sK + rr * KSTR + kv_c4, Kb + base + (size_t)rr * DM + kv_c4);
        cpasync16(sV + rr * VSTR + kv_c4, Vb + base + (size_t)rr * DM + kv_c4);
    }
    asm volatile("cp.async.commit_group;\n" ::: "memory");

    float m0 = -1e30f, m1 = -1e30f, l0 = 0.f, l1 = 0.f;
    float co[8][4];
    #pragma unroll
    for (int nt = 0; nt < 8; nt++)
        #pragma unroll
        for (int i = 0; i < 4; i++) co[nt][i] = 0.f;

    const int ITERS = LSEQ / FBKV;
    for (int it = 0; it < ITERS; ++it) {
        if (it + 1 < ITERS) {
            int st = (it + 1) & 1;
            size_t kvoff = (size_t)(it + 1) * FBKV * DM;
            #pragma unroll
            for (int i = 0; i < 4; i++) {
                int rr = kv_r + 16 * i;
                cpasync16(sK + st * FBKV * KSTR + rr * KSTR + kv_c4,
                          Kb + base + kvoff + (size_t)rr * DM + kv_c4);
                cpasync16(sV + st * FBKV * VSTR + rr * VSTR + kv_c4,
                          Vb + base + kvoff + (size_t)rr * DM + kv_c4);
            }
            asm volatile("cp.async.commit_group;\n" ::: "memory");
            asm volatile("cp.async.wait_group 1;\n" ::: "memory");
        } else {
            asm volatile("cp.async.wait_group 0;\n" ::: "memory");
        }
        __syncthreads();

        const unsigned* K_ = (const unsigned*)(sK + (it & 1) * FBKV * KSTR);
        const unsigned* V_ = (const unsigned*)(sV + (it & 1) * FBKV * VSTR);

        // ---- S = Q K^T ----
        float cs[8][4];
        #pragma unroll
        for (int nt = 0; nt < 8; nt++)
            #pragma unroll
            for (int i = 0; i < 4; i++) cs[nt][i] = 0.f;

        #pragma unroll
        for (int ks = 0; ks < 8; ks++) {
            int kc = ks * 8 + tg;
            unsigned bf[8][2];
            #pragma unroll
            for (int nt = 0; nt < 8; nt++) {
                bf[nt][0] = K_[(nt * 8 + g) * KSTR + kc];
                bf[nt][1] = K_[(nt * 8 + g) * KSTR + kc + 4];
            }
            #pragma unroll
            for (int nt = 0; nt < 8; nt++)
                mma_tf32(cs[nt], aq[ks], bf[nt]);
        }

        // ---- online softmax ----
        float rm0 = -1e30f, rm1 = -1e30f;
        #pragma unroll
        for (int nt = 0; nt < 8; nt++) {
            #pragma unroll
            for (int i = 0; i < 4; i++) cs[nt][i] *= 0.125f;
            rm0 = fmaxf(rm0, fmaxf(cs[nt][0], cs[nt][1]));
            rm1 = fmaxf(rm1, fmaxf(cs[nt][2], cs[nt][3]));
        }
        rm0 = fmaxf(rm0, __shfl_xor_sync(0xffffffffu, rm0, 1));
        rm0 = fmaxf(rm0, __shfl_xor_sync(0xffffffffu, rm0, 2));
        rm1 = fmaxf(rm1, __shfl_xor_sync(0xffffffffu, rm1, 1));
        rm1 = fmaxf(rm1, __shfl_xor_sync(0xffffffffu, rm1, 2));
        float mn0 = fmaxf(m0, rm0);
        float mn1 = fmaxf(m1, rm1);

        float ps0 = 0.f, ps1 = 0.f;
        #pragma unroll
        for (int nt = 0; nt < 8; nt++) {
            float p00 = __expf(cs[nt][0] - mn0);
            float p01 = __expf(cs[nt][1] - mn0);
            float p10 = __expf(cs[nt][2] - mn1);
            float p11 = __expf(cs[nt][3] - mn1);
            ps0 += p00 + p01;
            ps1 += p10 + p11;
            int col = nt * 8 + 2 * tg;
            sP[(mrow + g) * PSTR + col]     = p00;
            sP[(mrow + g) * PSTR + col + 1] = p01;
            sP[(mrow + g + 8) * PSTR + col]     = p10;
            sP[(mrow + g + 8) * PSTR + col + 1] = p11;
        }
        ps0 += __shfl_xor_sync(0xffffffffu, ps0, 1);
        ps0 += __shfl_xor_sync(0xffffffffu, ps0, 2);
        ps1 += __shfl_xor_sync(0xffffffffu, ps1, 1);
        ps1 += __shfl_xor_sync(0xffffffffu, ps1, 2);

        float f0 = __expf(m0 - mn0);
        float f1 = __expf(m1 - mn1);
        l0 = l0 * f0 + ps0;
        l1 = l1 * f1 + ps1;
        m0 = mn0; m1 = mn1;
        #pragma unroll
        for (int nt = 0; nt < 8; nt++) {
            co[nt][0] *= f0; co[nt][1] *= f0;
            co[nt][2] *= f1; co[nt][3] *= f1;
        }
        __syncwarp();

        // ---- O += P V ----
        #pragma unroll
        for (int ks = 0; ks < 8; ks++) {
            int kc = ks * 8 + tg;
            unsigned ap[4];
            ap[0] = sPu[(mrow + g) * PSTR + kc];
            ap[1] = sPu[(mrow + g + 8) * PSTR + kc];
            ap[2] = sPu[(mrow + g) * PSTR + kc + 4];
            ap[3] = sPu[(mrow + g + 8) * PSTR + kc + 4];
            unsigned bv[8][2];
            #pragma unroll
            for (int nt = 0; nt < 8; nt++) {
                bv[nt][0] = V_[kc * VSTR + nt * 8 + g];
                bv[nt][1] = V_[(kc + 4) * VSTR + nt * 8 + g];
            }
            #pragma unroll
            for (int nt = 0; nt < 8; nt++)
                mma_tf32(co[nt], ap, bv[nt]);
        }
        __syncwarp();
        __syncthreads();
    }

    float i0 = 1.f / l0, i1 = 1.f / l1;
    #pragma unroll
    for (int nt = 0; nt < 8; nt++) {
        int col = nt * 8 + 2 * tg;
        size_t o0 = base + (size_t)(q0 + mrow + g) * DM + col;
        size_t o1 = base + (size_t)(q0 + mrow + g + 8) * DM + col;
        *(float2*)(O + o0) = make_float2(co[nt][0] * i0, co[nt][1] * i0);
        *(float2*)(O + o1) = make_float2(co[nt][2] * i1, co[nt][3] * i1);
    }
}

// ---------------- SwiGLU elementwise (float4) ----------------
__global__ __launch_bounds__(256) void swiglu_kernel(
    float4* __restrict__ g, const float4* __restrict__ u, size_t n4)
{
    size_t i = (size_t)blockIdx.x * 256 + threadIdx.x;
    if (i < n4) {
        float4 x = g[i];
        float4 uu = u[i];
        float4 r;
        r.x = x.x * uu.x / (1.f + __expf(-x.x));
        r.y = x.y * uu.y / (1.f + __expf(-x.y));
        r.z = x.z * uu.z / (1.f + __expf(-x.z));
        r.w = x.w * uu.w / (1.f + __expf(-x.w));
        g[i] = r;
    }
}

// ---------------- launch ----------------
extern "C" void kernel_launch(void* const* d_in, const int* in_sizes, int n_in,
                              void* d_out, int out_size)
{
    const float* x           = (const float*)d_in[0];
    const float* W_q         = (const float*)d_in[1];
    const float* W_k         = (const float*)d_in[2];
    const float* W_v         = (const float*)d_in[3];
    const float* W_o         = (const float*)d_in[4];
    const float* b_o         = (const float*)d_in[5];
    const float* attn_norm_w = (const float*)d_in[6];
    const float* ffn_norm_w  = (const float*)d_in[7];
    const float* W_gate      = (const float*)d_in[8];
    const float* W_hidden    = (const float*)d_in[9];
    const float* W_out       = (const float*)d_in[10];
    const float* b_out       = (const float*)d_in[11];
    float* out = (float*)d_out;

    float *xn, *q, *k, *v, *att, *x1, *xn2, *gate, *hid;
    cudaGetSymbolAddress((void**)&xn,   g_xn);
    cudaGetSymbolAddress((void**)&q,    g_q);
    cudaGetSymbolAddress((void**)&k,    g_k);
    cudaGetSymbolAddress((void**)&v,    g_v);
    cudaGetSymbolAddress((void**)&att,  g_att);
    cudaGetSymbolAddress((void**)&x1,   g_x1);
    cudaGetSymbolAddress((void**)&xn2,  g_xn2);
    cudaGetSymbolAddress((void**)&gate, g_gate);
    cudaGetSymbolAddress((void**)&hid,  g_hid);

    static int smem_set = 0;
    if (!smem_set) {
        cudaFuncSetAttribute(gemm_tf32<0, 0>,
            cudaFuncAttributeMaxDynamicSharedMemorySize, GEMM_SMEM_BYTES);
        cudaFuncSetAttribute(gemm_tf32<1, 1>,
            cudaFuncAttributeMaxDynamicSharedMemorySize, GEMM_SMEM_BYTES);
        cudaFuncSetAttribute(flash_tc_kernel,
            cudaFuncAttributeMaxDynamicSharedMemorySize, FA_SMEM_BYTES);
        smem_set = 1;
    }

    dim3 gProj(DM / GBN, NT / GBM);
    dim3 gFfn (DH / GBN, NT / GBM);

    rmsnorm_kernel<<<NT, 256>>>(x, attn_norm_w, xn);
    gemm_tf32<0, 0><<<gProj, 256, GEMM_SMEM_BYTES>>>(xn, W_q, q, NT, DM, DM, nullptr, nullptr);
    gemm_tf32<0, 0><<<gProj, 256, GEMM_SMEM_BYTES>>>(xn, W_k, k, NT, DM, DM, nullptr, nullptr);
    gemm_tf32<0, 0><<<gProj, 256, GEMM_SMEM_BYTES>>>(xn, W_v, v, NT, DM, DM, nullptr, nullptr);
    flash_tc_kernel<<<dim3(LSEQ / FBQ, NBATCH * NH), 256, FA_SMEM_BYTES>>>(q, k, v, att);
    gemm_tf32<1, 1><<<gProj, 256, GEMM_SMEM_BYTES>>>(att, W_o, x1, NT, DM, DM, b_o, x);
    rmsnorm_kernel<<<NT, 256>>>(x1, ffn_norm_w, xn2);
    gemm_tf32<0, 0><<<gFfn, 256, GEMM_SMEM_BYTES>>>(xn2, W_gate,   gate, NT, DH, DM, nullptr, nullptr);
    gemm_tf32<0, 0><<<gFfn, 256, GEMM_SMEM_BYTES>>>(xn2, W_hidden, hid,  NT, DH, DM, nullptr, nullptr);
    swiglu_kernel<<<(unsigned)(((size_t)NT * DH) / 1024), 256>>>(
        (float4*)gate, (const float4*)hid, (size_t)NT * DH / 4);
    gemm_tf32<1, 1><<<gProj, 256, GEMM_SMEM_BYTES>>>(gate, W_out, out, NT, DM, DH, b_out, x1);
}

// round 6
// speedup vs baseline: 7.2307x; 1.3387x over previous
#include <cuda_runtime.h>
#include <cuda_fp16.h>
#include <math.h>
#include <stdint.h>

#define NT 4096      // total tokens (B*L)
#define DM 1024      // d_model
#define DH 4096      // d_hidden
#define NH 16
#define HD 64
#define LSEQ 2048
#define NBATCH 2
#define QSTR 3072    // packed qkv row stride

// ---------------- scratch (static device globals; no runtime alloc) ----------------
__device__ __half g_xnh [NT * DM];
__device__ float  g_qkv [(size_t)NT * QSTR];
__device__ __half g_atth[NT * DM];
__device__ float  g_x1  [NT * DM];
__device__ __half g_xn2h[NT * DM];
__device__ __half g_gateh[(size_t)NT * DH];
__device__ __half g_hidh [(size_t)NT * DH];
// transposed fp16 weights [N][K]
__device__ __half g_wtqkv[3 * DM * DM];
__device__ __half g_wto  [DM * DM];
__device__ __half g_wtg  [(size_t)DM * DH];
__device__ __half g_wth  [(size_t)DM * DH];
__device__ __half g_wtout[(size_t)DH * DM];

// ---------------- PTX helpers ----------------
__device__ __forceinline__ void cpa16(uint32_t saddr, const void* src) {
    asm volatile("cp.async.cg.shared.global [%0], [%1], 16;\n" :: "r"(saddr), "l"(src));
}
__device__ __forceinline__ void cpasync16(float* dst, const float* src) {
    unsigned saddr = (unsigned)__cvta_generic_to_shared(dst);
    asm volatile("cp.async.cg.shared.global [%0], [%1], 16;\n" :: "r"(saddr), "l"(src));
}
__device__ __forceinline__ uint32_t s2u(const void* p) {
    uint32_t a;
    asm("{ .reg .u64 t; cvta.to.shared.u64 t, %1; cvt.u32.u64 %0, t; }" : "=r"(a) : "l"(p));
    return a;
}
__device__ __forceinline__ void mma_f16(float* c, const unsigned* a, const unsigned* b) {
    asm volatile("mma.sync.aligned.m16n8k16.row.col.f32.f16.f16.f32 "
        "{%0,%1,%2,%3}, {%4,%5,%6,%7}, {%8,%9}, {%0,%1,%2,%3};\n"
        : "+f"(c[0]), "+f"(c[1]), "+f"(c[2]), "+f"(c[3])
        : "r"(a[0]), "r"(a[1]), "r"(a[2]), "r"(a[3]), "r"(b[0]), "r"(b[1]));
}
__device__ __forceinline__ void mma_tf32(float* c, const unsigned* a, const unsigned* b) {
    asm volatile("mma.sync.aligned.m16n8k8.row.col.f32.tf32.tf32.f32 "
        "{%0,%1,%2,%3}, {%4,%5,%6,%7}, {%8,%9}, {%0,%1,%2,%3};\n"
        : "+f"(c[0]), "+f"(c[1]), "+f"(c[2]), "+f"(c[3])
        : "r"(a[0]), "r"(a[1]), "r"(a[2]), "r"(a[3]), "r"(b[0]), "r"(b[1]));
}

// ---------------- weight transpose + fp32->fp16: in[R][C] -> out[C][R] ----------------
__global__ __launch_bounds__(256) void transpose_cvt_kernel(
    const float* __restrict__ in, __half* __restrict__ out, int R, int C)
{
    __shared__ float t[32][33];
    int c0 = blockIdx.x * 32, r0 = blockIdx.y * 32;
    int tx = threadIdx.x & 31, ty = threadIdx.x >> 5;   // 32 x 8
    #pragma unroll
    for (int j = 0; j < 4; j++)
        t[ty + 8 * j][tx] = in[(size_t)(r0 + ty + 8 * j) * C + c0 + tx];
    __syncthreads();
    #pragma unroll
    for (int j = 0; j < 4; j++)
        out[(size_t)(c0 + ty + 8 * j) * R + r0 + tx] = __float2half_rn(t[tx][ty + 8 * j]);
}

// ---------------- RMSNorm: fp32 in -> fp16 out ----------------
__global__ __launch_bounds__(256) void rmsnorm_h_kernel(
    const float* __restrict__ x, const float* __restrict__ w, __half* __restrict__ out)
{
    int row = blockIdx.x;
    const float4* xr = (const float4*)(x + (size_t)row * DM);
    float4 v = xr[threadIdx.x];
    float s = v.x * v.x + v.y * v.y + v.z * v.z + v.w * v.w;
    __shared__ float red[8];
    #pragma unroll
    for (int o = 16; o > 0; o >>= 1) s += __shfl_xor_sync(0xffffffffu, s, o);
    if ((threadIdx.x & 31) == 0) red[threadIdx.x >> 5] = s;
    __syncthreads();
    if (threadIdx.x < 8) {
        float t = red[threadIdx.x];
        #pragma unroll
        for (int o = 4; o > 0; o >>= 1) t += __shfl_xor_sync(0xffu, t, o);
        if (threadIdx.x == 0) red[0] = t;
    }
    __syncthreads();
    float inv = rsqrtf(red[0] * (1.0f / DM) + 1e-6f);
    float4 wv = ((const float4*)w)[threadIdx.x];
    __half2* orow = (__half2*)(out + (size_t)row * DM);
    orow[2 * threadIdx.x]     = __floats2half2_rn(wv.x * v.x * inv, wv.y * v.y * inv);
    orow[2 * threadIdx.x + 1] = __floats2half2_rn(wv.z * v.z * inv, wv.w * v.w * inv);
}

// ================= fp16 tensor-core GEMM (m16n8k16) =================
// C[M,N] = A[M,K] @ Bt[N,K]^T  (+bias)(+res). A,Bt fp16 K-major. M,N %128, K %32.
// 256 threads, 8 warps (4x2), warp tile 32x64. smem rows stride 40 halves.
#define HBM 128
#define HBN 128
#define HBK 32
#define HASTR 40                              // halves per smem row (32 + 8 pad)
#define HTILE_BYTES (HBM * HASTR * 2)         // 10240 per operand
#define HSTAGE (2 * HTILE_BYTES)              // 20480
#define HSMEM  (2 * HSTAGE)                   // 40960

__device__ __forceinline__ void hload(uint32_t s0, const __half* A, const __half* Bt,
    int bm, int bn, int K, int kk, int tid)
{
    const __half* Ag = A  + (size_t)bm * K + kk;
    const __half* Bg = Bt + (size_t)bn * K + kk;
    #pragma unroll
    for (int j = 0; j < 2; j++) {
        int idx = tid + 256 * j;               // 0..511
        int r = idx >> 2, c = idx & 3;         // c in 16B (8-half) units
        cpa16(s0 + (uint32_t)(r * HASTR + c * 8) * 2, Ag + (size_t)r * K + c * 8);
        cpa16(s0 + (uint32_t)HTILE_BYTES + (uint32_t)(r * HASTR + c * 8) * 2,
              Bg + (size_t)r * K + c * 8);
    }
    asm volatile("cp.async.commit_group;\n" ::: "memory");
}

template <int OUT_HALF, int HAS_BIAS, int HAS_RES>
__global__ __launch_bounds__(256, 2) void gemm_f16(
    const __half* __restrict__ A, const __half* __restrict__ Bt, void* __restrict__ Cv,
    int M, int N, int K, const float* __restrict__ bias, const float* __restrict__ res)
{
    extern __shared__ char hsm[];
    uint32_t sbase = s2u(hsm);
    int tid = threadIdx.x;
    int lane = tid & 31, g = lane >> 2, tg = lane & 3;
    int wid = tid >> 5;
    int m_base = (wid >> 1) * 32;
    int n_base = (wid & 1) * 64;
    int bm = blockIdx.y * HBM, bn = blockIdx.x * HBN;

    float c[2][8][4];
    #pragma unroll
    for (int mt = 0; mt < 2; mt++)
        #pragma unroll
        for (int nt = 0; nt < 8; nt++)
            #pragma unroll
            for (int i = 0; i < 4; i++) c[mt][nt][i] = 0.f;

    const int iters = K / HBK;
    hload(sbase, A, Bt, bm, bn, K, 0, tid);

    for (int it = 0; it < iters; ++it) {
        if (it + 1 < iters) {
            hload(sbase + ((it + 1) & 1) * HSTAGE, A, Bt, bm, bn, K, (it + 1) * HBK, tid);
            asm volatile("cp.async.wait_group 1;\n" ::: "memory");
        } else {
            asm volatile("cp.async.wait_group 0;\n" ::: "memory");
        }
        __syncthreads();

        const unsigned* As = (const unsigned*)(hsm + (size_t)(it & 1) * HSTAGE);
        const unsigned* Bs = As + (HBM * HASTR) / 2;   // 32-bit words

        #pragma unroll
        for (int ks = 0; ks < 2; ++ks) {
            int kw = ks * 8 + tg;                      // 32-bit word idx in row (20 words)
            unsigned af[2][4], bf[8][2];
            #pragma unroll
            for (int mt = 0; mt < 2; ++mt) {
                int row = m_base + mt * 16 + g;
                af[mt][0] = As[row * 20 + kw];
                af[mt][1] = As[(row + 8) * 20 + kw];
                af[mt][2] = As[row * 20 + kw + 4];
                af[mt][3] = As[(row + 8) * 20 + kw + 4];
            }
            #pragma unroll
            for (int nt = 0; nt < 8; ++nt) {
                int n = n_base + nt * 8 + g;
                bf[nt][0] = Bs[n * 20 + kw];
                bf[nt][1] = Bs[n * 20 + kw + 4];
            }
            #pragma unroll
            for (int mt = 0; mt < 2; ++mt)
                #pragma unroll
                for (int nt = 0; nt < 8; ++nt)
                    mma_f16(c[mt][nt], af[mt], bf[nt]);
        }
        __syncthreads();
    }

    #pragma unroll
    for (int mt = 0; mt < 2; ++mt) {
        #pragma unroll
        for (int nt = 0; nt < 8; ++nt) {
            int row = bm + m_base + mt * 16 + g;
            int col = bn + n_base + nt * 8 + 2 * tg;
            size_t o0 = (size_t)row * N + col;
            size_t o1 = (size_t)(row + 8) * N + col;
            float v00 = c[mt][nt][0], v01 = c[mt][nt][1];
            float v10 = c[mt][nt][2], v11 = c[mt][nt][3];
            if (HAS_BIAS) {
                float b0v = bias[col], b1v = bias[col + 1];
                v00 += b0v; v01 += b1v; v10 += b0v; v11 += b1v;
            }
            if (HAS_RES) {
                float2 r0 = *(const float2*)(res + o0);
                float2 r1 = *(const float2*)(res + o1);
                v00 += r0.x; v01 += r0.y; v10 += r1.x; v11 += r1.y;
            }
            if (OUT_HALF) {
                __half* Ch = (__half*)Cv;
                *(__half2*)(Ch + o0) = __floats2half2_rn(v00, v01);
                *(__half2*)(Ch + o1) = __floats2half2_rn(v10, v11);
            } else {
                float* Cf = (float*)Cv;
                *(float2*)(Cf + o0) = make_float2(v00, v01);
                *(float2*)(Cf + o1) = make_float2(v10, v11);
            }
        }
    }
}

// ================= tensor-core flash attention (tf32 internals) =================
// Reads packed fp32 QKV [token][3072]; writes fp16 O [token][1024].
#define FBQ 128
#define FBKV 64
#define KSTR 68
#define VSTR 72
#define PSTR 68
#define FA_SMEM_FLOATS (2 * FBKV * KSTR + 2 * FBKV * VSTR + FBQ * PSTR)
#define FA_SMEM_BYTES (FA_SMEM_FLOATS * 4)

__global__ __launch_bounds__(256, 1) void flash_tc_kernel(
    const float* __restrict__ QKV, __half* __restrict__ O)
{
    extern __shared__ float fsm[];
    float* sK = fsm;
    float* sV = fsm + 2 * FBKV * KSTR;
    float* sP = fsm + 2 * FBKV * KSTR + 2 * FBKV * VSTR;

    int tid = threadIdx.x;
    int lane = tid & 31, g = lane >> 2, tg = lane & 3;
    int wid = tid >> 5;
    int mrow = wid * 16;

    int bh = blockIdx.y;
    int b = bh >> 4, h = bh & 15;
    int q0 = blockIdx.x * FBQ;
    size_t base = ((size_t)b * LSEQ) * QSTR + (size_t)h * HD;
    const float* Qp = QKV;
    const float* Kp = QKV + DM;
    const float* Vp = QKV + 2 * DM;

    #pragma unroll
    for (int i = 0; i < 8; i++) {
        int flat = tid + 256 * i;
        int r = flat >> 4, c4 = (flat & 15) * 4;
        *(float4*)&sP[r * PSTR + c4] =
            *(const float4*)(Qp + base + (size_t)(q0 + r) * QSTR + c4);
    }
    __syncthreads();
    const unsigned* sPu = (const unsigned*)sP;
    unsigned aq[8][4];
    #pragma unroll
    for (int ks = 0; ks < 8; ks++) {
        int kc = ks * 8 + tg;
        aq[ks][0] = sPu[(mrow + g) * PSTR + kc];
        aq[ks][1] = sPu[(mrow + g + 8) * PSTR + kc];
        aq[ks][2] = sPu[(mrow + g) * PSTR + kc + 4];
        aq[ks][3] = sPu[(mrow + g + 8) * PSTR + kc + 4];
    }
    __syncthreads();

    int kv_r  = tid >> 4;
    int kv_c4 = (tid & 15) * 4;

    #pragma unroll
    for (int i = 0; i < 4; i++) {
        int rr = kv_r + 16 * i;
        cpasync16(sK + rr * KSTR + kv_c4, Kp + base + (size_t)rr * QSTR + kv_c4);
        cpasync16(sV + rr * VSTR + kv_c4, Vp + base + (size_t)rr * QSTR + kv_c4);
    }
    asm volatile("cp.async.commit_group;\n" ::: "memory");

    float m0 = -1e30f, m1 = -1e30f, l0 = 0.f, l1 = 0.f;
    float co[8][4];
    #pragma unroll
    for (int nt = 0; nt < 8; nt++)
        #pragma unroll
        for (int i = 0; i < 4; i++) co[nt][i] = 0.f;

    const int ITERS = LSEQ / FBKV;
    for (int it = 0; it < ITERS; ++it) {
        if (it + 1 < ITERS) {
            int st = (it + 1) & 1;
            size_t kvoff = (size_t)(it + 1) * FBKV * QSTR;
            #pragma unroll
            for (int i = 0; i < 4; i++) {
                int rr = kv_r + 16 * i;
                cpasync16(sK + st * FBKV * KSTR + rr * KSTR + kv_c4,
                          Kp + base + kvoff + (size_t)rr * QSTR + kv_c4);
                cpasync16(sV + st * FBKV * VSTR + rr * VSTR + kv_c4,
                          Vp + base + kvoff + (size_t)rr * QSTR + kv_c4);
            }
            asm volatile("cp.async.commit_group;\n" ::: "memory");
            asm volatile("cp.async.wait_group 1;\n" ::: "memory");
        } else {
            asm volatile("cp.async.wait_group 0;\n" ::: "memory");
        }
        __syncthreads();

        const unsigned* K_ = (const unsigned*)(sK + (it & 1) * FBKV * KSTR);
        const unsigned* V_ = (const unsigned*)(sV + (it & 1) * FBKV * VSTR);

        float cs[8][4];
        #pragma unroll
        for (int nt = 0; nt < 8; nt++)
            #pragma unroll
            for (int i = 0; i < 4; i++) cs[nt][i] = 0.f;

        #pragma unroll
        for (int ks = 0; ks < 8; ks++) {
            int kc = ks * 8 + tg;
            unsigned bf[8][2];
            #pragma unroll
            for (int nt = 0; nt < 8; nt++) {
                bf[nt][0] = K_[(nt * 8 + g) * KSTR + kc];
                bf[nt][1] = K_[(nt * 8 + g) * KSTR + kc + 4];
            }
            #pragma unroll
            for (int nt = 0; nt < 8; nt++)
                mma_tf32(cs[nt], aq[ks], bf[nt]);
        }

        float rm0 = -1e30f, rm1 = -1e30f;
        #pragma unroll
        for (int nt = 0; nt < 8; nt++) {
            #pragma unroll
            for (int i = 0; i < 4; i++) cs[nt][i] *= 0.125f;
            rm0 = fmaxf(rm0, fmaxf(cs[nt][0], cs[nt][1]));
            rm1 = fmaxf(rm1, fmaxf(cs[nt][2], cs[nt][3]));
        }
        rm0 = fmaxf(rm0, __shfl_xor_sync(0xffffffffu, rm0, 1));
        rm0 = fmaxf(rm0, __shfl_xor_sync(0xffffffffu, rm0, 2));
        rm1 = fmaxf(rm1, __shfl_xor_sync(0xffffffffu, rm1, 1));
        rm1 = fmaxf(rm1, __shfl_xor_sync(0xffffffffu, rm1, 2));
        float mn0 = fmaxf(m0, rm0);
        float mn1 = fmaxf(m1, rm1);

        float ps0 = 0.f, ps1 = 0.f;
        #pragma unroll
        for (int nt = 0; nt < 8; nt++) {
            float p00 = __expf(cs[nt][0] - mn0);
            float p01 = __expf(cs[nt][1] - mn0);
            float p10 = __expf(cs[nt][2] - mn1);
            float p11 = __expf(cs[nt][3] - mn1);
            ps0 += p00 + p01;
            ps1 += p10 + p11;
            int col = nt * 8 + 2 * tg;
            sP[(mrow + g) * PSTR + col]     = p00;
            sP[(mrow + g) * PSTR + col + 1] = p01;
            sP[(mrow + g + 8) * PSTR + col]     = p10;
            sP[(mrow + g + 8) * PSTR + col + 1] = p11;
        }
        ps0 += __shfl_xor_sync(0xffffffffu, ps0, 1);
        ps0 += __shfl_xor_sync(0xffffffffu, ps0, 2);
        ps1 += __shfl_xor_sync(0xffffffffu, ps1, 1);
        ps1 += __shfl_xor_sync(0xffffffffu, ps1, 2);

        float f0 = __expf(m0 - mn0);
        float f1 = __expf(m1 - mn1);
        l0 = l0 * f0 + ps0;
        l1 = l1 * f1 + ps1;
        m0 = mn0; m1 = mn1;
        #pragma unroll
        for (int nt = 0; nt < 8; nt++) {
            co[nt][0] *= f0; co[nt][1] *= f0;
            co[nt][2] *= f1; co[nt][3] *= f1;
        }
        __syncwarp();

        #pragma unroll
        for (int ks = 0; ks < 8; ks++) {
            int kc = ks * 8 + tg;
            unsigned ap[4];
            ap[0] = sPu[(mrow + g) * PSTR + kc];
            ap[1] = sPu[(mrow + g + 8) * PSTR + kc];
            ap[2] = sPu[(mrow + g) * PSTR + kc + 4];
            ap[3] = sPu[(mrow + g + 8) * PSTR + kc + 4];
            unsigned bv[8][2];
            #pragma unroll
            for (int nt = 0; nt < 8; nt++) {
                bv[nt][0] = V_[kc * VSTR + nt * 8 + g];
                bv[nt][1] = V_[(kc + 4) * VSTR + nt * 8 + g];
            }
            #pragma unroll
            for (int nt = 0; nt < 8; nt++)
                mma_tf32(co[nt], ap, bv[nt]);
        }
        __syncwarp();
        __syncthreads();
    }

    float i0 = 1.f / l0, i1 = 1.f / l1;
    size_t obase = ((size_t)b * LSEQ) * DM + (size_t)h * HD;
    #pragma unroll
    for (int nt = 0; nt < 8; nt++) {
        int col = nt * 8 + 2 * tg;
        size_t o0 = obase + (size_t)(q0 + mrow + g) * DM + col;
        size_t o1 = obase + (size_t)(q0 + mrow + g + 8) * DM + col;
        *(__half2*)(O + o0) = __floats2half2_rn(co[nt][0] * i0, co[nt][1] * i0);
        *(__half2*)(O + o1) = __floats2half2_rn(co[nt][2] * i1, co[nt][3] * i1);
    }
}

// ---------------- SwiGLU elementwise, fp16 in/out ----------------
__global__ __launch_bounds__(256) void swiglu_h_kernel(
    __half2* __restrict__ g, const __half2* __restrict__ u, int n2)
{
    int i = blockIdx.x * 256 + threadIdx.x;
    if (i < n2) {
        float2 xg = __half22float2(g[i]);
        float2 xu = __half22float2(u[i]);
        float rx = xg.x * xu.x / (1.f + __expf(-xg.x));
        float ry = xg.y * xu.y / (1.f + __expf(-xg.y));
        g[i] = __floats2half2_rn(rx, ry);
    }
}

// ---------------- launch ----------------
extern "C" void kernel_launch(void* const* d_in, const int* in_sizes, int n_in,
                              void* d_out, int out_size)
{
    const float* x           = (const float*)d_in[0];
    const float* W_q         = (const float*)d_in[1];
    const float* W_k         = (const float*)d_in[2];
    const float* W_v         = (const float*)d_in[3];
    const float* W_o         = (const float*)d_in[4];
    const float* b_o         = (const float*)d_in[5];
    const float* attn_norm_w = (const float*)d_in[6];
    const float* ffn_norm_w  = (const float*)d_in[7];
    const float* W_gate      = (const float*)d_in[8];
    const float* W_hidden    = (const float*)d_in[9];
    const float* W_out       = (const float*)d_in[10];
    const float* b_out       = (const float*)d_in[11];
    float* out = (float*)d_out;

    __half *xnh, *atth, *xn2h, *gateh, *hidh;
    __half *wtqkv, *wto, *wtg, *wth, *wtout;
    float *qkv, *x1;
    cudaGetSymbolAddress((void**)&xnh,    g_xnh);
    cudaGetSymbolAddress((void**)&qkv,    g_qkv);
    cudaGetSymbolAddress((void**)&atth,   g_atth);
    cudaGetSymbolAddress((void**)&x1,     g_x1);
    cudaGetSymbolAddress((void**)&xn2h,   g_xn2h);
    cudaGetSymbolAddress((void**)&gateh,  g_gateh);
    cudaGetSymbolAddress((void**)&hidh,   g_hidh);
    cudaGetSymbolAddress((void**)&wtqkv,  g_wtqkv);
    cudaGetSymbolAddress((void**)&wto,    g_wto);
    cudaGetSymbolAddress((void**)&wtg,    g_wtg);
    cudaGetSymbolAddress((void**)&wth,    g_wth);
    cudaGetSymbolAddress((void**)&wtout,  g_wtout);

    static int smem_set = 0;
    if (!smem_set) {
        cudaFuncSetAttribute(flash_tc_kernel,
            cudaFuncAttributeMaxDynamicSharedMemorySize, FA_SMEM_BYTES);
        smem_set = 1;
    }

    // weight transposes + fp16 conversion: [K][N] -> [N][K]
    transpose_cvt_kernel<<<dim3(DM / 32, DM / 32), 256>>>(W_q, wtqkv,              DM, DM);
    transpose_cvt_kernel<<<dim3(DM / 32, DM / 32), 256>>>(W_k, wtqkv + DM * DM,    DM, DM);
    transpose_cvt_kernel<<<dim3(DM / 32, DM / 32), 256>>>(W_v, wtqkv + 2 * DM * DM, DM, DM);
    transpose_cvt_kernel<<<dim3(DM / 32, DM / 32), 256>>>(W_o, wto, DM, DM);
    transpose_cvt_kernel<<<dim3(DH / 32, DM / 32), 256>>>(W_gate,   wtg, DM, DH);
    transpose_cvt_kernel<<<dim3(DH / 32, DM / 32), 256>>>(W_hidden, wth, DM, DH);
    transpose_cvt_kernel<<<dim3(DM / 32, DH / 32), 256>>>(W_out,  wtout, DH, DM);

    // 1. attn pre-norm (fp16 out)
    rmsnorm_h_kernel<<<NT, 256>>>(x, attn_norm_w, xnh);
    // 2. fused QKV projection (fp32 out, packed [NT][3072])
    gemm_f16<0, 0, 0><<<dim3(QSTR / HBN, NT / HBM), 256, HSMEM>>>(
        xnh, wtqkv, qkv, NT, QSTR, DM, nullptr, nullptr);
    // 3. attention (fp16 out)
    flash_tc_kernel<<<dim3(LSEQ / FBQ, NBATCH * NH), 256, FA_SMEM_BYTES>>>(qkv, atth);
    // 4. output projection + bias + residual (fp32 out)
    gemm_f16<0, 1, 1><<<dim3(DM / HBN, NT / HBM), 256, HSMEM>>>(
        atth, wto, x1, NT, DM, DM, b_o, x);
    // 5. ffn pre-norm (fp16 out)
    rmsnorm_h_kernel<<<NT, 256>>>(x1, ffn_norm_w, xn2h);
    // 6. gate & hidden (fp16 out)
    gemm_f16<1, 0, 0><<<dim3(DH / HBN, NT / HBM), 256, HSMEM>>>(
        xn2h, wtg, gateh, NT, DH, DM, nullptr, nullptr);
    gemm_f16<1, 0, 0><<<dim3(DH / HBN, NT / HBM), 256, HSMEM>>>(
        xn2h, wth, hidh, NT, DH, DM, nullptr, nullptr);
    // 7. silu(gate) * hidden (fp16)
    swiglu_h_kernel<<<(NT * DH / 2 + 255) / 256, 256>>>(
        (__half2*)gateh, (const __half2*)hidh, NT * DH / 2);
    // 8. out projection + bias + residual (fp32 out)
    gemm_f16<0, 1, 1><<<dim3(DM / HBN, NT / HBM), 256, HSMEM>>>(
        gateh, wtout, out, NT, DM, DH, b_out, x1);
}

// round 7
// speedup vs baseline: 8.6026x; 1.1897x over previous
#include <cuda_runtime.h>
#include <cuda_fp16.h>
#include <math.h>
#include <stdint.h>

#define NT 4096      // total tokens (B*L)
#define DM 1024      // d_model
#define DH 4096      // d_hidden
#define NH 16
#define HD 64
#define LSEQ 2048
#define NBATCH 2
#define QSTR 3072    // packed qkv row stride

// ---------------- scratch (static device globals; no runtime alloc) ----------------
__device__ __half g_xnh [NT * DM];
__device__ __half g_qkvh[(size_t)NT * QSTR];
__device__ __half g_atth[NT * DM];
__device__ float  g_x1  [NT * DM];
__device__ __half g_xn2h[NT * DM];
__device__ __half g_gateh[(size_t)NT * DH];
__device__ __half g_hidh [(size_t)NT * DH];
// transposed fp16 weights [N][K]
__device__ __half g_wtqkv[3 * DM * DM];
__device__ __half g_wto  [DM * DM];
__device__ __half g_wtg  [(size_t)DM * DH];
__device__ __half g_wth  [(size_t)DM * DH];
__device__ __half g_wtout[(size_t)DH * DM];

// ---------------- PTX helpers ----------------
__device__ __forceinline__ void cpa16(uint32_t saddr, const void* src) {
    asm volatile("cp.async.cg.shared.global [%0], [%1], 16;\n" :: "r"(saddr), "l"(src));
}
__device__ __forceinline__ uint32_t s2u(const void* p) {
    uint32_t a;
    asm("{ .reg .u64 t; cvta.to.shared.u64 t, %1; cvt.u32.u64 %0, t; }" : "=r"(a) : "l"(p));
    return a;
}
__device__ __forceinline__ void mma_f16(float* c, const unsigned* a, const unsigned* b) {
    asm volatile("mma.sync.aligned.m16n8k16.row.col.f32.f16.f16.f32 "
        "{%0,%1,%2,%3}, {%4,%5,%6,%7}, {%8,%9}, {%0,%1,%2,%3};\n"
        : "+f"(c[0]), "+f"(c[1]), "+f"(c[2]), "+f"(c[3])
        : "r"(a[0]), "r"(a[1]), "r"(a[2]), "r"(a[3]), "r"(b[0]), "r"(b[1]));
}
__device__ __forceinline__ void ldmx4t(unsigned* r, uint32_t addr) {
    asm volatile("ldmatrix.sync.aligned.m8n8.x4.trans.shared.b16 {%0,%1,%2,%3}, [%4];"
        : "=r"(r[0]), "=r"(r[1]), "=r"(r[2]), "=r"(r[3]) : "r"(addr));
}

// ---------------- weight transpose + fp32->fp16: in[R][C] -> out[C][R] ----------------
__global__ __launch_bounds__(256) void transpose_cvt_kernel(
    const float* __restrict__ in, __half* __restrict__ out, int R, int C)
{
    __shared__ float t[32][33];
    int c0 = blockIdx.x * 32, r0 = blockIdx.y * 32;
    int tx = threadIdx.x & 31, ty = threadIdx.x >> 5;   // 32 x 8
    #pragma unroll
    for (int j = 0; j < 4; j++)
        t[ty + 8 * j][tx] = in[(size_t)(r0 + ty + 8 * j) * C + c0 + tx];
    __syncthreads();
    #pragma unroll
    for (int j = 0; j < 4; j++)
        out[(size_t)(c0 + ty + 8 * j) * R + r0 + tx] = __float2half_rn(t[tx][ty + 8 * j]);
}

// ---------------- RMSNorm: fp32 in -> fp16 out ----------------
__global__ __launch_bounds__(256) void rmsnorm_h_kernel(
    const float* __restrict__ x, const float* __restrict__ w, __half* __restrict__ out)
{
    int row = blockIdx.x;
    const float4* xr = (const float4*)(x + (size_t)row * DM);
    float4 v = xr[threadIdx.x];
    float s = v.x * v.x + v.y * v.y + v.z * v.z + v.w * v.w;
    __shared__ float red[8];
    #pragma unroll
    for (int o = 16; o > 0; o >>= 1) s += __shfl_xor_sync(0xffffffffu, s, o);
    if ((threadIdx.x & 31) == 0) red[threadIdx.x >> 5] = s;
    __syncthreads();
    if (threadIdx.x < 8) {
        float t = red[threadIdx.x];
        #pragma unroll
        for (int o = 4; o > 0; o >>= 1) t += __shfl_xor_sync(0xffu, t, o);
        if (threadIdx.x == 0) red[0] = t;
    }
    __syncthreads();
    float inv = rsqrtf(red[0] * (1.0f / DM) + 1e-6f);
    float4 wv = ((const float4*)w)[threadIdx.x];
    __half2* orow = (__half2*)(out + (size_t)row * DM);
    orow[2 * threadIdx.x]     = __floats2half2_rn(wv.x * v.x * inv, wv.y * v.y * inv);
    orow[2 * threadIdx.x + 1] = __floats2half2_rn(wv.z * v.z * inv, wv.w * v.w * inv);
}

// ================= fp16 tensor-core GEMM (m16n8k16) =================
#define HBM 128
#define HBN 128
#define HBK 32
#define HASTR 40                              // halves per smem row
#define HTILE_BYTES (HBM * HASTR * 2)
#define HSTAGE (2 * HTILE_BYTES)
#define HSMEM  (2 * HSTAGE)

__device__ __forceinline__ void hload(uint32_t s0, const __half* A, const __half* Bt,
    int bm, int bn, int K, int kk, int tid)
{
    const __half* Ag = A  + (size_t)bm * K + kk;
    const __half* Bg = Bt + (size_t)bn * K + kk;
    #pragma unroll
    for (int j = 0; j < 2; j++) {
        int idx = tid + 256 * j;
        int r = idx >> 2, c = idx & 3;
        cpa16(s0 + (uint32_t)(r * HASTR + c * 8) * 2, Ag + (size_t)r * K + c * 8);
        cpa16(s0 + (uint32_t)HTILE_BYTES + (uint32_t)(r * HASTR + c * 8) * 2,
              Bg + (size_t)r * K + c * 8);
    }
    asm volatile("cp.async.commit_group;\n" ::: "memory");
}

template <int OUT_HALF, int HAS_BIAS, int HAS_RES, int SWI>
__global__ __launch_bounds__(256, 2) void gemm_f16(
    const __half* __restrict__ A, const __half* __restrict__ Bt, void* __restrict__ Cv,
    int M, int N, int K, const float* __restrict__ bias, const float* __restrict__ res,
    const __half* __restrict__ aux)
{
    extern __shared__ char hsm[];
    uint32_t sbase = s2u(hsm);
    int tid = threadIdx.x;
    int lane = tid & 31, g = lane >> 2, tg = lane & 3;
    int wid = tid >> 5;
    int m_base = (wid >> 1) * 32;
    int n_base = (wid & 1) * 64;
    int bm = blockIdx.y * HBM, bn = blockIdx.x * HBN;

    float c[2][8][4];
    #pragma unroll
    for (int mt = 0; mt < 2; mt++)
        #pragma unroll
        for (int nt = 0; nt < 8; nt++)
            #pragma unroll
            for (int i = 0; i < 4; i++) c[mt][nt][i] = 0.f;

    const int iters = K / HBK;
    hload(sbase, A, Bt, bm, bn, K, 0, tid);

    for (int it = 0; it < iters; ++it) {
        if (it + 1 < iters) {
            hload(sbase + ((it + 1) & 1) * HSTAGE, A, Bt, bm, bn, K, (it + 1) * HBK, tid);
            asm volatile("cp.async.wait_group 1;\n" ::: "memory");
        } else {
            asm volatile("cp.async.wait_group 0;\n" ::: "memory");
        }
        __syncthreads();

        const unsigned* As = (const unsigned*)(hsm + (size_t)(it & 1) * HSTAGE);
        const unsigned* Bs = As + (HBM * HASTR) / 2;

        #pragma unroll
        for (int ks = 0; ks < 2; ++ks) {
            int kw = ks * 8 + tg;
            unsigned af[2][4], bf[8][2];
            #pragma unroll
            for (int mt = 0; mt < 2; ++mt) {
                int row = m_base + mt * 16 + g;
                af[mt][0] = As[row * 20 + kw];
                af[mt][1] = As[(row + 8) * 20 + kw];
                af[mt][2] = As[row * 20 + kw + 4];
                af[mt][3] = As[(row + 8) * 20 + kw + 4];
            }
            #pragma unroll
            for (int nt = 0; nt < 8; ++nt) {
                int n = n_base + nt * 8 + g;
                bf[nt][0] = Bs[n * 20 + kw];
                bf[nt][1] = Bs[n * 20 + kw + 4];
            }
            #pragma unroll
            for (int mt = 0; mt < 2; ++mt)
                #pragma unroll
                for (int nt = 0; nt < 8; ++nt)
                    mma_f16(c[mt][nt], af[mt], bf[nt]);
        }
        __syncthreads();
    }

    #pragma unroll
    for (int mt = 0; mt < 2; ++mt) {
        #pragma unroll
        for (int nt = 0; nt < 8; ++nt) {
            int row = bm + m_base + mt * 16 + g;
            int col = bn + n_base + nt * 8 + 2 * tg;
            size_t o0 = (size_t)row * N + col;
            size_t o1 = (size_t)(row + 8) * N + col;
            float v00 = c[mt][nt][0], v01 = c[mt][nt][1];
            float v10 = c[mt][nt][2], v11 = c[mt][nt][3];
            if (HAS_BIAS) {
                float b0v = bias[col], b1v = bias[col + 1];
                v00 += b0v; v01 += b1v; v10 += b0v; v11 += b1v;
            }
            if (HAS_RES) {
                float2 r0 = *(const float2*)(res + o0);
                float2 r1 = *(const float2*)(res + o1);
                v00 += r0.x; v01 += r0.y; v10 += r1.x; v11 += r1.y;
            }
            if (SWI) {   // this GEMM computed hid; aux = gate. out = silu(gate)*hid
                float2 g0 = __half22float2(*(const __half2*)(aux + o0));
                float2 g1 = __half22float2(*(const __half2*)(aux + o1));
                v00 *= g0.x / (1.f + __expf(-g0.x));
                v01 *= g0.y / (1.f + __expf(-g0.y));
                v10 *= g1.x / (1.f + __expf(-g1.x));
                v11 *= g1.y / (1.f + __expf(-g1.y));
            }
            if (OUT_HALF) {
                __half* Ch = (__half*)Cv;
                *(__half2*)(Ch + o0) = __floats2half2_rn(v00, v01);
                *(__half2*)(Ch + o1) = __floats2half2_rn(v10, v11);
            } else {
                float* Cf = (float*)Cv;
                *(float2*)(Cf + o0) = make_float2(v00, v01);
                *(float2*)(Cf + o1) = make_float2(v10, v11);
            }
        }
    }
}

// ================= fp16 tensor-core flash attention =================
// BQ=128, BKV=64, HD=64. 8 warps, warp owns 16 q rows.
// S and PV via mma.m16n8k16.f16; V B-fragments via ldmatrix.x4.trans.
#define FBQ 128
#define FBKV 64
#define FSTRH 72                  // halves per smem row (64 + 8 pad); 36 words
#define FKV_BYTES (FBKV * FSTRH * 2)        // 9216 per stage
#define FP_BYTES  (FBQ * FSTRH * 2)         // 18432
#define FA_SMEM (4 * FKV_BYTES + FP_BYTES)  // 55296

__global__ __launch_bounds__(256, 2) void flash_h_kernel(
    const __half* __restrict__ QKV, __half* __restrict__ O)
{
    extern __shared__ __half hsm2[];
    __half* sK = hsm2;                       // 2 stages
    __half* sV = sK + 2 * FBKV * FSTRH;      // 2 stages
    __half* sP = sV + 2 * FBKV * FSTRH;      // also Q staging

    int tid = threadIdx.x;
    int lane = tid & 31, g = lane >> 2, tg = lane & 3;
    int wid = tid >> 5;
    int mrow = wid * 16;

    int bh = blockIdx.y;
    int b = bh >> 4, h = bh & 15;
    int q0 = blockIdx.x * FBQ;
    size_t base = ((size_t)b * LSEQ) * QSTR + (size_t)h * HD;
    const __half* Qp = QKV;
    const __half* Kp = QKV + DM;
    const __half* Vp = QKV + 2 * DM;

    // ---- stage Q into sP (16B chunks), build Q fragments ----
    #pragma unroll
    for (int i = 0; i < 4; i++) {
        int flat = tid + 256 * i;            // 0..1023
        int r = flat >> 3, c = flat & 7;
        *(uint4*)&sP[r * FSTRH + c * 8] =
            *(const uint4*)(Qp + base + (size_t)(q0 + r) * QSTR + c * 8);
    }
    __syncthreads();
    const unsigned* sPw = (const unsigned*)sP;
    unsigned aq[4][4];
    #pragma unroll
    for (int ks = 0; ks < 4; ks++) {
        int kw = ks * 8 + tg;
        aq[ks][0] = sPw[(mrow + g) * 36 + kw];
        aq[ks][1] = sPw[(mrow + g + 8) * 36 + kw];
        aq[ks][2] = sPw[(mrow + g) * 36 + kw + 4];
        aq[ks][3] = sPw[(mrow + g + 8) * 36 + kw + 4];
    }
    __syncthreads();   // sP now free for P tiles

    uint32_t sKu = s2u(sK), sVu = s2u(sV);
    // per-lane ldmatrix base offset within a V stage
    int vrow = lane & 15;
    int vcol = (lane >> 4) << 3;

    // prefetch stage 0: K/V 64 rows x 8 chunks each
    #pragma unroll
    for (int j = 0; j < 2; j++) {
        int cid = tid + 256 * j;             // 0..511
        int r = cid >> 3, c = cid & 7;
        cpa16(sKu + (uint32_t)(r * FSTRH + c * 8) * 2,
              Kp + base + (size_t)r * QSTR + c * 8);
        cpa16(sVu + (uint32_t)(r * FSTRH + c * 8) * 2,
              Vp + base + (size_t)r * QSTR + c * 8);
    }
    asm volatile("cp.async.commit_group;\n" ::: "memory");

    float m0 = -1e30f, m1 = -1e30f, l0 = 0.f, l1 = 0.f;
    float co[8][4];
    #pragma unroll
    for (int nt = 0; nt < 8; nt++)
        #pragma unroll
        for (int i = 0; i < 4; i++) co[nt][i] = 0.f;

    const int ITERS = LSEQ / FBKV;
    for (int it = 0; it < ITERS; ++it) {
        if (it + 1 < ITERS) {
            uint32_t stoff = (uint32_t)((it + 1) & 1) * FKV_BYTES;
            size_t kvoff = (size_t)(it + 1) * FBKV * QSTR;
            #pragma unroll
            for (int j = 0; j < 2; j++) {
                int cid = tid + 256 * j;
                int r = cid >> 3, c = cid & 7;
                cpa16(sKu + stoff + (uint32_t)(r * FSTRH + c * 8) * 2,
                      Kp + base + kvoff + (size_t)r * QSTR + c * 8);
                cpa16(sVu + stoff + (uint32_t)(r * FSTRH + c * 8) * 2,
                      Vp + base + kvoff + (size_t)r * QSTR + c * 8);
            }
            asm volatile("cp.async.commit_group;\n" ::: "memory");
            asm volatile("cp.async.wait_group 1;\n" ::: "memory");
        } else {
            asm volatile("cp.async.wait_group 0;\n" ::: "memory");
        }
        __syncthreads();

        int st = it & 1;
        const unsigned* Kw = (const unsigned*)(sK + st * FBKV * FSTRH);
        uint32_t vstage = sVu + (uint32_t)st * FKV_BYTES;

        // ---- S = Q K^T (fp16 mma, 4 k16 slices over d=64) ----
        float cs[8][4];
        #pragma unroll
        for (int nt = 0; nt < 8; nt++)
            #pragma unroll
            for (int i = 0; i < 4; i++) cs[nt][i] = 0.f;

        #pragma unroll
        for (int ks = 0; ks < 4; ks++) {
            int kw = ks * 8 + tg;
            unsigned bf[8][2];
            #pragma unroll
            for (int nt = 0; nt < 8; nt++) {
                int n = nt * 8 + g;
                bf[nt][0] = Kw[n * 36 + kw];
                bf[nt][1] = Kw[n * 36 + kw + 4];
            }
            #pragma unroll
            for (int nt = 0; nt < 8; nt++)
                mma_f16(cs[nt], aq[ks], bf[nt]);
        }

        // ---- online softmax ----
        float rm0 = -1e30f, rm1 = -1e30f;
        #pragma unroll
        for (int nt = 0; nt < 8; nt++) {
            #pragma unroll
            for (int i = 0; i < 4; i++) cs[nt][i] *= 0.125f;
            rm0 = fmaxf(rm0, fmaxf(cs[nt][0], cs[nt][1]));
            rm1 = fmaxf(rm1, fmaxf(cs[nt][2], cs[nt][3]));
        }
        rm0 = fmaxf(rm0, __shfl_xor_sync(0xffffffffu, rm0, 1));
        rm0 = fmaxf(rm0, __shfl_xor_sync(0xffffffffu, rm0, 2));
        rm1 = fmaxf(rm1, __shfl_xor_sync(0xffffffffu, rm1, 1));
        rm1 = fmaxf(rm1, __shfl_xor_sync(0xffffffffu, rm1, 2));
        float mn0 = fmaxf(m0, rm0);
        float mn1 = fmaxf(m1, rm1);

        __half2* sPh2 = (__half2*)sP;
        float ps0 = 0.f, ps1 = 0.f;
        #pragma unroll
        for (int nt = 0; nt < 8; nt++) {
            float p00 = __expf(cs[nt][0] - mn0);
            float p01 = __expf(cs[nt][1] - mn0);
            float p10 = __expf(cs[nt][2] - mn1);
            float p11 = __expf(cs[nt][3] - mn1);
            ps0 += p00 + p01;
            ps1 += p10 + p11;
            sPh2[(mrow + g) * 36 + nt * 4 + tg]     = __floats2half2_rn(p00, p01);
            sPh2[(mrow + g + 8) * 36 + nt * 4 + tg] = __floats2half2_rn(p10, p11);
        }
        ps0 += __shfl_xor_sync(0xffffffffu, ps0, 1);
        ps0 += __shfl_xor_sync(0xffffffffu, ps0, 2);
        ps1 += __shfl_xor_sync(0xffffffffu, ps1, 1);
        ps1 += __shfl_xor_sync(0xffffffffu, ps1, 2);

        float f0 = __expf(m0 - mn0);
        float f1 = __expf(m1 - mn1);
        l0 = l0 * f0 + ps0;
        l1 = l1 * f1 + ps1;
        m0 = mn0; m1 = mn1;
        #pragma unroll
        for (int nt = 0; nt < 8; nt++) {
            co[nt][0] *= f0; co[nt][1] *= f0;
            co[nt][2] *= f1; co[nt][3] *= f1;
        }
        __syncwarp();   // P slab is warp-private

        // ---- O += P V (4 k16 slices over kv=64; V frags via ldmatrix.trans) ----
        #pragma unroll
        for (int ks = 0; ks < 4; ks++) {
            int kw = ks * 8 + tg;
            unsigned ap[4];
            ap[0] = sPw[(mrow + g) * 36 + kw];
            ap[1] = sPw[(mrow + g + 8) * 36 + kw];
            ap[2] = sPw[(mrow + g) * 36 + kw + 4];
            ap[3] = sPw[(mrow + g + 8) * 36 + kw + 4];
            #pragma unroll
            for (int ntp = 0; ntp < 4; ntp++) {
                unsigned bb[4];
                uint32_t addr = vstage +
                    (uint32_t)((ks * 16 + vrow) * FSTRH + ntp * 16 + vcol) * 2;
                ldmx4t(bb, addr);
                mma_f16(co[2 * ntp],     ap, bb);
                mma_f16(co[2 * ntp + 1], ap, bb + 2);
            }
        }
        __syncwarp();
        __syncthreads();
    }

    // ---- normalize + write fp16 O ----
    float i0 = 1.f / l0, i1 = 1.f / l1;
    size_t obase = ((size_t)b * LSEQ) * DM + (size_t)h * HD;
    #pragma unroll
    for (int nt = 0; nt < 8; nt++) {
        int col = nt * 8 + 2 * tg;
        size_t o0 = obase + (size_t)(q0 + mrow + g) * DM + col;
        size_t o1 = obase + (size_t)(q0 + mrow + g + 8) * DM + col;
        *(__half2*)(O + o0) = __floats2half2_rn(co[nt][0] * i0, co[nt][1] * i0);
        *(__half2*)(O + o1) = __floats2half2_rn(co[nt][2] * i1, co[nt][3] * i1);
    }
}

// ---------------- launch ----------------
extern "C" void kernel_launch(void* const* d_in, const int* in_sizes, int n_in,
                              void* d_out, int out_size)
{
    const float* x           = (const float*)d_in[0];
    const float* W_q         = (const float*)d_in[1];
    const float* W_k         = (const float*)d_in[2];
    const float* W_v         = (const float*)d_in[3];
    const float* W_o         = (const float*)d_in[4];
    const float* b_o         = (const float*)d_in[5];
    const float* attn_norm_w = (const float*)d_in[6];
    const float* ffn_norm_w  = (const float*)d_in[7];
    const float* W_gate      = (const float*)d_in[8];
    const float* W_hidden    = (const float*)d_in[9];
    const float* W_out       = (const float*)d_in[10];
    const float* b_out       = (const float*)d_in[11];
    float* out = (float*)d_out;

    __half *xnh, *qkvh, *atth, *xn2h, *gateh, *hidh;
    __half *wtqkv, *wto, *wtg, *wth, *wtout;
    float *x1;
    cudaGetSymbolAddress((void**)&xnh,    g_xnh);
    cudaGetSymbolAddress((void**)&qkvh,   g_qkvh);
    cudaGetSymbolAddress((void**)&atth,   g_atth);
    cudaGetSymbolAddress((void**)&x1,     g_x1);
    cudaGetSymbolAddress((void**)&xn2h,   g_xn2h);
    cudaGetSymbolAddress((void**)&gateh,  g_gateh);
    cudaGetSymbolAddress((void**)&hidh,   g_hidh);
    cudaGetSymbolAddress((void**)&wtqkv,  g_wtqkv);
    cudaGetSymbolAddress((void**)&wto,    g_wto);
    cudaGetSymbolAddress((void**)&wtg,    g_wtg);
    cudaGetSymbolAddress((void**)&wth,    g_wth);
    cudaGetSymbolAddress((void**)&wtout,  g_wtout);

    static int smem_set = 0;
    if (!smem_set) {
        cudaFuncSetAttribute(flash_h_kernel,
            cudaFuncAttributeMaxDynamicSharedMemorySize, FA_SMEM);
        smem_set = 1;
    }

    // weight transposes + fp16 conversion: [K][N] -> [N][K]
    transpose_cvt_kernel<<<dim3(DM / 32, DM / 32), 256>>>(W_q, wtqkv,               DM, DM);
    transpose_cvt_kernel<<<dim3(DM / 32, DM / 32), 256>>>(W_k, wtqkv + DM * DM,     DM, DM);
    transpose_cvt_kernel<<<dim3(DM / 32, DM / 32), 256>>>(W_v, wtqkv + 2 * DM * DM, DM, DM);
    transpose_cvt_kernel<<<dim3(DM / 32, DM / 32), 256>>>(W_o, wto, DM, DM);
    transpose_cvt_kernel<<<dim3(DH / 32, DM / 32), 256>>>(W_gate,   wtg, DM, DH);
    transpose_cvt_kernel<<<dim3(DH / 32, DM / 32), 256>>>(W_hidden, wth, DM, DH);
    transpose_cvt_kernel<<<dim3(DM / 32, DH / 32), 256>>>(W_out,  wtout, DH, DM);

    // 1. attn pre-norm (fp16)
    rmsnorm_h_kernel<<<NT, 256>>>(x, attn_norm_w, xnh);
    // 2. fused QKV projection -> fp16 packed [NT][3072]
    gemm_f16<1, 0, 0, 0><<<dim3(QSTR / HBN, NT / HBM), 256, HSMEM>>>(
        xnh, wtqkv, qkvh, NT, QSTR, DM, nullptr, nullptr, nullptr);
    // 3. attention (fp16 in/out)
    flash_h_kernel<<<dim3(LSEQ / FBQ, NBATCH * NH), 256, FA_SMEM>>>(qkvh, atth);
    // 4. output projection + bias + residual (fp32 out)
    gemm_f16<0, 1, 1, 0><<<dim3(DM / HBN, NT / HBM), 256, HSMEM>>>(
        atth, wto, x1, NT, DM, DM, b_o, x, nullptr);
    // 5. ffn pre-norm (fp16)
    rmsnorm_h_kernel<<<NT, 256>>>(x1, ffn_norm_w, xn2h);
    // 6. gate GEMM (fp16)
    gemm_f16<1, 0, 0, 0><<<dim3(DH / HBN, NT / HBM), 256, HSMEM>>>(
        xn2h, wtg, gateh, NT, DH, DM, nullptr, nullptr, nullptr);
    // 7. hidden GEMM with fused swiglu epilogue: hidh = silu(gate) * hid (fp16)
    gemm_f16<1, 0, 0, 1><<<dim3(DH / HBN, NT / HBM), 256, HSMEM>>>(
        xn2h, wth, hidh, NT, DH, DM, nullptr, nullptr, gateh);
    // 8. out projection + bias + residual (fp32 out)
    gemm_f16<0, 1, 1, 0><<<dim3(DM / HBN, NT / HBM), 256, HSMEM>>>(
        hidh, wtout, out, NT, DM, DH, b_out, x1, nullptr);
}

// round 8
// speedup vs baseline: 9.6227x; 1.1186x over previous
#include <cuda_runtime.h>
#include <cuda_fp16.h>
#include <math.h>
#include <stdint.h>

#define NT 4096      // total tokens (B*L)
#define DM 1024      // d_model
#define DH 4096      // d_hidden
#define NH 16
#define HD 64
#define LSEQ 2048
#define NBATCH 2
#define QSTR 3072    // packed qkv row stride

// ---------------- scratch (static device globals; no runtime alloc) ----------------
__device__ __half g_xnh [NT * DM];
__device__ __half g_qkvh[(size_t)NT * QSTR];
__device__ __half g_atth[NT * DM];
__device__ float  g_x1  [NT * DM];
__device__ __half g_xn2h[NT * DM];
__device__ __half g_gateh[(size_t)NT * DH];
__device__ __half g_hidh [(size_t)NT * DH];
// fp16 weights, NATURAL [K][N] layout (no transpose)
__device__ __half g_wqkv[(size_t)DM * QSTR];        // [1024][3072] q|k|v
__device__ __half g_wo  [DM * DM];
__device__ __half g_wg  [(size_t)DM * DH];
__device__ __half g_wh  [(size_t)DM * DH];
__device__ __half g_wout[(size_t)DH * DM];

// ---------------- PTX helpers ----------------
__device__ __forceinline__ void cpa16(uint32_t saddr, const void* src) {
    asm volatile("cp.async.cg.shared.global [%0], [%1], 16;\n" :: "r"(saddr), "l"(src));
}
__device__ __forceinline__ uint32_t s2u(const void* p) {
    uint32_t a;
    asm("{ .reg .u64 t; cvta.to.shared.u64 t, %1; cvt.u32.u64 %0, t; }" : "=r"(a) : "l"(p));
    return a;
}
__device__ __forceinline__ void mma_f16(float* c, const unsigned* a, const unsigned* b) {
    asm volatile("mma.sync.aligned.m16n8k16.row.col.f32.f16.f16.f32 "
        "{%0,%1,%2,%3}, {%4,%5,%6,%7}, {%8,%9}, {%0,%1,%2,%3};\n"
        : "+f"(c[0]), "+f"(c[1]), "+f"(c[2]), "+f"(c[3])
        : "r"(a[0]), "r"(a[1]), "r"(a[2]), "r"(a[3]), "r"(b[0]), "r"(b[1]));
}
__device__ __forceinline__ void ldmx4(unsigned* r, uint32_t addr) {
    asm volatile("ldmatrix.sync.aligned.m8n8.x4.shared.b16 {%0,%1,%2,%3}, [%4];"
        : "=r"(r[0]), "=r"(r[1]), "=r"(r[2]), "=r"(r[3]) : "r"(addr));
}
__device__ __forceinline__ void ldmx4t(unsigned* r, uint32_t addr) {
    asm volatile("ldmatrix.sync.aligned.m8n8.x4.trans.shared.b16 {%0,%1,%2,%3}, [%4];"
        : "=r"(r[0]), "=r"(r[1]), "=r"(r[2]), "=r"(r[3]) : "r"(addr));
}

// ---------------- pure fp32->fp16 convert (streaming, coalesced) ----------------
// in: [R][C] fp32, out row stride outStride halves, col offset baked into out ptr.
__global__ __launch_bounds__(256) void cvt_h_kernel(
    const float* __restrict__ in, __half* __restrict__ out, int C, int outStride)
{
    int idx = blockIdx.x * 256 + threadIdx.x;    // one per 8 elems
    int tpr = C >> 3;
    int row = idx / tpr;
    int col = (idx - row * tpr) * 8;
    const float4* p = (const float4*)(in + (size_t)row * C + col);
    float4 a = p[0], b = p[1];
    __half2 h0 = __floats2half2_rn(a.x, a.y);
    __half2 h1 = __floats2half2_rn(a.z, a.w);
    __half2 h2 = __floats2half2_rn(b.x, b.y);
    __half2 h3 = __floats2half2_rn(b.z, b.w);
    uint4 v;
    v.x = *(unsigned*)&h0; v.y = *(unsigned*)&h1;
    v.z = *(unsigned*)&h2; v.w = *(unsigned*)&h3;
    *(uint4*)(out + (size_t)row * outStride + col) = v;
}

// ---------------- RMSNorm: fp32 in -> fp16 out ----------------
__global__ __launch_bounds__(256) void rmsnorm_h_kernel(
    const float* __restrict__ x, const float* __restrict__ w, __half* __restrict__ out)
{
    int row = blockIdx.x;
    const float4* xr = (const float4*)(x + (size_t)row * DM);
    float4 v = xr[threadIdx.x];
    float s = v.x * v.x + v.y * v.y + v.z * v.z + v.w * v.w;
    __shared__ float red[8];
    #pragma unroll
    for (int o = 16; o > 0; o >>= 1) s += __shfl_xor_sync(0xffffffffu, s, o);
    if ((threadIdx.x & 31) == 0) red[threadIdx.x >> 5] = s;
    __syncthreads();
    if (threadIdx.x < 8) {
        float t = red[threadIdx.x];
        #pragma unroll
        for (int o = 4; o > 0; o >>= 1) t += __shfl_xor_sync(0xffu, t, o);
        if (threadIdx.x == 0) red[0] = t;
    }
    __syncthreads();
    float inv = rsqrtf(red[0] * (1.0f / DM) + 1e-6f);
    float4 wv = ((const float4*)w)[threadIdx.x];
    __half2* orow = (__half2*)(out + (size_t)row * DM);
    orow[2 * threadIdx.x]     = __floats2half2_rn(wv.x * v.x * inv, wv.y * v.y * inv);
    orow[2 * threadIdx.x + 1] = __floats2half2_rn(wv.z * v.z * inv, wv.w * v.w * inv);
}

// ================= fp16 tensor-core GEMM, B in natural [K][N] =================
// C[M,N] = A[M,K] @ B[K,N] (+bias)(+res)(+swiglu). 256 thr, 8 warps (4m x 2n),
// warp tile 32x64. A smem [128][40h]; B smem [32][136h]. Frags via ldmatrix.
#define HBM 128
#define HBN 128
#define HBK 32
#define ASTRH 40                               // A halves/row (5x16B, coprime 8)
#define BSTRH 136                              // B halves/row (17x16B, coprime 8)
#define ATILE_B (HBM * ASTRH * 2)              // 10240
#define BTILE_B (HBK * BSTRH * 2)              // 8704
#define HSTAGE (ATILE_B + BTILE_B)             // 18944
#define HSMEM  (2 * HSTAGE)                    // 37888

__device__ __forceinline__ void hload(uint32_t s0, const __half* A, const __half* B,
    int bm, int bn, int K, int N, int kk, int tid)
{
    const __half* Ag = A + (size_t)bm * K + kk;
    const __half* Bg = B + (size_t)kk * N + bn;
    #pragma unroll
    for (int j = 0; j < 2; j++) {
        int idx = tid + 256 * j;               // 0..511
        int ar = idx >> 2, ac = idx & 3;
        cpa16(s0 + (uint32_t)(ar * ASTRH + ac * 8) * 2, Ag + (size_t)ar * K + ac * 8);
        int br = idx >> 4, bc = idx & 15;
        cpa16(s0 + (uint32_t)ATILE_B + (uint32_t)(br * BSTRH + bc * 8) * 2,
              Bg + (size_t)br * N + bc * 8);
    }
    asm volatile("cp.async.commit_group;\n" ::: "memory");
}

template <int OUT_HALF, int HAS_BIAS, int HAS_RES, int SWI>
__global__ __launch_bounds__(256, 2) void gemm_f16(
    const __half* __restrict__ A, const __half* __restrict__ B, void* __restrict__ Cv,
    int M, int N, int K, const float* __restrict__ bias, const float* __restrict__ res,
    const __half* __restrict__ aux)
{
    extern __shared__ char hsm[];
    uint32_t sbase = s2u(hsm);
    int tid = threadIdx.x;
    int lane = tid & 31, g = lane >> 2, tg = lane & 3;
    int wid = tid >> 5;
    int m_base = (wid >> 1) * 32;
    int n_base = (wid & 1) * 64;
    int bm = blockIdx.y * HBM, bn = blockIdx.x * HBN;
    int lr = lane & 15, lc = lane >> 4;        // ldmatrix address split

    float c[2][8][4];
    #pragma unroll
    for (int mt = 0; mt < 2; mt++)
        #pragma unroll
        for (int nt = 0; nt < 8; nt++)
            #pragma unroll
            for (int i = 0; i < 4; i++) c[mt][nt][i] = 0.f;

    const int iters = K / HBK;
    hload(sbase, A, B, bm, bn, K, N, 0, tid);

    for (int it = 0; it < iters; ++it) {
        if (it + 1 < iters) {
            hload(sbase + ((it + 1) & 1) * HSTAGE, A, B, bm, bn, K, N, (it + 1) * HBK, tid);
            asm volatile("cp.async.wait_group 1;\n" ::: "memory");
        } else {
            asm volatile("cp.async.wait_group 0;\n" ::: "memory");
        }
        __syncthreads();

        uint32_t As = sbase + (uint32_t)(it & 1) * HSTAGE;
        uint32_t Bs = As + ATILE_B;

        #pragma unroll
        for (int ks = 0; ks < 2; ++ks) {
            unsigned af[2][4];
            #pragma unroll
            for (int mt = 0; mt < 2; ++mt)
                ldmx4(af[mt], As + (uint32_t)((m_base + mt * 16 + lr) * ASTRH
                                              + ks * 16 + lc * 8) * 2);
            #pragma unroll
            for (int ntp = 0; ntp < 4; ++ntp) {
                unsigned bb[4];
                ldmx4t(bb, Bs + (uint32_t)((ks * 16 + lr) * BSTRH
                                           + n_base + ntp * 16 + lc * 8) * 2);
                #pragma unroll
                for (int mt = 0; mt < 2; ++mt) {
                    mma_f16(c[mt][2 * ntp],     af[mt], bb);
                    mma_f16(c[mt][2 * ntp + 1], af[mt], bb + 2);
                }
            }
        }
        __syncthreads();
    }

    #pragma unroll
    for (int mt = 0; mt < 2; ++mt) {
        #pragma unroll
        for (int nt = 0; nt < 8; ++nt) {
            int row = bm + m_base + mt * 16 + g;
            int col = bn + n_base + nt * 8 + 2 * tg;
            size_t o0 = (size_t)row * N + col;
            size_t o1 = (size_t)(row + 8) * N + col;
            float v00 = c[mt][nt][0], v01 = c[mt][nt][1];
            float v10 = c[mt][nt][2], v11 = c[mt][nt][3];
            if (HAS_BIAS) {
                float b0v = bias[col], b1v = bias[col + 1];
                v00 += b0v; v01 += b1v; v10 += b0v; v11 += b1v;
            }
            if (HAS_RES) {
                float2 r0 = *(const float2*)(res + o0);
                float2 r1 = *(const float2*)(res + o1);
                v00 += r0.x; v01 += r0.y; v10 += r1.x; v11 += r1.y;
            }
            if (SWI) {   // this GEMM computed hid; aux = gate. out = silu(gate)*hid
                float2 g0 = __half22float2(*(const __half2*)(aux + o0));
                float2 g1 = __half22float2(*(const __half2*)(aux + o1));
                v00 *= g0.x / (1.f + __expf(-g0.x));
                v01 *= g0.y / (1.f + __expf(-g0.y));
                v10 *= g1.x / (1.f + __expf(-g1.x));
                v11 *= g1.y / (1.f + __expf(-g1.y));
            }
            if (OUT_HALF) {
                __half* Ch = (__half*)Cv;
                *(__half2*)(Ch + o0) = __floats2half2_rn(v00, v01);
                *(__half2*)(Ch + o1) = __floats2half2_rn(v10, v11);
            } else {
                float* Cf = (float*)Cv;
                *(float2*)(Cf + o0) = make_float2(v00, v01);
                *(float2*)(Cf + o1) = make_float2(v10, v11);
            }
        }
    }
}

// ================= fp16 tensor-core flash attention =================
#define FBQ 128
#define FBKV 64
#define FSTRH 72
#define FKV_BYTES (FBKV * FSTRH * 2)
#define FP_BYTES  (FBQ * FSTRH * 2)
#define FA_SMEM (4 * FKV_BYTES + FP_BYTES)

__global__ __launch_bounds__(256, 2) void flash_h_kernel(
    const __half* __restrict__ QKV, __half* __restrict__ O)
{
    extern __shared__ __half hsm2[];
    __half* sK = hsm2;
    __half* sV = sK + 2 * FBKV * FSTRH;
    __half* sP = sV + 2 * FBKV * FSTRH;

    int tid = threadIdx.x;
    int lane = tid & 31, g = lane >> 2, tg = lane & 3;
    int wid = tid >> 5;
    int mrow = wid * 16;

    int bh = blockIdx.y;
    int b = bh >> 4, h = bh & 15;
    int q0 = blockIdx.x * FBQ;
    size_t base = ((size_t)b * LSEQ) * QSTR + (size_t)h * HD;
    const __half* Qp = QKV;
    const __half* Kp = QKV + DM;
    const __half* Vp = QKV + 2 * DM;

    #pragma unroll
    for (int i = 0; i < 4; i++) {
        int flat = tid + 256 * i;
        int r = flat >> 3, c = flat & 7;
        *(uint4*)&sP[r * FSTRH + c * 8] =
            *(const uint4*)(Qp + base + (size_t)(q0 + r) * QSTR + c * 8);
    }
    __syncthreads();
    const unsigned* sPw = (const unsigned*)sP;
    unsigned aq[4][4];
    #pragma unroll
    for (int ks = 0; ks < 4; ks++) {
        int kw = ks * 8 + tg;
        aq[ks][0] = sPw[(mrow + g) * 36 + kw];
        aq[ks][1] = sPw[(mrow + g + 8) * 36 + kw];
        aq[ks][2] = sPw[(mrow + g) * 36 + kw + 4];
        aq[ks][3] = sPw[(mrow + g + 8) * 36 + kw + 4];
    }
    __syncthreads();

    uint32_t sKu = s2u(sK), sVu = s2u(sV);
    int vrow = lane & 15;
    int vcol = (lane >> 4) << 3;

    #pragma unroll
    for (int j = 0; j < 2; j++) {
        int cid = tid + 256 * j;
        int r = cid >> 3, c = cid & 7;
        cpa16(sKu + (uint32_t)(r * FSTRH + c * 8) * 2,
              Kp + base + (size_t)r * QSTR + c * 8);
        cpa16(sVu + (uint32_t)(r * FSTRH + c * 8) * 2,
              Vp + base + (size_t)r * QSTR + c * 8);
    }
    asm volatile("cp.async.commit_group;\n" ::: "memory");

    float m0 = -1e30f, m1 = -1e30f, l0 = 0.f, l1 = 0.f;
    float co[8][4];
    #pragma unroll
    for (int nt = 0; nt < 8; nt++)
        #pragma unroll
        for (int i = 0; i < 4; i++) co[nt][i] = 0.f;

    const int ITERS = LSEQ / FBKV;
    for (int it = 0; it < ITERS; ++it) {
        if (it + 1 < ITERS) {
            uint32_t stoff = (uint32_t)((it + 1) & 1) * FKV_BYTES;
            size_t kvoff = (size_t)(it + 1) * FBKV * QSTR;
            #pragma unroll
            for (int j = 0; j < 2; j++) {
                int cid = tid + 256 * j;
                int r = cid >> 3, c = cid & 7;
                cpa16(sKu + stoff + (uint32_t)(r * FSTRH + c * 8) * 2,
                      Kp + base + kvoff + (size_t)r * QSTR + c * 8);
                cpa16(sVu + stoff + (uint32_t)(r * FSTRH + c * 8) * 2,
                      Vp + base + kvoff + (size_t)r * QSTR + c * 8);
            }
            asm volatile("cp.async.commit_group;\n" ::: "memory");
            asm volatile("cp.async.wait_group 1;\n" ::: "memory");
        } else {
            asm volatile("cp.async.wait_group 0;\n" ::: "memory");
        }
        __syncthreads();

        int st = it & 1;
        const unsigned* Kw = (const unsigned*)(sK + st * FBKV * FSTRH);
        uint32_t vstage = sVu + (uint32_t)st * FKV_BYTES;

        float cs[8][4];
        #pragma unroll
        for (int nt = 0; nt < 8; nt++)
            #pragma unroll
            for (int i = 0; i < 4; i++) cs[nt][i] = 0.f;

        #pragma unroll
        for (int ks = 0; ks < 4; ks++) {
            int kw = ks * 8 + tg;
            unsigned bf[8][2];
            #pragma unroll
            for (int nt = 0; nt < 8; nt++) {
                int n = nt * 8 + g;
                bf[nt][0] = Kw[n * 36 + kw];
                bf[nt][1] = Kw[n * 36 + kw + 4];
            }
            #pragma unroll
            for (int nt = 0; nt < 8; nt++)
                mma_f16(cs[nt], aq[ks], bf[nt]);
        }

        float rm0 = -1e30f, rm1 = -1e30f;
        #pragma unroll
        for (int nt = 0; nt < 8; nt++) {
            #pragma unroll
            for (int i = 0; i < 4; i++) cs[nt][i] *= 0.125f;
            rm0 = fmaxf(rm0, fmaxf(cs[nt][0], cs[nt][1]));
            rm1 = fmaxf(rm1, fmaxf(cs[nt][2], cs[nt][3]));
        }
        rm0 = fmaxf(rm0, __shfl_xor_sync(0xffffffffu, rm0, 1));
        rm0 = fmaxf(rm0, __shfl_xor_sync(0xffffffffu, rm0, 2));
        rm1 = fmaxf(rm1, __shfl_xor_sync(0xffffffffu, rm1, 1));
        rm1 = fmaxf(rm1, __shfl_xor_sync(0xffffffffu, rm1, 2));
        float mn0 = fmaxf(m0, rm0);
        float mn1 = fmaxf(m1, rm1);

        __half2* sPh2 = (__half2*)sP;
        float ps0 = 0.f, ps1 = 0.f;
        #pragma unroll
        for (int nt = 0; nt < 8; nt++) {
            float p00 = __expf(cs[nt][0] - mn0);
            float p01 = __expf(cs[nt][1] - mn0);
            float p10 = __expf(cs[nt][2] - mn1);
            float p11 = __expf(cs[nt][3] - mn1);
            ps0 += p00 + p01;
            ps1 += p10 + p11;
            sPh2[(mrow + g) * 36 + nt * 4 + tg]     = __floats2half2_rn(p00, p01);
            sPh2[(mrow + g + 8) * 36 + nt * 4 + tg] = __floats2half2_rn(p10, p11);
        }
        ps0 += __shfl_xor_sync(0xffffffffu, ps0, 1);
        ps0 += __shfl_xor_sync(0xffffffffu, ps0, 2);
        ps1 += __shfl_xor_sync(0xffffffffu, ps1, 1);
        ps1 += __shfl_xor_sync(0xffffffffu, ps1, 2);

        float f0 = __expf(m0 - mn0);
        float f1 = __expf(m1 - mn1);
        l0 = l0 * f0 + ps0;
        l1 = l1 * f1 + ps1;
        m0 = mn0; m1 = mn1;
        #pragma unroll
        for (int nt = 0; nt < 8; nt++) {
            co[nt][0] *= f0; co[nt][1] *= f0;
            co[nt][2] *= f1; co[nt][3] *= f1;
        }
        __syncwarp();

        #pragma unroll
        for (int ks = 0; ks < 4; ks++) {
            int kw = ks * 8 + tg;
            unsigned ap[4];
            ap[0] = sPw[(mrow + g) * 36 + kw];
            ap[1] = sPw[(mrow + g + 8) * 36 + kw];
            ap[2] = sPw[(mrow + g) * 36 + kw + 4];
            ap[3] = sPw[(mrow + g + 8) * 36 + kw + 4];
            #pragma unroll
            for (int ntp = 0; ntp < 4; ntp++) {
                unsigned bb[4];
                uint32_t addr = vstage +
                    (uint32_t)((ks * 16 + vrow) * FSTRH + ntp * 16 + vcol) * 2;
                ldmx4t(bb, addr);
                mma_f16(co[2 * ntp],     ap, bb);
                mma_f16(co[2 * ntp + 1], ap, bb + 2);
            }
        }
        __syncwarp();
        __syncthreads();
    }

    float i0 = 1.f / l0, i1 = 1.f / l1;
    size_t obase = ((size_t)b * LSEQ) * DM + (size_t)h * HD;
    #pragma unroll
    for (int nt = 0; nt < 8; nt++) {
        int col = nt * 8 + 2 * tg;
        size_t o0 = obase + (size_t)(q0 + mrow + g) * DM + col;
        size_t o1 = obase + (size_t)(q0 + mrow + g + 8) * DM + col;
        *(__half2*)(O + o0) = __floats2half2_rn(co[nt][0] * i0, co[nt][1] * i0);
        *(__half2*)(O + o1) = __floats2half2_rn(co[nt][2] * i1, co[nt][3] * i1);
    }
}

// ---------------- launch ----------------
extern "C" void kernel_launch(void* const* d_in, const int* in_sizes, int n_in,
                              void* d_out, int out_size)
{
    const float* x           = (const float*)d_in[0];
    const float* W_q         = (const float*)d_in[1];
    const float* W_k         = (const float*)d_in[2];
    const float* W_v         = (const float*)d_in[3];
    const float* W_o         = (const float*)d_in[4];
    const float* b_o         = (const float*)d_in[5];
    const float* attn_norm_w = (const float*)d_in[6];
    const float* ffn_norm_w  = (const float*)d_in[7];
    const float* W_gate      = (const float*)d_in[8];
    const float* W_hidden    = (const float*)d_in[9];
    const float* W_out       = (const float*)d_in[10];
    const float* b_out       = (const float*)d_in[11];
    float* out = (float*)d_out;

    __half *xnh, *qkvh, *atth, *xn2h, *gateh, *hidh;
    __half *wqkv, *wo, *wg, *wh, *wout;
    float *x1;
    cudaGetSymbolAddress((void**)&xnh,   g_xnh);
    cudaGetSymbolAddress((void**)&qkvh,  g_qkvh);
    cudaGetSymbolAddress((void**)&atth,  g_atth);
    cudaGetSymbolAddress((void**)&x1,    g_x1);
    cudaGetSymbolAddress((void**)&xn2h,  g_xn2h);
    cudaGetSymbolAddress((void**)&gateh, g_gateh);
    cudaGetSymbolAddress((void**)&hidh,  g_hidh);
    cudaGetSymbolAddress((void**)&wqkv,  g_wqkv);
    cudaGetSymbolAddress((void**)&wo,    g_wo);
    cudaGetSymbolAddress((void**)&wg,    g_wg);
    cudaGetSymbolAddress((void**)&wh,    g_wh);
    cudaGetSymbolAddress((void**)&wout,  g_wout);

    static int smem_set = 0;
    if (!smem_set) {
        cudaFuncSetAttribute(flash_h_kernel,
            cudaFuncAttributeMaxDynamicSharedMemorySize, FA_SMEM);
        smem_set = 1;
    }

    // fp32->fp16 weight converts (streaming, no transpose).
    // QKV packed along N into [1024][3072].
    cvt_h_kernel<<<DM * DM / 8 / 256, 256>>>(W_q, wqkv,            DM, QSTR);
    cvt_h_kernel<<<DM * DM / 8 / 256, 256>>>(W_k, wqkv + DM,       DM, QSTR);
    cvt_h_kernel<<<DM * DM / 8 / 256, 256>>>(W_v, wqkv + 2 * DM,   DM, QSTR);
    cvt_h_kernel<<<DM * DM / 8 / 256, 256>>>(W_o, wo, DM, DM);
    cvt_h_kernel<<<DM * DH / 8 / 256, 256>>>(W_gate,   wg, DH, DH);
    cvt_h_kernel<<<DM * DH / 8 / 256, 256>>>(W_hidden, wh, DH, DH);
    cvt_h_kernel<<<DH * DM / 8 / 256, 256>>>(W_out,  wout, DM, DM);

    // 1. attn pre-norm (fp16)
    rmsnorm_h_kernel<<<NT, 256>>>(x, attn_norm_w, xnh);
    // 2. fused QKV projection -> fp16 packed [NT][3072]
    gemm_f16<1, 0, 0, 0><<<dim3(QSTR / HBN, NT / HBM), 256, HSMEM>>>(
        xnh, wqkv, qkvh, NT, QSTR, DM, nullptr, nullptr, nullptr);
    // 3. attention (fp16 in/out)
    flash_h_kernel<<<dim3(LSEQ / FBQ, NBATCH * NH), 256, FA_SMEM>>>(qkvh, atth);
    // 4. output projection + bias + residual (fp32 out)
    gemm_f16<0, 1, 1, 0><<<dim3(DM / HBN, NT / HBM), 256, HSMEM>>>(
        atth, wo, x1, NT, DM, DM, b_o, x, nullptr);
    // 5. ffn pre-norm (fp16)
    rmsnorm_h_kernel<<<NT, 256>>>(x1, ffn_norm_w, xn2h);
    // 6. gate GEMM (fp16)
    gemm_f16<1, 0, 0, 0><<<dim3(DH / HBN, NT / HBM), 256, HSMEM>>>(
        xn2h, wg, gateh, NT, DH, DM, nullptr, nullptr, nullptr);
    // 7. hidden GEMM with fused swiglu epilogue: hidh = silu(gate) * hid (fp16)
    gemm_f16<1, 0, 0, 1><<<dim3(DH / HBN, NT / HBM), 256, HSMEM>>>(
        xn2h, wh, hidh, NT, DH, DM, nullptr, nullptr, gateh);
    // 8. out projection + bias + residual (fp32 out)
    gemm_f16<0, 1, 1, 0><<<dim3(DM / HBN, NT / HBM), 256, HSMEM>>>(
        hidh, wout, out, NT, DM, DH, b_out, x1, nullptr);
}

// round 9
// speedup vs baseline: 10.2520x; 1.0654x over previous
#include <cuda_runtime.h>
#include <cuda_fp16.h>
#include <math.h>
#include <stdint.h>

#define NT 4096      // total tokens (B*L)
#define DM 1024      // d_model
#define DH 4096      // d_hidden
#define NH 16
#define HD 64
#define LSEQ 2048
#define NBATCH 2
#define QSTR 3072    // packed qkv row stride

// ---------------- scratch (static device globals; no runtime alloc) ----------------
__device__ __half g_xnh [NT * DM];
__device__ __half g_qkvh[(size_t)NT * QSTR];
__device__ __half g_atth[NT * DM];
__device__ float  g_x1  [NT * DM];
__device__ __half g_xn2h[NT * DM];
__device__ __half g_gateh[(size_t)NT * DH];
__device__ __half g_hidh [(size_t)NT * DH];
// fp16 weights, NATURAL [K][N] layout (no transpose)
__device__ __half g_wqkv[(size_t)DM * QSTR];
__device__ __half g_wo  [DM * DM];
__device__ __half g_wg  [(size_t)DM * DH];
__device__ __half g_wh  [(size_t)DM * DH];
__device__ __half g_wout[(size_t)DH * DM];

// ---------------- PTX helpers ----------------
__device__ __forceinline__ void cpa16(uint32_t saddr, const void* src) {
    asm volatile("cp.async.cg.shared.global [%0], [%1], 16;\n" :: "r"(saddr), "l"(src));
}
__device__ __forceinline__ uint32_t s2u(const void* p) {
    uint32_t a;
    asm("{ .reg .u64 t; cvta.to.shared.u64 t, %1; cvt.u32.u64 %0, t; }" : "=r"(a) : "l"(p));
    return a;
}
__device__ __forceinline__ void mma_f16(float* c, const unsigned* a, const unsigned* b) {
    asm volatile("mma.sync.aligned.m16n8k16.row.col.f32.f16.f16.f32 "
        "{%0,%1,%2,%3}, {%4,%5,%6,%7}, {%8,%9}, {%0,%1,%2,%3};\n"
        : "+f"(c[0]), "+f"(c[1]), "+f"(c[2]), "+f"(c[3])
        : "r"(a[0]), "r"(a[1]), "r"(a[2]), "r"(a[3]), "r"(b[0]), "r"(b[1]));
}
__device__ __forceinline__ void ldmx4(unsigned* r, uint32_t addr) {
    asm volatile("ldmatrix.sync.aligned.m8n8.x4.shared.b16 {%0,%1,%2,%3}, [%4];"
        : "=r"(r[0]), "=r"(r[1]), "=r"(r[2]), "=r"(r[3]) : "r"(addr));
}
__device__ __forceinline__ void ldmx4t(unsigned* r, uint32_t addr) {
    asm volatile("ldmatrix.sync.aligned.m8n8.x4.trans.shared.b16 {%0,%1,%2,%3}, [%4];"
        : "=r"(r[0]), "=r"(r[1]), "=r"(r[2]), "=r"(r[3]) : "r"(addr));
}

// ---------------- pure fp32->fp16 convert (streaming, coalesced) ----------------
__global__ __launch_bounds__(256) void cvt_h_kernel(
    const float* __restrict__ in, __half* __restrict__ out, int C, int outStride)
{
    int idx = blockIdx.x * 256 + threadIdx.x;
    int tpr = C >> 3;
    int row = idx / tpr;
    int col = (idx - row * tpr) * 8;
    const float4* p = (const float4*)(in + (size_t)row * C + col);
    float4 a = p[0], b = p[1];
    __half2 h0 = __floats2half2_rn(a.x, a.y);
    __half2 h1 = __floats2half2_rn(a.z, a.w);
    __half2 h2 = __floats2half2_rn(b.x, b.y);
    __half2 h3 = __floats2half2_rn(b.z, b.w);
    uint4 v;
    v.x = *(unsigned*)&h0; v.y = *(unsigned*)&h1;
    v.z = *(unsigned*)&h2; v.w = *(unsigned*)&h3;
    *(uint4*)(out + (size_t)row * outStride + col) = v;
}

// ---------------- RMSNorm: fp32 in -> fp16 out ----------------
__global__ __launch_bounds__(256) void rmsnorm_h_kernel(
    const float* __restrict__ x, const float* __restrict__ w, __half* __restrict__ out)
{
    int row = blockIdx.x;
    const float4* xr = (const float4*)(x + (size_t)row * DM);
    float4 v = xr[threadIdx.x];
    float s = v.x * v.x + v.y * v.y + v.z * v.z + v.w * v.w;
    __shared__ float red[8];
    #pragma unroll
    for (int o = 16; o > 0; o >>= 1) s += __shfl_xor_sync(0xffffffffu, s, o);
    if ((threadIdx.x & 31) == 0) red[threadIdx.x >> 5] = s;
    __syncthreads();
    if (threadIdx.x < 8) {
        float t = red[threadIdx.x];
        #pragma unroll
        for (int o = 4; o > 0; o >>= 1) t += __shfl_xor_sync(0xffu, t, o);
        if (threadIdx.x == 0) red[0] = t;
    }
    __syncthreads();
    float inv = rsqrtf(red[0] * (1.0f / DM) + 1e-6f);
    float4 wv = ((const float4*)w)[threadIdx.x];
    __half2* orow = (__half2*)(out + (size_t)row * DM);
    orow[2 * threadIdx.x]     = __floats2half2_rn(wv.x * v.x * inv, wv.y * v.y * inv);
    orow[2 * threadIdx.x + 1] = __floats2half2_rn(wv.z * v.z * inv, wv.w * v.w * inv);
}

// ================= fp16 tensor-core GEMM, BK=64, B natural [K][N] =================
#define HBM 128
#define HBN 128
#define HBK 64
#define ASTRH 72                               // A halves/row (9x16B, odd)
#define BSTRH 136                              // B halves/row (17x16B, odd)
#define ATILE_B (HBM * ASTRH * 2)              // 18432
#define BTILE_B (HBK * BSTRH * 2)              // 17408
#define HSTAGE (ATILE_B + BTILE_B)             // 35840
#define HSMEM  (2 * HSTAGE)                    // 71680

__device__ __forceinline__ void hload(uint32_t s0, const __half* A, const __half* B,
    int bm, int bn, int K, int N, int kk, int tid)
{
    const __half* Ag = A + (size_t)bm * K + kk;
    const __half* Bg = B + (size_t)kk * N + bn;
    #pragma unroll
    for (int j = 0; j < 4; j++) {
        int idx = tid + 256 * j;               // 0..1023
        int ar = idx >> 3, ac = idx & 7;       // A: 128 rows x 8 chunks
        cpa16(s0 + (uint32_t)(ar * ASTRH + ac * 8) * 2, Ag + (size_t)ar * K + ac * 8);
        int br = idx >> 4, bc = idx & 15;      // B: 64 rows x 16 chunks
        cpa16(s0 + (uint32_t)ATILE_B + (uint32_t)(br * BSTRH + bc * 8) * 2,
              Bg + (size_t)br * N + bc * 8);
    }
    asm volatile("cp.async.commit_group;\n" ::: "memory");
}

template <int OUT_HALF, int HAS_BIAS, int HAS_RES, int SWI>
__global__ __launch_bounds__(256, 2) void gemm_f16(
    const __half* __restrict__ A, const __half* __restrict__ B, void* __restrict__ Cv,
    int M, int N, int K, const float* __restrict__ bias, const float* __restrict__ res,
    const __half* __restrict__ aux)
{
    extern __shared__ char hsm[];
    uint32_t sbase = s2u(hsm);
    int tid = threadIdx.x;
    int lane = tid & 31, g = lane >> 2, tg = lane & 3;
    int wid = tid >> 5;
    int m_base = (wid >> 1) * 32;
    int n_base = (wid & 1) * 64;
    int bm = blockIdx.y * HBM, bn = blockIdx.x * HBN;
    int lr = lane & 15, lc = lane >> 4;

    float c[2][8][4];
    #pragma unroll
    for (int mt = 0; mt < 2; mt++)
        #pragma unroll
        for (int nt = 0; nt < 8; nt++)
            #pragma unroll
            for (int i = 0; i < 4; i++) c[mt][nt][i] = 0.f;

    const int iters = K / HBK;
    hload(sbase, A, B, bm, bn, K, N, 0, tid);

    for (int it = 0; it < iters; ++it) {
        if (it + 1 < iters) {
            hload(sbase + ((it + 1) & 1) * HSTAGE, A, B, bm, bn, K, N, (it + 1) * HBK, tid);
            asm volatile("cp.async.wait_group 1;\n" ::: "memory");
        } else {
            asm volatile("cp.async.wait_group 0;\n" ::: "memory");
        }
        __syncthreads();

        uint32_t As = sbase + (uint32_t)(it & 1) * HSTAGE;
        uint32_t Bs = As + ATILE_B;

        #pragma unroll
        for (int ks = 0; ks < 4; ++ks) {
            unsigned af[2][4];
            #pragma unroll
            for (int mt = 0; mt < 2; ++mt)
                ldmx4(af[mt], As + (uint32_t)((m_base + mt * 16 + lr) * ASTRH
                                              + ks * 16 + lc * 8) * 2);
            #pragma unroll
            for (int ntp = 0; ntp < 4; ++ntp) {
                unsigned bb[4];
                ldmx4t(bb, Bs + (uint32_t)((ks * 16 + lr) * BSTRH
                                           + n_base + ntp * 16 + lc * 8) * 2);
                #pragma unroll
                for (int mt = 0; mt < 2; ++mt) {
                    mma_f16(c[mt][2 * ntp],     af[mt], bb);
                    mma_f16(c[mt][2 * ntp + 1], af[mt], bb + 2);
                }
            }
        }
        __syncthreads();
    }

    #pragma unroll
    for (int mt = 0; mt < 2; ++mt) {
        #pragma unroll
        for (int nt = 0; nt < 8; ++nt) {
            int row = bm + m_base + mt * 16 + g;
            int col = bn + n_base + nt * 8 + 2 * tg;
            size_t o0 = (size_t)row * N + col;
            size_t o1 = (size_t)(row + 8) * N + col;
            float v00 = c[mt][nt][0], v01 = c[mt][nt][1];
            float v10 = c[mt][nt][2], v11 = c[mt][nt][3];
            if (HAS_BIAS) {
                float b0v = bias[col], b1v = bias[col + 1];
                v00 += b0v; v01 += b1v; v10 += b0v; v11 += b1v;
            }
            if (HAS_RES) {
                float2 r0 = *(const float2*)(res + o0);
                float2 r1 = *(const float2*)(res + o1);
                v00 += r0.x; v01 += r0.y; v10 += r1.x; v11 += r1.y;
            }
            if (SWI) {
                float2 g0 = __half22float2(*(const __half2*)(aux + o0));
                float2 g1 = __half22float2(*(const __half2*)(aux + o1));
                v00 *= g0.x / (1.f + __expf(-g0.x));
                v01 *= g0.y / (1.f + __expf(-g0.y));
                v10 *= g1.x / (1.f + __expf(-g1.x));
                v11 *= g1.y / (1.f + __expf(-g1.y));
            }
            if (OUT_HALF) {
                __half* Ch = (__half*)Cv;
                *(__half2*)(Ch + o0) = __floats2half2_rn(v00, v01);
                *(__half2*)(Ch + o1) = __floats2half2_rn(v10, v11);
            } else {
                float* Cf = (float*)Cv;
                *(float2*)(Cf + o0) = make_float2(v00, v01);
                *(float2*)(Cf + o1) = make_float2(v10, v11);
            }
        }
    }
}

// ================= fp16 tensor-core flash attention =================
#define FBQ 128
#define FBKV 64
#define FSTRH 72
#define FKV_BYTES (FBKV * FSTRH * 2)
#define FP_BYTES  (FBQ * FSTRH * 2)
#define FA_SMEM (4 * FKV_BYTES + FP_BYTES)

__global__ __launch_bounds__(256, 2) void flash_h_kernel(
    const __half* __restrict__ QKV, __half* __restrict__ O)
{
    extern __shared__ __half hsm2[];
    __half* sK = hsm2;
    __half* sV = sK + 2 * FBKV * FSTRH;
    __half* sP = sV + 2 * FBKV * FSTRH;

    int tid = threadIdx.x;
    int lane = tid & 31, g = lane >> 2, tg = lane & 3;
    int wid = tid >> 5;
    int mrow = wid * 16;

    int bh = blockIdx.y;
    int b = bh >> 4, h = bh & 15;
    int q0 = blockIdx.x * FBQ;
    size_t base = ((size_t)b * LSEQ) * QSTR + (size_t)h * HD;
    const __half* Qp = QKV;
    const __half* Kp = QKV + DM;
    const __half* Vp = QKV + 2 * DM;

    #pragma unroll
    for (int i = 0; i < 4; i++) {
        int flat = tid + 256 * i;
        int r = flat >> 3, c = flat & 7;
        *(uint4*)&sP[r * FSTRH + c * 8] =
            *(const uint4*)(Qp + base + (size_t)(q0 + r) * QSTR + c * 8);
    }
    __syncthreads();
    const unsigned* sPw = (const unsigned*)sP;
    unsigned aq[4][4];
    #pragma unroll
    for (int ks = 0; ks < 4; ks++) {
        int kw = ks * 8 + tg;
        aq[ks][0] = sPw[(mrow + g) * 36 + kw];
        aq[ks][1] = sPw[(mrow + g + 8) * 36 + kw];
        aq[ks][2] = sPw[(mrow + g) * 36 + kw + 4];
        aq[ks][3] = sPw[(mrow + g + 8) * 36 + kw + 4];
    }
    __syncthreads();

    uint32_t sKu = s2u(sK), sVu = s2u(sV);
    int vrow = lane & 15;
    int vcol = (lane >> 4) << 3;

    #pragma unroll
    for (int j = 0; j < 2; j++) {
        int cid = tid + 256 * j;
        int r = cid >> 3, c = cid & 7;
        cpa16(sKu + (uint32_t)(r * FSTRH + c * 8) * 2,
              Kp + base + (size_t)r * QSTR + c * 8);
        cpa16(sVu + (uint32_t)(r * FSTRH + c * 8) * 2,
              Vp + base + (size_t)r * QSTR + c * 8);
    }
    asm volatile("cp.async.commit_group;\n" ::: "memory");

    float m0 = -1e30f, m1 = -1e30f, l0 = 0.f, l1 = 0.f;
    float co[8][4];
    #pragma unroll
    for (int nt = 0; nt < 8; nt++)
        #pragma unroll
        for (int i = 0; i < 4; i++) co[nt][i] = 0.f;

    const int ITERS = LSEQ / FBKV;
    for (int it = 0; it < ITERS; ++it) {
        if (it + 1 < ITERS) {
            uint32_t stoff = (uint32_t)((it + 1) & 1) * FKV_BYTES;
            size_t kvoff = (size_t)(it + 1) * FBKV * QSTR;
            #pragma unroll
            for (int j = 0; j < 2; j++) {
                int cid = tid + 256 * j;
                int r = cid >> 3, c = cid & 7;
                cpa16(sKu + stoff + (uint32_t)(r * FSTRH + c * 8) * 2,
                      Kp + base + kvoff + (size_t)r * QSTR + c * 8);
                cpa16(sVu + stoff + (uint32_t)(r * FSTRH + c * 8) * 2,
                      Vp + base + kvoff + (size_t)r * QSTR + c * 8);
            }
            asm volatile("cp.async.commit_group;\n" ::: "memory");
            asm volatile("cp.async.wait_group 1;\n" ::: "memory");
        } else {
            asm volatile("cp.async.wait_group 0;\n" ::: "memory");
        }
        __syncthreads();

        int st = it & 1;
        const unsigned* Kw = (const unsigned*)(sK + st * FBKV * FSTRH);
        uint32_t vstage = sVu + (uint32_t)st * FKV_BYTES;

        float cs[8][4];
        #pragma unroll
        for (int nt = 0; nt < 8; nt++)
            #pragma unroll
            for (int i = 0; i < 4; i++) cs[nt][i] = 0.f;

        #pragma unroll
        for (int ks = 0; ks < 4; ks++) {
            int kw = ks * 8 + tg;
            unsigned bf[8][2];
            #pragma unroll
            for (int nt = 0; nt < 8; nt++) {
                int n = nt * 8 + g;
                bf[nt][0] = Kw[n * 36 + kw];
                bf[nt][1] = Kw[n * 36 + kw + 4];
            }
            #pragma unroll
            for (int nt = 0; nt < 8; nt++)
                mma_f16(cs[nt], aq[ks], bf[nt]);
        }

        float rm0 = -1e30f, rm1 = -1e30f;
        #pragma unroll
        for (int nt = 0; nt < 8; nt++) {
            #pragma unroll
            for (int i = 0; i < 4; i++) cs[nt][i] *= 0.125f;
            rm0 = fmaxf(rm0, fmaxf(cs[nt][0], cs[nt][1]));
            rm1 = fmaxf(rm1, fmaxf(cs[nt][2], cs[nt][3]));
        }
        rm0 = fmaxf(rm0, __shfl_xor_sync(0xffffffffu, rm0, 1));
        rm0 = fmaxf(rm0, __shfl_xor_sync(0xffffffffu, rm0, 2));
        rm1 = fmaxf(rm1, __shfl_xor_sync(0xffffffffu, rm1, 1));
        rm1 = fmaxf(rm1, __shfl_xor_sync(0xffffffffu, rm1, 2));
        float mn0 = fmaxf(m0, rm0);
        float mn1 = fmaxf(m1, rm1);

        __half2* sPh2 = (__half2*)sP;
        float ps0 = 0.f, ps1 = 0.f;
        #pragma unroll
        for (int nt = 0; nt < 8; nt++) {
            float p00 = __expf(cs[nt][0] - mn0);
            float p01 = __expf(cs[nt][1] - mn0);
            float p10 = __expf(cs[nt][2] - mn1);
            float p11 = __expf(cs[nt][3] - mn1);
            ps0 += p00 + p01;
            ps1 += p10 + p11;
            sPh2[(mrow + g) * 36 + nt * 4 + tg]     = __floats2half2_rn(p00, p01);
            sPh2[(mrow + g + 8) * 36 + nt * 4 + tg] = __floats2half2_rn(p10, p11);
        }
        ps0 += __shfl_xor_sync(0xffffffffu, ps0, 1);
        ps0 += __shfl_xor_sync(0xffffffffu, ps0, 2);
        ps1 += __shfl_xor_sync(0xffffffffu, ps1, 1);
        ps1 += __shfl_xor_sync(0xffffffffu, ps1, 2);

        float f0 = __expf(m0 - mn0);
        float f1 = __expf(m1 - mn1);
        l0 = l0 * f0 + ps0;
        l1 = l1 * f1 + ps1;
        m0 = mn0; m1 = mn1;
        #pragma unroll
        for (int nt = 0; nt < 8; nt++) {
            co[nt][0] *= f0; co[nt][1] *= f0;
            co[nt][2] *= f1; co[nt][3] *= f1;
        }
        __syncwarp();

        #pragma unroll
        for (int ks = 0; ks < 4; ks++) {
            int kw = ks * 8 + tg;
            unsigned ap[4];
            ap[0] = sPw[(mrow + g) * 36 + kw];
            ap[1] = sPw[(mrow + g + 8) * 36 + kw];
            ap[2] = sPw[(mrow + g) * 36 + kw + 4];
            ap[3] = sPw[(mrow + g + 8) * 36 + kw + 4];
            #pragma unroll
            for (int ntp = 0; ntp < 4; ntp++) {
                unsigned bb[4];
                uint32_t addr = vstage +
                    (uint32_t)((ks * 16 + vrow) * FSTRH + ntp * 16 + vcol) * 2;
                ldmx4t(bb, addr);
                mma_f16(co[2 * ntp],     ap, bb);
                mma_f16(co[2 * ntp + 1], ap, bb + 2);
            }
        }
        __syncwarp();
        __syncthreads();
    }

    float i0 = 1.f / l0, i1 = 1.f / l1;
    size_t obase = ((size_t)b * LSEQ) * DM + (size_t)h * HD;
    #pragma unroll
    for (int nt = 0; nt < 8; nt++) {
        int col = nt * 8 + 2 * tg;
        size_t o0 = obase + (size_t)(q0 + mrow + g) * DM + col;
        size_t o1 = obase + (size_t)(q0 + mrow + g + 8) * DM + col;
        *(__half2*)(O + o0) = __floats2half2_rn(co[nt][0] * i0, co[nt][1] * i0);
        *(__half2*)(O + o1) = __floats2half2_rn(co[nt][2] * i1, co[nt][3] * i1);
    }
}

// ---------------- launch ----------------
extern "C" void kernel_launch(void* const* d_in, const int* in_sizes, int n_in,
                              void* d_out, int out_size)
{
    const float* x           = (const float*)d_in[0];
    const float* W_q         = (const float*)d_in[1];
    const float* W_k         = (const float*)d_in[2];
    const float* W_v         = (const float*)d_in[3];
    const float* W_o         = (const float*)d_in[4];
    const float* b_o         = (const float*)d_in[5];
    const float* attn_norm_w = (const float*)d_in[6];
    const float* ffn_norm_w  = (const float*)d_in[7];
    const float* W_gate      = (const float*)d_in[8];
    const float* W_hidden    = (const float*)d_in[9];
    const float* W_out       = (const float*)d_in[10];
    const float* b_out       = (const float*)d_in[11];
    float* out = (float*)d_out;

    __half *xnh, *qkvh, *atth, *xn2h, *gateh, *hidh;
    __half *wqkv, *wo, *wg, *wh, *wout;
    float *x1;
    cudaGetSymbolAddress((void**)&xnh,   g_xnh);
    cudaGetSymbolAddress((void**)&qkvh,  g_qkvh);
    cudaGetSymbolAddress((void**)&atth,  g_atth);
    cudaGetSymbolAddress((void**)&x1,    g_x1);
    cudaGetSymbolAddress((void**)&xn2h,  g_xn2h);
    cudaGetSymbolAddress((void**)&gateh, g_gateh);
    cudaGetSymbolAddress((void**)&hidh,  g_hidh);
    cudaGetSymbolAddress((void**)&wqkv,  g_wqkv);
    cudaGetSymbolAddress((void**)&wo,    g_wo);
    cudaGetSymbolAddress((void**)&wg,    g_wg);
    cudaGetSymbolAddress((void**)&wh,    g_wh);
    cudaGetSymbolAddress((void**)&wout,  g_wout);

    static int smem_set = 0;
    if (!smem_set) {
        cudaFuncSetAttribute(flash_h_kernel,
            cudaFuncAttributeMaxDynamicSharedMemorySize, FA_SMEM);
        cudaFuncSetAttribute(gemm_f16<1, 0, 0, 0>,
            cudaFuncAttributeMaxDynamicSharedMemorySize, HSMEM);
        cudaFuncSetAttribute(gemm_f16<0, 1, 1, 0>,
            cudaFuncAttributeMaxDynamicSharedMemorySize, HSMEM);
        cudaFuncSetAttribute(gemm_f16<1, 0, 0, 1>,
            cudaFuncAttributeMaxDynamicSharedMemorySize, HSMEM);
        smem_set = 1;
    }

    // fp32->fp16 weight converts (streaming, no transpose).
    cvt_h_kernel<<<DM * DM / 8 / 256, 256>>>(W_q, wqkv,            DM, QSTR);
    cvt_h_kernel<<<DM * DM / 8 / 256, 256>>>(W_k, wqkv + DM,       DM, QSTR);
    cvt_h_kernel<<<DM * DM / 8 / 256, 256>>>(W_v, wqkv + 2 * DM,   DM, QSTR);
    cvt_h_kernel<<<DM * DM / 8 / 256, 256>>>(W_o, wo, DM, DM);
    cvt_h_kernel<<<DM * DH / 8 / 256, 256>>>(W_gate,   wg, DH, DH);
    cvt_h_kernel<<<DM * DH / 8 / 256, 256>>>(W_hidden, wh, DH, DH);
    cvt_h_kernel<<<DH * DM / 8 / 256, 256>>>(W_out,  wout, DM, DM);

    // 1. attn pre-norm (fp16)
    rmsnorm_h_kernel<<<NT, 256>>>(x, attn_norm_w, xnh);
    // 2. fused QKV projection -> fp16 packed [NT][3072]
    gemm_f16<1, 0, 0, 0><<<dim3(QSTR / HBN, NT / HBM), 256, HSMEM>>>(
        xnh, wqkv, qkvh, NT, QSTR, DM, nullptr, nullptr, nullptr);
    // 3. attention (fp16 in/out)
    flash_h_kernel<<<dim3(LSEQ / FBQ, NBATCH * NH), 256, FA_SMEM>>>(qkvh, atth);
    // 4. output projection + bias + residual (fp32 out)
    gemm_f16<0, 1, 1, 0><<<dim3(DM / HBN, NT / HBM), 256, HSMEM>>>(
        atth, wo, x1, NT, DM, DM, b_o, x, nullptr);
    // 5. ffn pre-norm (fp16)
    rmsnorm_h_kernel<<<NT, 256>>>(x1, ffn_norm_w, xn2h);
    // 6. gate GEMM (fp16)
    gemm_f16<1, 0, 0, 0><<<dim3(DH / HBN, NT / HBM), 256, HSMEM>>>(
        xn2h, wg, gateh, NT, DH, DM, nullptr, nullptr, nullptr);
    // 7. hidden GEMM with fused swiglu epilogue: hidh = silu(gate) * hid (fp16)
    gemm_f16<1, 0, 0, 1><<<dim3(DH / HBN, NT / HBM), 256, HSMEM>>>(
        xn2h, wh, hidh, NT, DH, DM, nullptr, nullptr, gateh);
    // 8. out projection + bias + residual (fp32 out)
    gemm_f16<0, 1, 1, 0><<<dim3(DM / HBN, NT / HBM), 256, HSMEM>>>(
        hidh, wout, out, NT, DM, DH, b_out, x1, nullptr);
}

// round 10
// speedup vs baseline: 10.4826x; 1.0225x over previous
#include <cuda_runtime.h>
#include <cuda_fp16.h>
#include <math.h>
#include <stdint.h>

#define NT 4096      // total tokens (B*L)
#define DM 1024      // d_model
#define DH 4096      // d_hidden
#define NH 16
#define HD 64
#define LSEQ 2048
#define NBATCH 2
#define QSTR 3072    // packed qkv row stride

// ---------------- scratch (static device globals; no runtime alloc) ----------------
__device__ __half g_xnh [NT * DM];
__device__ __half g_qkvh[(size_t)NT * QSTR];
__device__ __half g_atth[NT * DM];
__device__ float  g_x1  [NT * DM];
__device__ __half g_xn2h[NT * DM];
__device__ __half g_gateh[(size_t)NT * DH];
__device__ __half g_hidh [(size_t)NT * DH];
// fp16 weights, NATURAL [K][N] layout (no transpose)
__device__ __half g_wqkv[(size_t)DM * QSTR];
__device__ __half g_wo  [DM * DM];
__device__ __half g_wg  [(size_t)DM * DH];
__device__ __half g_wh  [(size_t)DM * DH];
__device__ __half g_wout[(size_t)DH * DM];

// ---------------- PTX helpers ----------------
__device__ __forceinline__ void cpa16(uint32_t saddr, const void* src) {
    asm volatile("cp.async.cg.shared.global [%0], [%1], 16;\n" :: "r"(saddr), "l"(src));
}
__device__ __forceinline__ uint32_t s2u(const void* p) {
    uint32_t a;
    asm("{ .reg .u64 t; cvta.to.shared.u64 t, %1; cvt.u32.u64 %0, t; }" : "=r"(a) : "l"(p));
    return a;
}
__device__ __forceinline__ void mma_f16(float* c, const unsigned* a, const unsigned* b) {
    asm volatile("mma.sync.aligned.m16n8k16.row.col.f32.f16.f16.f32 "
        "{%0,%1,%2,%3}, {%4,%5,%6,%7}, {%8,%9}, {%0,%1,%2,%3};\n"
        : "+f"(c[0]), "+f"(c[1]), "+f"(c[2]), "+f"(c[3])
        : "r"(a[0]), "r"(a[1]), "r"(a[2]), "r"(a[3]), "r"(b[0]), "r"(b[1]));
}
__device__ __forceinline__ void ldmx4(unsigned* r, uint32_t addr) {
    asm volatile("ldmatrix.sync.aligned.m8n8.x4.shared.b16 {%0,%1,%2,%3}, [%4];"
        : "=r"(r[0]), "=r"(r[1]), "=r"(r[2]), "=r"(r[3]) : "r"(addr));
}
__device__ __forceinline__ void ldmx4t(unsigned* r, uint32_t addr) {
    asm volatile("ldmatrix.sync.aligned.m8n8.x4.trans.shared.b16 {%0,%1,%2,%3}, [%4];"
        : "=r"(r[0]), "=r"(r[1]), "=r"(r[2]), "=r"(r[3]) : "r"(addr));
}

// ---------------- fused fp32->fp16 weight convert (ALL weights, one launch) ----------------
// Each block converts 2048 contiguous elements of one segment.
// segs: q(512) k(512) v(512) o(512) gate(2048) hidden(2048) out(2048) = 8192 blocks
__global__ __launch_bounds__(256) void cvt_all_kernel(
    const float* __restrict__ Wq, const float* __restrict__ Wk, const float* __restrict__ Wv,
    const float* __restrict__ Wo, const float* __restrict__ Wg, const float* __restrict__ Wh,
    const float* __restrict__ Wout2,
    __half* __restrict__ wqkv, __half* __restrict__ wo, __half* __restrict__ wg,
    __half* __restrict__ wh, __half* __restrict__ wout)
{
    int bx = blockIdx.x;
    const float* in; __half* out; int C, outStride, blk;
    if (bx < 512)        { in = Wq;   out = wqkv;          C = DM; outStride = QSTR; blk = bx; }
    else if (bx < 1024)  { in = Wk;   out = wqkv + DM;     C = DM; outStride = QSTR; blk = bx - 512; }
    else if (bx < 1536)  { in = Wv;   out = wqkv + 2 * DM; C = DM; outStride = QSTR; blk = bx - 1024; }
    else if (bx < 2048)  { in = Wo;   out = wo;            C = DM; outStride = DM;   blk = bx - 1536; }
    else if (bx < 4096)  { in = Wg;   out = wg;            C = DH; outStride = DH;   blk = bx - 2048; }
    else if (bx < 6144)  { in = Wh;   out = wh;            C = DH; outStride = DH;   blk = bx - 4096; }
    else                 { in = Wout2; out = wout;         C = DM; outStride = DM;   blk = bx - 6144; }

    int idx = blk * 256 + threadIdx.x;      // one per 8 elems
    int tpr = C >> 3;
    int row = idx / tpr;
    int col = (idx - row * tpr) * 8;
    const float4* p = (const float4*)(in + (size_t)row * C + col);
    float4 a = p[0], b = p[1];
    __half2 h0 = __floats2half2_rn(a.x, a.y);
    __half2 h1 = __floats2half2_rn(a.z, a.w);
    __half2 h2 = __floats2half2_rn(b.x, b.y);
    __half2 h3 = __floats2half2_rn(b.z, b.w);
    uint4 v;
    v.x = *(unsigned*)&h0; v.y = *(unsigned*)&h1;
    v.z = *(unsigned*)&h2; v.w = *(unsigned*)&h3;
    *(uint4*)(out + (size_t)row * outStride + col) = v;
}

// ---------------- RMSNorm: fp32 in -> fp16 out ----------------
__global__ __launch_bounds__(256) void rmsnorm_h_kernel(
    const float* __restrict__ x, const float* __restrict__ w, __half* __restrict__ out)
{
    int row = blockIdx.x;
    const float4* xr = (const float4*)(x + (size_t)row * DM);
    float4 v = xr[threadIdx.x];
    float s = v.x * v.x + v.y * v.y + v.z * v.z + v.w * v.w;
    __shared__ float red[8];
    #pragma unroll
    for (int o = 16; o > 0; o >>= 1) s += __shfl_xor_sync(0xffffffffu, s, o);
    if ((threadIdx.x & 31) == 0) red[threadIdx.x >> 5] = s;
    __syncthreads();
    if (threadIdx.x < 8) {
        float t = red[threadIdx.x];
        #pragma unroll
        for (int o = 4; o > 0; o >>= 1) t += __shfl_xor_sync(0xffu, t, o);
        if (threadIdx.x == 0) red[0] = t;
    }
    __syncthreads();
    float inv = rsqrtf(red[0] * (1.0f / DM) + 1e-6f);
    float4 wv = ((const float4*)w)[threadIdx.x];
    __half2* orow = (__half2*)(out + (size_t)row * DM);
    orow[2 * threadIdx.x]     = __floats2half2_rn(wv.x * v.x * inv, wv.y * v.y * inv);
    orow[2 * threadIdx.x + 1] = __floats2half2_rn(wv.z * v.z * inv, wv.w * v.w * inv);
}

// ================= fp16 tensor-core GEMM, BK=64, 3-stage pipeline =================
#define HBM 128
#define HBN 128
#define HBK 64
#define ASTRH 72                               // A halves/row (9x16B, odd)
#define BSTRH 136                              // B halves/row (17x16B, odd)
#define ATILE_B (HBM * ASTRH * 2)              // 18432
#define BTILE_B (HBK * BSTRH * 2)              // 17408
#define HSTAGE (ATILE_B + BTILE_B)             // 35840
#define NSTAGE 3
#define HSMEM  (NSTAGE * HSTAGE)               // 107520

__device__ __forceinline__ void hload(uint32_t s0, const __half* A, const __half* B,
    int bm, int bn, int K, int N, int kk, int tid)
{
    const __half* Ag = A + (size_t)bm * K + kk;
    const __half* Bg = B + (size_t)kk * N + bn;
    #pragma unroll
    for (int j = 0; j < 4; j++) {
        int idx = tid + 256 * j;               // 0..1023
        int ar = idx >> 3, ac = idx & 7;       // A: 128 rows x 8 chunks
        cpa16(s0 + (uint32_t)(ar * ASTRH + ac * 8) * 2, Ag + (size_t)ar * K + ac * 8);
        int br = idx >> 4, bc = idx & 15;      // B: 64 rows x 16 chunks
        cpa16(s0 + (uint32_t)ATILE_B + (uint32_t)(br * BSTRH + bc * 8) * 2,
              Bg + (size_t)br * N + bc * 8);
    }
    asm volatile("cp.async.commit_group;\n" ::: "memory");
}

template <int OUT_HALF, int HAS_BIAS, int HAS_RES, int SWI>
__global__ __launch_bounds__(256, 2) void gemm_f16(
    const __half* __restrict__ A, const __half* __restrict__ B, void* __restrict__ Cv,
    int M, int N, int K, const float* __restrict__ bias, const float* __restrict__ res,
    const __half* __restrict__ aux)
{
    extern __shared__ char hsm[];
    uint32_t sbase = s2u(hsm);
    int tid = threadIdx.x;
    int lane = tid & 31, g = lane >> 2, tg = lane & 3;
    int wid = tid >> 5;
    int m_base = (wid >> 1) * 32;
    int n_base = (wid & 1) * 64;
    int bm = blockIdx.y * HBM, bn = blockIdx.x * HBN;
    int lr = lane & 15, lc = lane >> 4;

    float c[2][8][4];
    #pragma unroll
    for (int mt = 0; mt < 2; mt++)
        #pragma unroll
        for (int nt = 0; nt < 8; nt++)
            #pragma unroll
            for (int i = 0; i < 4; i++) c[mt][nt][i] = 0.f;

    const int iters = K / HBK;
    hload(sbase, A, B, bm, bn, K, N, 0, tid);
    hload(sbase + HSTAGE, A, B, bm, bn, K, N, HBK, tid);

    int stage = 0;
    for (int it = 0; it < iters; ++it) {
        if (it + 2 < iters) {
            int ls = stage + 2; if (ls >= NSTAGE) ls -= NSTAGE;
            hload(sbase + (uint32_t)ls * HSTAGE, A, B, bm, bn, K, N, (it + 2) * HBK, tid);
        } else {
            asm volatile("cp.async.commit_group;\n" ::: "memory");
        }
        asm volatile("cp.async.wait_group 2;\n" ::: "memory");
        __syncthreads();

        uint32_t As = sbase + (uint32_t)stage * HSTAGE;
        uint32_t Bs = As + ATILE_B;

        #pragma unroll
        for (int ks = 0; ks < 4; ++ks) {
            unsigned af[2][4];
            #pragma unroll
            for (int mt = 0; mt < 2; ++mt)
                ldmx4(af[mt], As + (uint32_t)((m_base + mt * 16 + lr) * ASTRH
                                              + ks * 16 + lc * 8) * 2);
            #pragma unroll
            for (int ntp = 0; ntp < 4; ++ntp) {
                unsigned bb[4];
                ldmx4t(bb, Bs + (uint32_t)((ks * 16 + lr) * BSTRH
                                           + n_base + ntp * 16 + lc * 8) * 2);
                #pragma unroll
                for (int mt = 0; mt < 2; ++mt) {
                    mma_f16(c[mt][2 * ntp],     af[mt], bb);
                    mma_f16(c[mt][2 * ntp + 1], af[mt], bb + 2);
                }
            }
        }
        __syncthreads();
        if (++stage >= NSTAGE) stage = 0;
    }

    #pragma unroll
    for (int mt = 0; mt < 2; ++mt) {
        #pragma unroll
        for (int nt = 0; nt < 8; ++nt) {
            int row = bm + m_base + mt * 16 + g;
            int col = bn + n_base + nt * 8 + 2 * tg;
            size_t o0 = (size_t)row * N + col;
            size_t o1 = (size_t)(row + 8) * N + col;
            float v00 = c[mt][nt][0], v01 = c[mt][nt][1];
            float v10 = c[mt][nt][2], v11 = c[mt][nt][3];
            if (HAS_BIAS) {
                float b0v = bias[col], b1v = bias[col + 1];
                v00 += b0v; v01 += b1v; v10 += b0v; v11 += b1v;
            }
            if (HAS_RES) {
                float2 r0 = *(const float2*)(res + o0);
                float2 r1 = *(const float2*)(res + o1);
                v00 += r0.x; v01 += r0.y; v10 += r1.x; v11 += r1.y;
            }
            if (SWI) {
                float2 g0 = __half22float2(*(const __half2*)(aux + o0));
                float2 g1 = __half22float2(*(const __half2*)(aux + o1));
                v00 *= g0.x / (1.f + __expf(-g0.x));
                v01 *= g0.y / (1.f + __expf(-g0.y));
                v10 *= g1.x / (1.f + __expf(-g1.x));
                v11 *= g1.y / (1.f + __expf(-g1.y));
            }
            if (OUT_HALF) {
                __half* Ch = (__half*)Cv;
                *(__half2*)(Ch + o0) = __floats2half2_rn(v00, v01);
                *(__half2*)(Ch + o1) = __floats2half2_rn(v10, v11);
            } else {
                float* Cf = (float*)Cv;
                *(float2*)(Cf + o0) = make_float2(v00, v01);
                *(float2*)(Cf + o1) = make_float2(v10, v11);
            }
        }
    }
}

// ================= fp16 tensor-core flash attention =================
#define FBQ 128
#define FBKV 64
#define FSTRH 72
#define FKV_BYTES (FBKV * FSTRH * 2)
#define FP_BYTES  (FBQ * FSTRH * 2)
#define FA_SMEM (4 * FKV_BYTES + FP_BYTES)

__global__ __launch_bounds__(256, 2) void flash_h_kernel(
    const __half* __restrict__ QKV, __half* __restrict__ O)
{
    extern __shared__ __half hsm2[];
    __half* sK = hsm2;
    __half* sV = sK + 2 * FBKV * FSTRH;
    __half* sP = sV + 2 * FBKV * FSTRH;

    int tid = threadIdx.x;
    int lane = tid & 31, g = lane >> 2, tg = lane & 3;
    int wid = tid >> 5;
    int mrow = wid * 16;

    int bh = blockIdx.y;
    int b = bh >> 4, h = bh & 15;
    int q0 = blockIdx.x * FBQ;
    size_t base = ((size_t)b * LSEQ) * QSTR + (size_t)h * HD;
    const __half* Qp = QKV;
    const __half* Kp = QKV + DM;
    const __half* Vp = QKV + 2 * DM;

    #pragma unroll
    for (int i = 0; i < 4; i++) {
        int flat = tid + 256 * i;
        int r = flat >> 3, c = flat & 7;
        *(uint4*)&sP[r * FSTRH + c * 8] =
            *(const uint4*)(Qp + base + (size_t)(q0 + r) * QSTR + c * 8);
    }
    __syncthreads();
    const unsigned* sPw = (const unsigned*)sP;
    unsigned aq[4][4];
    #pragma unroll
    for (int ks = 0; ks < 4; ks++) {
        int kw = ks * 8 + tg;
        aq[ks][0] = sPw[(mrow + g) * 36 + kw];
        aq[ks][1] = sPw[(mrow + g + 8) * 36 + kw];
        aq[ks][2] = sPw[(mrow + g) * 36 + kw + 4];
        aq[ks][3] = sPw[(mrow + g + 8) * 36 + kw + 4];
    }
    __syncthreads();

    uint32_t sKu = s2u(sK), sVu = s2u(sV);
    int vrow = lane & 15;
    int vcol = (lane >> 4) << 3;

    #pragma unroll
    for (int j = 0; j < 2; j++) {
        int cid = tid + 256 * j;
        int r = cid >> 3, c = cid & 7;
        cpa16(sKu + (uint32_t)(r * FSTRH + c * 8) * 2,
              Kp + base + (size_t)r * QSTR + c * 8);
        cpa16(sVu + (uint32_t)(r * FSTRH + c * 8) * 2,
              Vp + base + (size_t)r * QSTR + c * 8);
    }
    asm volatile("cp.async.commit_group;\n" ::: "memory");

    float m0 = -1e30f, m1 = -1e30f, l0 = 0.f, l1 = 0.f;
    float co[8][4];
    #pragma unroll
    for (int nt = 0; nt < 8; nt++)
        #pragma unroll
        for (int i = 0; i < 4; i++) co[nt][i] = 0.f;

    const int ITERS = LSEQ / FBKV;
    for (int it = 0; it < ITERS; ++it) {
        if (it + 1 < ITERS) {
            uint32_t stoff = (uint32_t)((it + 1) & 1) * FKV_BYTES;
            size_t kvoff = (size_t)(it + 1) * FBKV * QSTR;
            #pragma unroll
            for (int j = 0; j < 2; j++) {
                int cid = tid + 256 * j;
                int r = cid >> 3, c = cid & 7;
                cpa16(sKu + stoff + (uint32_t)(r * FSTRH + c * 8) * 2,
                      Kp + base + kvoff + (size_t)r * QSTR + c * 8);
                cpa16(sVu + stoff + (uint32_t)(r * FSTRH + c * 8) * 2,
                      Vp + base + kvoff + (size_t)r * QSTR + c * 8);
            }
            asm volatile("cp.async.commit_group;\n" ::: "memory");
            asm volatile("cp.async.wait_group 1;\n" ::: "memory");
        } else {
            asm volatile("cp.async.wait_group 0;\n" ::: "memory");
        }
        __syncthreads();

        int st = it & 1;
        const unsigned* Kw = (const unsigned*)(sK + st * FBKV * FSTRH);
        uint32_t vstage = sVu + (uint32_t)st * FKV_BYTES;

        float cs[8][4];
        #pragma unroll
        for (int nt = 0; nt < 8; nt++)
            #pragma unroll
            for (int i = 0; i < 4; i++) cs[nt][i] = 0.f;

        #pragma unroll
        for (int ks = 0; ks < 4; ks++) {
            int kw = ks * 8 + tg;
            unsigned bf[8][2];
            #pragma unroll
            for (int nt = 0; nt < 8; nt++) {
                int n = nt * 8 + g;
                bf[nt][0] = Kw[n * 36 + kw];
                bf[nt][1] = Kw[n * 36 + kw + 4];
            }
            #pragma unroll
            for (int nt = 0; nt < 8; nt++)
                mma_f16(cs[nt], aq[ks], bf[nt]);
        }

        float rm0 = -1e30f, rm1 = -1e30f;
        #pragma unroll
        for (int nt = 0; nt < 8; nt++) {
            #pragma unroll
            for (int i = 0; i < 4; i++) cs[nt][i] *= 0.125f;
            rm0 = fmaxf(rm0, fmaxf(cs[nt][0], cs[nt][1]));
            rm1 = fmaxf(rm1, fmaxf(cs[nt][2], cs[nt][3]));
        }
        rm0 = fmaxf(rm0, __shfl_xor_sync(0xffffffffu, rm0, 1));
        rm0 = fmaxf(rm0, __shfl_xor_sync(0xffffffffu, rm0, 2));
        rm1 = fmaxf(rm1, __shfl_xor_sync(0xffffffffu, rm1, 1));
        rm1 = fmaxf(rm1, __shfl_xor_sync(0xffffffffu, rm1, 2));
        float mn0 = fmaxf(m0, rm0);
        float mn1 = fmaxf(m1, rm1);

        __half2* sPh2 = (__half2*)sP;
        float ps0 = 0.f, ps1 = 0.f;
        #pragma unroll
        for (int nt = 0; nt < 8; nt++) {
            float p00 = __expf(cs[nt][0] - mn0);
            float p01 = __expf(cs[nt][1] - mn0);
            float p10 = __expf(cs[nt][2] - mn1);
            float p11 = __expf(cs[nt][3] - mn1);
            ps0 += p00 + p01;
            ps1 += p10 + p11;
            sPh2[(mrow + g) * 36 + nt * 4 + tg]     = __floats2half2_rn(p00, p01);
            sPh2[(mrow + g + 8) * 36 + nt * 4 + tg] = __floats2half2_rn(p10, p11);
        }
        ps0 += __shfl_xor_sync(0xffffffffu, ps0, 1);
        ps0 += __shfl_xor_sync(0xffffffffu, ps0, 2);
        ps1 += __shfl_xor_sync(0xffffffffu, ps1, 1);
        ps1 += __shfl_xor_sync(0xffffffffu, ps1, 2);

        float f0 = __expf(m0 - mn0);
        float f1 = __expf(m1 - mn1);
        l0 = l0 * f0 + ps0;
        l1 = l1 * f1 + ps1;
        m0 = mn0; m1 = mn1;
        #pragma unroll
        for (int nt = 0; nt < 8; nt++) {
            co[nt][0] *= f0; co[nt][1] *= f0;
            co[nt][2] *= f1; co[nt][3] *= f1;
        }
        __syncwarp();

        #pragma unroll
        for (int ks = 0; ks < 4; ks++) {
            int kw = ks * 8 + tg;
            unsigned ap[4];
            ap[0] = sPw[(mrow + g) * 36 + kw];
            ap[1] = sPw[(mrow + g + 8) * 36 + kw];
            ap[2] = sPw[(mrow + g) * 36 + kw + 4];
            ap[3] = sPw[(mrow + g + 8) * 36 + kw + 4];
            #pragma unroll
            for (int ntp = 0; ntp < 4; ntp++) {
                unsigned bb[4];
                uint32_t addr = vstage +
                    (uint32_t)((ks * 16 + vrow) * FSTRH + ntp * 16 + vcol) * 2;
                ldmx4t(bb, addr);
                mma_f16(co[2 * ntp],     ap, bb);
                mma_f16(co[2 * ntp + 1], ap, bb + 2);
            }
        }
        __syncwarp();
        __syncthreads();
    }

    float i0 = 1.f / l0, i1 = 1.f / l1;
    size_t obase = ((size_t)b * LSEQ) * DM + (size_t)h * HD;
    #pragma unroll
    for (int nt = 0; nt < 8; nt++) {
        int col = nt * 8 + 2 * tg;
        size_t o0 = obase + (size_t)(q0 + mrow + g) * DM + col;
        size_t o1 = obase + (size_t)(q0 + mrow + g + 8) * DM + col;
        *(__half2*)(O + o0) = __floats2half2_rn(co[nt][0] * i0, co[nt][1] * i0);
        *(__half2*)(O + o1) = __floats2half2_rn(co[nt][2] * i1, co[nt][3] * i1);
    }
}

// ---------------- launch ----------------
extern "C" void kernel_launch(void* const* d_in, const int* in_sizes, int n_in,
                              void* d_out, int out_size)
{
    const float* x           = (const float*)d_in[0];
    const float* W_q         = (const float*)d_in[1];
    const float* W_k         = (const float*)d_in[2];
    const float* W_v         = (const float*)d_in[3];
    const float* W_o         = (const float*)d_in[4];
    const float* b_o         = (const float*)d_in[5];
    const float* attn_norm_w = (const float*)d_in[6];
    const float* ffn_norm_w  = (const float*)d_in[7];
    const float* W_gate      = (const float*)d_in[8];
    const float* W_hidden    = (const float*)d_in[9];
    const float* W_out       = (const float*)d_in[10];
    const float* b_out       = (const float*)d_in[11];
    float* out = (float*)d_out;

    __half *xnh, *qkvh, *atth, *xn2h, *gateh, *hidh;
    __half *wqkv, *wo, *wg, *wh, *wout;
    float *x1;
    cudaGetSymbolAddress((void**)&xnh,   g_xnh);
    cudaGetSymbolAddress((void**)&qkvh,  g_qkvh);
    cudaGetSymbolAddress((void**)&atth,  g_atth);
    cudaGetSymbolAddress((void**)&x1,    g_x1);
    cudaGetSymbolAddress((void**)&xn2h,  g_xn2h);
    cudaGetSymbolAddress((void**)&gateh, g_gateh);
    cudaGetSymbolAddress((void**)&hidh,  g_hidh);
    cudaGetSymbolAddress((void**)&wqkv,  g_wqkv);
    cudaGetSymbolAddress((void**)&wo,    g_wo);
    cudaGetSymbolAddress((void**)&wg,    g_wg);
    cudaGetSymbolAddress((void**)&wh,    g_wh);
    cudaGetSymbolAddress((void**)&wout,  g_wout);

    static int smem_set = 0;
    if (!smem_set) {
        cudaFuncSetAttribute(flash_h_kernel,
            cudaFuncAttributeMaxDynamicSharedMemorySize, FA_SMEM);
        cudaFuncSetAttribute(gemm_f16<1, 0, 0, 0>,
            cudaFuncAttributeMaxDynamicSharedMemorySize, HSMEM);
        cudaFuncSetAttribute(gemm_f16<0, 1, 1, 0>,
            cudaFuncAttributeMaxDynamicSharedMemorySize, HSMEM);
        cudaFuncSetAttribute(gemm_f16<1, 0, 0, 1>,
            cudaFuncAttributeMaxDynamicSharedMemorySize, HSMEM);
        smem_set = 1;
    }

    // fused fp32->fp16 weight converts, single launch
    cvt_all_kernel<<<8192, 256>>>(W_q, W_k, W_v, W_o, W_gate, W_hidden, W_out,
                                  wqkv, wo, wg, wh, wout);

    // 1. attn pre-norm (fp16)
    rmsnorm_h_kernel<<<NT, 256>>>(x, attn_norm_w, xnh);
    // 2. fused QKV projection -> fp16 packed [NT][3072]
    gemm_f16<1, 0, 0, 0><<<dim3(QSTR / HBN, NT / HBM), 256, HSMEM>>>(
        xnh, wqkv, qkvh, NT, QSTR, DM, nullptr, nullptr, nullptr);
    // 3. attention (fp16 in/out)
    flash_h_kernel<<<dim3(LSEQ / FBQ, NBATCH * NH), 256, FA_SMEM>>>(qkvh, atth);
    // 4. output projection + bias + residual (fp32 out)
    gemm_f16<0, 1, 1, 0><<<dim3(DM / HBN, NT / HBM), 256, HSMEM>>>(
        atth, wo, x1, NT, DM, DM, b_o, x, nullptr);
    // 5. ffn pre-norm (fp16)
    rmsnorm_h_kernel<<<NT, 256>>>(x1, ffn_norm_w, xn2h);
    // 6. gate GEMM (fp16)
    gemm_f16<1, 0, 0, 0><<<dim3(DH / HBN, NT / HBM), 256, HSMEM>>>(
        xn2h, wg, gateh, NT, DH, DM, nullptr, nullptr, nullptr);
    // 7. hidden GEMM with fused swiglu epilogue: hidh = silu(gate) * hid (fp16)
    gemm_f16<1, 0, 0, 1><<<dim3(DH / HBN, NT / HBM), 256, HSMEM>>>(
        xn2h, wh, hidh, NT, DH, DM, nullptr, nullptr, gateh);
    // 8. out projection + bias + residual (fp32 out)
    gemm_f16<0, 1, 1, 0><<<dim3(DM / HBN, NT / HBM), 256, HSMEM>>>(
        hidh, wout, out, NT, DM, DH, b_out, x1, nullptr);
}

// round 11
// speedup vs baseline: 10.9763x; 1.0471x over previous
#include <cuda_runtime.h>
#include <cuda_fp16.h>
#include <math.h>
#include <stdint.h>

#define NT 4096      // total tokens (B*L)
#define DM 1024      // d_model
#define DH 4096      // d_hidden
#define NH 16
#define HD 64
#define LSEQ 2048
#define NBATCH 2
#define QSTR 3072    // packed qkv row stride

// ---------------- scratch (static device globals; no runtime alloc) ----------------
__device__ __half g_xnh [NT * DM];
__device__ __half g_qkvh[(size_t)NT * QSTR];
__device__ __half g_atth[NT * DM];
__device__ float  g_x1  [NT * DM];
__device__ __half g_xn2h[NT * DM];
__device__ __half g_gateh[(size_t)NT * DH];
__device__ __half g_hidh [(size_t)NT * DH];
// fp16 weights, NATURAL [K][N] layout (no transpose)
__device__ __half g_wqkv[(size_t)DM * QSTR];
__device__ __half g_wo  [DM * DM];
__device__ __half g_wg  [(size_t)DM * DH];
__device__ __half g_wh  [(size_t)DM * DH];
__device__ __half g_wout[(size_t)DH * DM];

// ---------------- PTX helpers ----------------
__device__ __forceinline__ void cpa16(uint32_t saddr, const void* src) {
    asm volatile("cp.async.cg.shared.global [%0], [%1], 16;\n" :: "r"(saddr), "l"(src));
}
__device__ __forceinline__ uint32_t s2u(const void* p) {
    uint32_t a;
    asm("{ .reg .u64 t; cvta.to.shared.u64 t, %1; cvt.u32.u64 %0, t; }" : "=r"(a) : "l"(p));
    return a;
}
__device__ __forceinline__ void mma_f16(float* c, const unsigned* a, const unsigned* b) {
    asm volatile("mma.sync.aligned.m16n8k16.row.col.f32.f16.f16.f32 "
        "{%0,%1,%2,%3}, {%4,%5,%6,%7}, {%8,%9}, {%0,%1,%2,%3};\n"
        : "+f"(c[0]), "+f"(c[1]), "+f"(c[2]), "+f"(c[3])
        : "r"(a[0]), "r"(a[1]), "r"(a[2]), "r"(a[3]), "r"(b[0]), "r"(b[1]));
}
__device__ __forceinline__ void ldmx4(unsigned* r, uint32_t addr) {
    asm volatile("ldmatrix.sync.aligned.m8n8.x4.shared.b16 {%0,%1,%2,%3}, [%4];"
        : "=r"(r[0]), "=r"(r[1]), "=r"(r[2]), "=r"(r[3]) : "r"(addr));
}
__device__ __forceinline__ void ldmx4t(unsigned* r, uint32_t addr) {
    asm volatile("ldmatrix.sync.aligned.m8n8.x4.trans.shared.b16 {%0,%1,%2,%3}, [%4];"
        : "=r"(r[0]), "=r"(r[1]), "=r"(r[2]), "=r"(r[3]) : "r"(addr));
}
__device__ __forceinline__ float ex2f(float x) {
    float r; asm("ex2.approx.ftz.f32 %0, %1;" : "=f"(r) : "f"(x)); return r;
}
__device__ __forceinline__ unsigned packh2(float a, float b) {
    __half2 h = __floats2half2_rn(a, b); return *(unsigned*)&h;
}

// ---------------- fused fp32->fp16 weight convert (ALL weights, one launch) ----------------
__global__ __launch_bounds__(256) void cvt_all_kernel(
    const float* __restrict__ Wq, const float* __restrict__ Wk, const float* __restrict__ Wv,
    const float* __restrict__ Wo, const float* __restrict__ Wg, const float* __restrict__ Wh,
    const float* __restrict__ Wout2,
    __half* __restrict__ wqkv, __half* __restrict__ wo, __half* __restrict__ wg,
    __half* __restrict__ wh, __half* __restrict__ wout)
{
    int bx = blockIdx.x;
    const float* in; __half* out; int C, outStride, blk;
    if (bx < 512)        { in = Wq;   out = wqkv;          C = DM; outStride = QSTR; blk = bx; }
    else if (bx < 1024)  { in = Wk;   out = wqkv + DM;     C = DM; outStride = QSTR; blk = bx - 512; }
    else if (bx < 1536)  { in = Wv;   out = wqkv + 2 * DM; C = DM; outStride = QSTR; blk = bx - 1024; }
    else if (bx < 2048)  { in = Wo;   out = wo;            C = DM; outStride = DM;   blk = bx - 1536; }
    else if (bx < 4096)  { in = Wg;   out = wg;            C = DH; outStride = DH;   blk = bx - 2048; }
    else if (bx < 6144)  { in = Wh;   out = wh;            C = DH; outStride = DH;   blk = bx - 4096; }
    else                 { in = Wout2; out = wout;         C = DM; outStride = DM;   blk = bx - 6144; }

    int idx = blk * 256 + threadIdx.x;
    int tpr = C >> 3;
    int row = idx / tpr;
    int col = (idx - row * tpr) * 8;
    const float4* p = (const float4*)(in + (size_t)row * C + col);
    float4 a = p[0], b = p[1];
    __half2 h0 = __floats2half2_rn(a.x, a.y);
    __half2 h1 = __floats2half2_rn(a.z, a.w);
    __half2 h2 = __floats2half2_rn(b.x, b.y);
    __half2 h3 = __floats2half2_rn(b.z, b.w);
    uint4 v;
    v.x = *(unsigned*)&h0; v.y = *(unsigned*)&h1;
    v.z = *(unsigned*)&h2; v.w = *(unsigned*)&h3;
    *(uint4*)(out + (size_t)row * outStride + col) = v;
}

// ---------------- RMSNorm: fp32 in -> fp16 out ----------------
__global__ __launch_bounds__(256) void rmsnorm_h_kernel(
    const float* __restrict__ x, const float* __restrict__ w, __half* __restrict__ out)
{
    int row = blockIdx.x;
    const float4* xr = (const float4*)(x + (size_t)row * DM);
    float4 v = xr[threadIdx.x];
    float s = v.x * v.x + v.y * v.y + v.z * v.z + v.w * v.w;
    __shared__ float red[8];
    #pragma unroll
    for (int o = 16; o > 0; o >>= 1) s += __shfl_xor_sync(0xffffffffu, s, o);
    if ((threadIdx.x & 31) == 0) red[threadIdx.x >> 5] = s;
    __syncthreads();
    if (threadIdx.x < 8) {
        float t = red[threadIdx.x];
        #pragma unroll
        for (int o = 4; o > 0; o >>= 1) t += __shfl_xor_sync(0xffu, t, o);
        if (threadIdx.x == 0) red[0] = t;
    }
    __syncthreads();
    float inv = rsqrtf(red[0] * (1.0f / DM) + 1e-6f);
    float4 wv = ((const float4*)w)[threadIdx.x];
    __half2* orow = (__half2*)(out + (size_t)row * DM);
    orow[2 * threadIdx.x]     = __floats2half2_rn(wv.x * v.x * inv, wv.y * v.y * inv);
    orow[2 * threadIdx.x + 1] = __floats2half2_rn(wv.z * v.z * inv, wv.w * v.w * inv);
}

// ================= fp16 tensor-core GEMM, BK=64, 3-stage pipeline =================
#define HBM 128
#define HBN 128
#define HBK 64
#define ASTRH 72
#define BSTRH 136
#define ATILE_B (HBM * ASTRH * 2)
#define BTILE_B (HBK * BSTRH * 2)
#define HSTAGE (ATILE_B + BTILE_B)
#define NSTAGE 3
#define HSMEM  (NSTAGE * HSTAGE)

__device__ __forceinline__ void hload(uint32_t s0, const __half* A, const __half* B,
    int bm, int bn, int K, int N, int kk, int tid)
{
    const __half* Ag = A + (size_t)bm * K + kk;
    const __half* Bg = B + (size_t)kk * N + bn;
    #pragma unroll
    for (int j = 0; j < 4; j++) {
        int idx = tid + 256 * j;
        int ar = idx >> 3, ac = idx & 7;
        cpa16(s0 + (uint32_t)(ar * ASTRH + ac * 8) * 2, Ag + (size_t)ar * K + ac * 8);
        int br = idx >> 4, bc = idx & 15;
        cpa16(s0 + (uint32_t)ATILE_B + (uint32_t)(br * BSTRH + bc * 8) * 2,
              Bg + (size_t)br * N + bc * 8);
    }
    asm volatile("cp.async.commit_group;\n" ::: "memory");
}

template <int OUT_HALF, int HAS_BIAS, int HAS_RES, int SWI>
__global__ __launch_bounds__(256, 2) void gemm_f16(
    const __half* __restrict__ A, const __half* __restrict__ B, void* __restrict__ Cv,
    int M, int N, int K, const float* __restrict__ bias, const float* __restrict__ res,
    const __half* __restrict__ aux)
{
    extern __shared__ char hsm[];
    uint32_t sbase = s2u(hsm);
    int tid = threadIdx.x;
    int lane = tid & 31, g = lane >> 2, tg = lane & 3;
    int wid = tid >> 5;
    int m_base = (wid >> 1) * 32;
    int n_base = (wid & 1) * 64;
    int bm = blockIdx.y * HBM, bn = blockIdx.x * HBN;
    int lr = lane & 15, lc = lane >> 4;

    float c[2][8][4];
    #pragma unroll
    for (int mt = 0; mt < 2; mt++)
        #pragma unroll
        for (int nt = 0; nt < 8; nt++)
            #pragma unroll
            for (int i = 0; i < 4; i++) c[mt][nt][i] = 0.f;

    const int iters = K / HBK;
    hload(sbase, A, B, bm, bn, K, N, 0, tid);
    hload(sbase + HSTAGE, A, B, bm, bn, K, N, HBK, tid);

    int stage = 0;
    for (int it = 0; it < iters; ++it) {
        if (it + 2 < iters) {
            int ls = stage + 2; if (ls >= NSTAGE) ls -= NSTAGE;
            hload(sbase + (uint32_t)ls * HSTAGE, A, B, bm, bn, K, N, (it + 2) * HBK, tid);
        } else {
            asm volatile("cp.async.commit_group;\n" ::: "memory");
        }
        asm volatile("cp.async.wait_group 2;\n" ::: "memory");
        __syncthreads();

        uint32_t As = sbase + (uint32_t)stage * HSTAGE;
        uint32_t Bs = As + ATILE_B;

        #pragma unroll
        for (int ks = 0; ks < 4; ++ks) {
            unsigned af[2][4];
            #pragma unroll
            for (int mt = 0; mt < 2; ++mt)
                ldmx4(af[mt], As + (uint32_t)((m_base + mt * 16 + lr) * ASTRH
                                              + ks * 16 + lc * 8) * 2);
            #pragma unroll
            for (int ntp = 0; ntp < 4; ++ntp) {
                unsigned bb[4];
                ldmx4t(bb, Bs + (uint32_t)((ks * 16 + lr) * BSTRH
                                           + n_base + ntp * 16 + lc * 8) * 2);
                #pragma unroll
                for (int mt = 0; mt < 2; ++mt) {
                    mma_f16(c[mt][2 * ntp],     af[mt], bb);
                    mma_f16(c[mt][2 * ntp + 1], af[mt], bb + 2);
                }
            }
        }
        __syncthreads();
        if (++stage >= NSTAGE) stage = 0;
    }

    #pragma unroll
    for (int mt = 0; mt < 2; ++mt) {
        #pragma unroll
        for (int nt = 0; nt < 8; ++nt) {
            int row = bm + m_base + mt * 16 + g;
            int col = bn + n_base + nt * 8 + 2 * tg;
            size_t o0 = (size_t)row * N + col;
            size_t o1 = (size_t)(row + 8) * N + col;
            float v00 = c[mt][nt][0], v01 = c[mt][nt][1];
            float v10 = c[mt][nt][2], v11 = c[mt][nt][3];
            if (HAS_BIAS) {
                float b0v = bias[col], b1v = bias[col + 1];
                v00 += b0v; v01 += b1v; v10 += b0v; v11 += b1v;
            }
            if (HAS_RES) {
                float2 r0 = *(const float2*)(res + o0);
                float2 r1 = *(const float2*)(res + o1);
                v00 += r0.x; v01 += r0.y; v10 += r1.x; v11 += r1.y;
            }
            if (SWI) {
                float2 g0 = __half22float2(*(const __half2*)(aux + o0));
                float2 g1 = __half22float2(*(const __half2*)(aux + o1));
                v00 *= g0.x / (1.f + __expf(-g0.x));
                v01 *= g0.y / (1.f + __expf(-g0.y));
                v10 *= g1.x / (1.f + __expf(-g1.x));
                v11 *= g1.y / (1.f + __expf(-g1.y));
            }
            if (OUT_HALF) {
                __half* Ch = (__half*)Cv;
                *(__half2*)(Ch + o0) = __floats2half2_rn(v00, v01);
                *(__half2*)(Ch + o1) = __floats2half2_rn(v10, v11);
            } else {
                float* Cf = (float*)Cv;
                *(float2*)(Cf + o0) = make_float2(v00, v01);
                *(float2*)(Cf + o1) = make_float2(v10, v11);
            }
        }
    }
}

// ================= fp16 flash attention, register-resident P =================
// BQ=128, BKV=64. S C-fragment repacked in-registers as P A-fragment (no sP).
// K fragments via ldmatrix non-trans ([n][k] tile == B-frag). exp via ex2.
#define FBQ 128
#define FBKV 64
#define FSTRH 72
#define FKV_BYTES (FBKV * FSTRH * 2)        // 9216 per stage
#define FA_SMEM (4 * FKV_BYTES)             // 36864: K x2, V x2 (Q staged in sK)

__global__ __launch_bounds__(256, 2) void flash_h_kernel(
    const __half* __restrict__ QKV, __half* __restrict__ O)
{
    extern __shared__ __half hsm2[];
    __half* sK = hsm2;
    __half* sV = sK + 2 * FBKV * FSTRH;

    int tid = threadIdx.x;
    int lane = tid & 31, g = lane >> 2, tg = lane & 3;
    int wid = tid >> 5;
    int mrow = wid * 16;

    int bh = blockIdx.y;
    int b = bh >> 4, h = bh & 15;
    int q0 = blockIdx.x * FBQ;
    size_t base = ((size_t)b * LSEQ) * QSTR + (size_t)h * HD;
    const __half* Qp = QKV;
    const __half* Kp = QKV + DM;
    const __half* Vp = QKV + 2 * DM;

    uint32_t sKu = s2u(sK), sVu = s2u(sV);
    int lr = lane & 15, lc = lane >> 4;

    // ---- stage Q through sK region, build Q A-fragments via ldmatrix ----
    #pragma unroll
    for (int i = 0; i < 4; i++) {
        int flat = tid + 256 * i;
        int r = flat >> 3, c = flat & 7;
        *(uint4*)&sK[r * FSTRH + c * 8] =
            *(const uint4*)(Qp + base + (size_t)(q0 + r) * QSTR + c * 8);
    }
    __syncthreads();
    unsigned aq[4][4];
    #pragma unroll
    for (int ks = 0; ks < 4; ks++)
        ldmx4(aq[ks], sKu + (uint32_t)((mrow + lr) * FSTRH + ks * 16 + lc * 8) * 2);
    __syncthreads();   // sK free for K stages

    // prefetch stage 0
    #pragma unroll
    for (int j = 0; j < 2; j++) {
        int cid = tid + 256 * j;
        int r = cid >> 3, c = cid & 7;
        cpa16(sKu + (uint32_t)(r * FSTRH + c * 8) * 2,
              Kp + base + (size_t)r * QSTR + c * 8);
        cpa16(sVu + (uint32_t)(r * FSTRH + c * 8) * 2,
              Vp + base + (size_t)r * QSTR + c * 8);
    }
    asm volatile("cp.async.commit_group;\n" ::: "memory");

    const float SC = 0.18033688f;   // 0.125 * log2(e)
    float m0 = -1e30f, m1 = -1e30f, l0 = 0.f, l1 = 0.f;
    float co[8][4];
    #pragma unroll
    for (int nt = 0; nt < 8; nt++)
        #pragma unroll
        for (int i = 0; i < 4; i++) co[nt][i] = 0.f;

    // ldmatrix address components
    int kt = lane >> 3;             // tile id 0..3
    int krow = lane & 7;
    int kn_off = ((kt >> 1) & 1) * 8 + krow;   // n offset within ntp group
    int kk_off = (kt & 1) * 8;                 // k offset within k16 slice
    int vrow = lane & 15;
    int vcol = (lane >> 4) << 3;

    const int ITERS = LSEQ / FBKV;
    for (int it = 0; it < ITERS; ++it) {
        if (it + 1 < ITERS) {
            uint32_t stoff = (uint32_t)((it + 1) & 1) * FKV_BYTES;
            size_t kvoff = (size_t)(it + 1) * FBKV * QSTR;
            #pragma unroll
            for (int j = 0; j < 2; j++) {
                int cid = tid + 256 * j;
                int r = cid >> 3, c = cid & 7;
                cpa16(sKu + stoff + (uint32_t)(r * FSTRH + c * 8) * 2,
                      Kp + base + kvoff + (size_t)r * QSTR + c * 8);
                cpa16(sVu + stoff + (uint32_t)(r * FSTRH + c * 8) * 2,
                      Vp + base + kvoff + (size_t)r * QSTR + c * 8);
            }
            asm volatile("cp.async.commit_group;\n" ::: "memory");
            asm volatile("cp.async.wait_group 1;\n" ::: "memory");
        } else {
            asm volatile("cp.async.wait_group 0;\n" ::: "memory");
        }
        __syncthreads();

        int st = it & 1;
        uint32_t kstage = sKu + (uint32_t)st * FKV_BYTES;
        uint32_t vstage = sVu + (uint32_t)st * FKV_BYTES;

        // ---- S = Q K^T : K B-frags via ldmatrix non-trans ----
        float cs[8][4];
        #pragma unroll
        for (int nt = 0; nt < 8; nt++)
            #pragma unroll
            for (int i = 0; i < 4; i++) cs[nt][i] = 0.f;

        #pragma unroll
        for (int ks = 0; ks < 4; ks++) {
            #pragma unroll
            for (int ntp = 0; ntp < 4; ntp++) {
                unsigned bb[4];
                ldmx4(bb, kstage + (uint32_t)((ntp * 16 + kn_off) * FSTRH
                                              + ks * 16 + kk_off) * 2);
                mma_f16(cs[2 * ntp],     aq[ks], bb);
                mma_f16(cs[2 * ntp + 1], aq[ks], bb + 2);
            }
        }

        // ---- online softmax (log2 domain, ex2) ----
        float rm0 = -1e30f, rm1 = -1e30f;
        #pragma unroll
        for (int nt = 0; nt < 8; nt++) {
            #pragma unroll
            for (int i = 0; i < 4; i++) cs[nt][i] *= SC;
            rm0 = fmaxf(rm0, fmaxf(cs[nt][0], cs[nt][1]));
            rm1 = fmaxf(rm1, fmaxf(cs[nt][2], cs[nt][3]));
        }
        rm0 = fmaxf(rm0, __shfl_xor_sync(0xffffffffu, rm0, 1));
        rm0 = fmaxf(rm0, __shfl_xor_sync(0xffffffffu, rm0, 2));
        rm1 = fmaxf(rm1, __shfl_xor_sync(0xffffffffu, rm1, 1));
        rm1 = fmaxf(rm1, __shfl_xor_sync(0xffffffffu, rm1, 2));
        float mn0 = fmaxf(m0, rm0);
        float mn1 = fmaxf(m1, rm1);

        float ps0 = 0.f, ps1 = 0.f;
        #pragma unroll
        for (int nt = 0; nt < 8; nt++) {
            cs[nt][0] = ex2f(cs[nt][0] - mn0);
            cs[nt][1] = ex2f(cs[nt][1] - mn0);
            cs[nt][2] = ex2f(cs[nt][2] - mn1);
            cs[nt][3] = ex2f(cs[nt][3] - mn1);
            ps0 += cs[nt][0] + cs[nt][1];
            ps1 += cs[nt][2] + cs[nt][3];
        }
        ps0 += __shfl_xor_sync(0xffffffffu, ps0, 1);
        ps0 += __shfl_xor_sync(0xffffffffu, ps0, 2);
        ps1 += __shfl_xor_sync(0xffffffffu, ps1, 1);
        ps1 += __shfl_xor_sync(0xffffffffu, ps1, 2);

        float f0 = ex2f(m0 - mn0);
        float f1 = ex2f(m1 - mn1);
        l0 = l0 * f0 + ps0;
        l1 = l1 * f1 + ps1;
        m0 = mn0; m1 = mn1;
        #pragma unroll
        for (int nt = 0; nt < 8; nt++) {
            co[nt][0] *= f0; co[nt][1] *= f0;
            co[nt][2] *= f1; co[nt][3] *= f1;
        }

        // ---- O += P V : P A-frags packed straight from registers ----
        #pragma unroll
        for (int ks = 0; ks < 4; ks++) {
            unsigned ap[4];
            ap[0] = packh2(cs[2 * ks][0],     cs[2 * ks][1]);
            ap[1] = packh2(cs[2 * ks][2],     cs[2 * ks][3]);
            ap[2] = packh2(cs[2 * ks + 1][0], cs[2 * ks + 1][1]);
            ap[3] = packh2(cs[2 * ks + 1][2], cs[2 * ks + 1][3]);
            #pragma unroll
            for (int ntp = 0; ntp < 4; ntp++) {
                unsigned bb[4];
                ldmx4t(bb, vstage + (uint32_t)((ks * 16 + vrow) * FSTRH
                                               + ntp * 16 + vcol) * 2);
                mma_f16(co[2 * ntp],     ap, bb);
                mma_f16(co[2 * ntp + 1], ap, bb + 2);
            }
        }
        __syncthreads();
    }

    float i0 = 1.f / l0, i1 = 1.f / l1;
    size_t obase = ((size_t)b * LSEQ) * DM + (size_t)h * HD;
    #pragma unroll
    for (int nt = 0; nt < 8; nt++) {
        int col = nt * 8 + 2 * tg;
        size_t o0 = obase + (size_t)(q0 + mrow + g) * DM + col;
        size_t o1 = obase + (size_t)(q0 + mrow + g + 8) * DM + col;
        *(__half2*)(O + o0) = __floats2half2_rn(co[nt][0] * i0, co[nt][1] * i0);
        *(__half2*)(O + o1) = __floats2half2_rn(co[nt][2] * i1, co[nt][3] * i1);
    }
}

// ---------------- launch ----------------
extern "C" void kernel_launch(void* const* d_in, const int* in_sizes, int n_in,
                              void* d_out, int out_size)
{
    const float* x           = (const float*)d_in[0];
    const float* W_q         = (const float*)d_in[1];
    const float* W_k         = (const float*)d_in[2];
    const float* W_v         = (const float*)d_in[3];
    const float* W_o         = (const float*)d_in[4];
    const float* b_o         = (const float*)d_in[5];
    const float* attn_norm_w = (const float*)d_in[6];
    const float* ffn_norm_w  = (const float*)d_in[7];
    const float* W_gate      = (const float*)d_in[8];
    const float* W_hidden    = (const float*)d_in[9];
    const float* W_out       = (const float*)d_in[10];
    const float* b_out       = (const float*)d_in[11];
    float* out = (float*)d_out;

    __half *xnh, *qkvh, *atth, *xn2h, *gateh, *hidh;
    __half *wqkv, *wo, *wg, *wh, *wout;
    float *x1;
    cudaGetSymbolAddress((void**)&xnh,   g_xnh);
    cudaGetSymbolAddress((void**)&qkvh,  g_qkvh);
    cudaGetSymbolAddress((void**)&atth,  g_atth);
    cudaGetSymbolAddress((void**)&x1,    g_x1);
    cudaGetSymbolAddress((void**)&xn2h,  g_xn2h);
    cudaGetSymbolAddress((void**)&gateh, g_gateh);
    cudaGetSymbolAddress((void**)&hidh,  g_hidh);
    cudaGetSymbolAddress((void**)&wqkv,  g_wqkv);
    cudaGetSymbolAddress((void**)&wo,    g_wo);
    cudaGetSymbolAddress((void**)&wg,    g_wg);
    cudaGetSymbolAddress((void**)&wh,    g_wh);
    cudaGetSymbolAddress((void**)&wout,  g_wout);

    static int smem_set = 0;
    if (!smem_set) {
        cudaFuncSetAttribute(flash_h_kernel,
            cudaFuncAttributeMaxDynamicSharedMemorySize, FA_SMEM);
        cudaFuncSetAttribute(gemm_f16<1, 0, 0, 0>,
            cudaFuncAttributeMaxDynamicSharedMemorySize, HSMEM);
        cudaFuncSetAttribute(gemm_f16<0, 1, 1, 0>,
            cudaFuncAttributeMaxDynamicSharedMemorySize, HSMEM);
        cudaFuncSetAttribute(gemm_f16<1, 0, 0, 1>,
            cudaFuncAttributeMaxDynamicSharedMemorySize, HSMEM);
        smem_set = 1;
    }

    // fused fp32->fp16 weight converts, single launch
    cvt_all_kernel<<<8192, 256>>>(W_q, W_k, W_v, W_o, W_gate, W_hidden, W_out,
                                  wqkv, wo, wg, wh, wout);

    // 1. attn pre-norm (fp16)
    rmsnorm_h_kernel<<<NT, 256>>>(x, attn_norm_w, xnh);
    // 2. fused QKV projection -> fp16 packed [NT][3072]
    gemm_f16<1, 0, 0, 0><<<dim3(QSTR / HBN, NT / HBM), 256, HSMEM>>>(
        xnh, wqkv, qkvh, NT, QSTR, DM, nullptr, nullptr, nullptr);
    // 3. attention (fp16 in/out)
    flash_h_kernel<<<dim3(LSEQ / FBQ, NBATCH * NH), 256, FA_SMEM>>>(qkvh, atth);
    // 4. output projection + bias + residual (fp32 out)
    gemm_f16<0, 1, 1, 0><<<dim3(DM / HBN, NT / HBM), 256, HSMEM>>>(
        atth, wo, x1, NT, DM, DM, b_o, x, nullptr);
    // 5. ffn pre-norm (fp16)
    rmsnorm_h_kernel<<<NT, 256>>>(x1, ffn_norm_w, xn2h);
    // 6. gate GEMM (fp16)
    gemm_f16<1, 0, 0, 0><<<dim3(DH / HBN, NT / HBM), 256, HSMEM>>>(
        xn2h, wg, gateh, NT, DH, DM, nullptr, nullptr, nullptr);
    // 7. hidden GEMM with fused swiglu epilogue: hidh = silu(gate) * hid (fp16)
    gemm_f16<1, 0, 0, 1><<<dim3(DH / HBN, NT / HBM), 256, HSMEM>>>(
        xn2h, wh, hidh, NT, DH, DM, nullptr, nullptr, gateh);
    // 8. out projection + bias + residual (fp32 out)
    gemm_f16<0, 1, 1, 0><<<dim3(DM / HBN, NT / HBM), 256, HSMEM>>>(
        hidh, wout, out, NT, DM, DH, b_out, x1, nullptr);
}